// round 1
// baseline (speedup 1.0000x reference)
#include <cuda_runtime.h>
#include <math.h>

// Problem constants
#define BB 8
#define TT 1024
#define DD 1024
#define NHEAD 16
#define HDIM 64
#define FF 4096
#define MM (BB * TT)   // 8192

// ---------------------------------------------------------------------------
// Scratch buffers (device globals: allocation-free per harness rules)
// ---------------------------------------------------------------------------
__device__ float g_xn[MM * DD];   // rmsnorm output
__device__ float g_q [MM * DD];
__device__ float g_k [MM * DD];
__device__ float g_v [MM * DD];
__device__ float g_ao[MM * DD];   // attention output (pre out-proj)
__device__ float g_ar[MM * DD];   // attn residual result (res2)
__device__ float g_hn[MM * DD];   // layernorm output
__device__ float g_h1[MM * FF];   // FFN hidden

// ---------------------------------------------------------------------------
// RMSNorm: one block per row (D=1024), 256 threads, float4 per thread
// ---------------------------------------------------------------------------
__global__ __launch_bounds__(256) void rmsnorm_kernel(
    const float* __restrict__ x, const float* __restrict__ scale,
    float* __restrict__ out)
{
    const int row = blockIdx.x;
    const int tid = threadIdx.x;
    const float4 v = ((const float4*)(x + (size_t)row * DD))[tid];
    float ss = v.x * v.x + v.y * v.y + v.z * v.z + v.w * v.w;
    #pragma unroll
    for (int m = 16; m; m >>= 1) ss += __shfl_xor_sync(0xffffffffu, ss, m);
    __shared__ float sred[8];
    if ((tid & 31) == 0) sred[tid >> 5] = ss;
    __syncthreads();
    float tot = 0.f;
    #pragma unroll
    for (int i = 0; i < 8; i++) tot += sred[i];
    const float r = rsqrtf(tot * (1.0f / DD) + 1e-6f);
    const float4 s4 = ((const float4*)scale)[tid];
    float4 o;
    o.x = v.x * r * s4.x; o.y = v.y * r * s4.y;
    o.z = v.z * r * s4.z; o.w = v.w * r * s4.w;
    ((float4*)(out + (size_t)row * DD))[tid] = o;
}

// ---------------------------------------------------------------------------
// LayerNorm: same structure, mean + var
// ---------------------------------------------------------------------------
__global__ __launch_bounds__(256) void layernorm_kernel(
    const float* __restrict__ x, const float* __restrict__ gamma,
    const float* __restrict__ beta, float* __restrict__ out)
{
    const int row = blockIdx.x;
    const int tid = threadIdx.x;
    const float4 v = ((const float4*)(x + (size_t)row * DD))[tid];
    float s  = v.x + v.y + v.z + v.w;
    float ss = v.x * v.x + v.y * v.y + v.z * v.z + v.w * v.w;
    #pragma unroll
    for (int m = 16; m; m >>= 1) {
        s  += __shfl_xor_sync(0xffffffffu, s,  m);
        ss += __shfl_xor_sync(0xffffffffu, ss, m);
    }
    __shared__ float sr1[8], sr2[8];
    if ((tid & 31) == 0) { sr1[tid >> 5] = s; sr2[tid >> 5] = ss; }
    __syncthreads();
    float S = 0.f, SS = 0.f;
    #pragma unroll
    for (int i = 0; i < 8; i++) { S += sr1[i]; SS += sr2[i]; }
    const float mean = S * (1.0f / DD);
    const float var  = SS * (1.0f / DD) - mean * mean;
    const float r = rsqrtf(var + 1e-5f);
    const float4 g4 = ((const float4*)gamma)[tid];
    const float4 b4 = ((const float4*)beta)[tid];
    float4 o;
    o.x = (v.x - mean) * r * g4.x + b4.x;
    o.y = (v.y - mean) * r * g4.y + b4.y;
    o.z = (v.z - mean) * r * g4.z + b4.z;
    o.w = (v.w - mean) * r * g4.w + b4.w;
    ((float4*)(out + (size_t)row * DD))[tid] = o;
}

// ---------------------------------------------------------------------------
// SGEMM: C[M,N] = A[M,K] @ B (+epilogue). 128x128 block, BK=8, 8x8/thread.
//   BT=false: B is [K,N] row-major.   BT=true: B is [N,K] row-major (B^T).
// EPI: 0 = +bias; 1 = (+bias)*qscale(per_dim_scale); 2 = +bias+residual;
//      3 = relu(+bias)
// All dims are multiples of 128 here -> no bounds checks.
// ---------------------------------------------------------------------------
__device__ __forceinline__ float softplus_f(float x) {
    return (x > 15.f) ? x : log1pf(__expf(x));
}

template <int EPI, bool BT>
__global__ __launch_bounds__(256, 2) void sgemm_kernel(
    const float* __restrict__ A, const float* __restrict__ Bm,
    const float* __restrict__ bias, const float* __restrict__ extra,
    float* __restrict__ C, int M, int N, int K)
{
    __shared__ float As[8][128];
    __shared__ float Bs[8][128];
    const int tid = threadIdx.x;
    const int tx = tid & 15;
    const int ty = tid >> 4;
    const int m0 = blockIdx.y << 7;
    const int n0 = blockIdx.x << 7;

    float acc[8][8];
    #pragma unroll
    for (int i = 0; i < 8; i++)
        #pragma unroll
        for (int j = 0; j < 8; j++) acc[i][j] = 0.f;

    // A tile loader: 128 rows x 8 k, one float4 along K per thread
    const int arow = tid >> 1;
    const int acol = (tid & 1) << 2;
    const float* Ap = A + (size_t)(m0 + arow) * K + acol;
    // B tile loaders
    const int bkN = tid >> 5;
    const int bnN = (tid & 31) << 2;
    const float* BpN = Bm + (size_t)bkN * N + n0 + bnN;
    const int bnT = tid >> 1;
    const int bkT = (tid & 1) << 2;
    const float* BpT = Bm + (size_t)(n0 + bnT) * K + bkT;

    for (int k0 = 0; k0 < K; k0 += 8) {
        float4 a4 = *(const float4*)Ap; Ap += 8;
        As[acol + 0][arow] = a4.x;
        As[acol + 1][arow] = a4.y;
        As[acol + 2][arow] = a4.z;
        As[acol + 3][arow] = a4.w;
        if (!BT) {
            float4 b4 = *(const float4*)BpN; BpN += (size_t)8 * N;
            *(float4*)&Bs[bkN][bnN] = b4;
        } else {
            float4 b4 = *(const float4*)BpT; BpT += 8;
            Bs[bkT + 0][bnT] = b4.x;
            Bs[bkT + 1][bnT] = b4.y;
            Bs[bkT + 2][bnT] = b4.z;
            Bs[bkT + 3][bnT] = b4.w;
        }
        __syncthreads();
        #pragma unroll
        for (int kk = 0; kk < 8; kk++) {
            float ar_[8], br_[8];
            float4 t0v = *(const float4*)&As[kk][ty << 2];
            float4 t1v = *(const float4*)&As[kk][64 + (ty << 2)];
            ar_[0] = t0v.x; ar_[1] = t0v.y; ar_[2] = t0v.z; ar_[3] = t0v.w;
            ar_[4] = t1v.x; ar_[5] = t1v.y; ar_[6] = t1v.z; ar_[7] = t1v.w;
            float4 u0 = *(const float4*)&Bs[kk][tx << 2];
            float4 u1 = *(const float4*)&Bs[kk][64 + (tx << 2)];
            br_[0] = u0.x; br_[1] = u0.y; br_[2] = u0.z; br_[3] = u0.w;
            br_[4] = u1.x; br_[5] = u1.y; br_[6] = u1.z; br_[7] = u1.w;
            #pragma unroll
            for (int i = 0; i < 8; i++)
                #pragma unroll
                for (int j = 0; j < 8; j++)
                    acc[i][j] = fmaf(ar_[i], br_[j], acc[i][j]);
        }
        __syncthreads();
    }

    // Epilogue
    #pragma unroll
    for (int jh = 0; jh < 2; jh++) {
        const int ccol = n0 + (jh ? 64 : 0) + (tx << 2);
        const float4 b4 = *(const float4*)(bias + ccol);
        float4 s4 = make_float4(1.f, 1.f, 1.f, 1.f);
        if (EPI == 1) {
            const float c = 0.18033688f; // log2(e)/sqrt(64)
            s4.x = c * softplus_f(extra[(ccol + 0) & 63]);
            s4.y = c * softplus_f(extra[(ccol + 1) & 63]);
            s4.z = c * softplus_f(extra[(ccol + 2) & 63]);
            s4.w = c * softplus_f(extra[(ccol + 3) & 63]);
        }
        #pragma unroll
        for (int ih = 0; ih < 2; ih++) {
            #pragma unroll
            for (int i = 0; i < 4; i++) {
                const int r = m0 + (ih ? 64 : 0) + (ty << 2) + i;
                const int ai = ih * 4 + i;
                const int aj = jh * 4;
                float4 vv;
                vv.x = acc[ai][aj + 0] + b4.x;
                vv.y = acc[ai][aj + 1] + b4.y;
                vv.z = acc[ai][aj + 2] + b4.z;
                vv.w = acc[ai][aj + 3] + b4.w;
                if (EPI == 1) {
                    vv.x *= s4.x; vv.y *= s4.y; vv.z *= s4.z; vv.w *= s4.w;
                }
                if (EPI == 2) {
                    const float4 rr = *(const float4*)(extra + (size_t)r * N + ccol);
                    vv.x += rr.x; vv.y += rr.y; vv.z += rr.z; vv.w += rr.w;
                }
                if (EPI == 3) {
                    vv.x = fmaxf(vv.x, 0.f); vv.y = fmaxf(vv.y, 0.f);
                    vv.z = fmaxf(vv.z, 0.f); vv.w = fmaxf(vv.w, 0.f);
                }
                *(float4*)(C + (size_t)r * N + ccol) = vv;
            }
        }
    }
}

// ---------------------------------------------------------------------------
// Flash attention. grid = (T/64, B*NHEAD), 256 threads.
// Tiles: 64 q-rows x 64 keys, H=64. Qs/Ks stored [h][row] (transposed) so the
// inner-product fragment loads are broadcast/contiguous LDS.128.
// Online softmax (natural exp, matching reference exactly up to fp error).
// ---------------------------------------------------------------------------
#define FPAD 68
struct FlashSmem {
    float Qs[64][FPAD];  // [h][r]
    float Ks[64][FPAD];  // [h][s]
    float Vs[64][FPAD];  // [s][h]
    float Ps[64][FPAD];  // [s][r]
    float m_s[64];
    float l_s[64];
    float padq[64];
    float pads[64];
};

__global__ __launch_bounds__(256) void flash_kernel(
    const float* __restrict__ q, const float* __restrict__ k,
    const float* __restrict__ v, const float* __restrict__ pad,
    float* __restrict__ out)
{
    extern __shared__ char smraw[];
    FlashSmem* sm = (FlashSmem*)smraw;
    const int tid = threadIdx.x;
    const int tx = tid & 15;
    const int ty = tid >> 4;
    const int t0 = blockIdx.x << 6;
    const int bn = blockIdx.y;
    const int b = bn >> 4, n = bn & 15;

    // Load Q tile transposed: thread covers row r = tid/4, 16 h's
    {
        const int r = tid >> 2;
        const int h0 = (tid & 3) << 4;
        const float* qp = q + ((size_t)((b * TT + t0 + r) * NHEAD + n)) * HDIM + h0;
        #pragma unroll
        for (int u = 0; u < 4; u++) {
            const float4 qv = *(const float4*)(qp + u * 4);
            sm->Qs[h0 + u * 4 + 0][r] = qv.x;
            sm->Qs[h0 + u * 4 + 1][r] = qv.y;
            sm->Qs[h0 + u * 4 + 2][r] = qv.z;
            sm->Qs[h0 + u * 4 + 3][r] = qv.w;
        }
    }
    if (tid < 64) {
        sm->m_s[tid] = -1e30f;
        sm->l_s[tid] = 0.f;
        sm->padq[tid] = pad[b * TT + t0 + tid];
    }
    float o[4][4] = {};

    for (int s0 = 0; s0 <= t0; s0 += 64) {
        // Load K (transposed) + V (direct) tiles
        {
            const int r = tid >> 2;
            const int h0 = (tid & 3) << 4;
            const float* kp = k + ((size_t)((b * TT + s0 + r) * NHEAD + n)) * HDIM + h0;
            #pragma unroll
            for (int u = 0; u < 4; u++) {
                const float4 kv = *(const float4*)(kp + u * 4);
                sm->Ks[h0 + u * 4 + 0][r] = kv.x;
                sm->Ks[h0 + u * 4 + 1][r] = kv.y;
                sm->Ks[h0 + u * 4 + 2][r] = kv.z;
                sm->Ks[h0 + u * 4 + 3][r] = kv.w;
            }
            const float* vp = v + ((size_t)((b * TT + s0 + r) * NHEAD + n)) * HDIM + h0;
            #pragma unroll
            for (int u = 0; u < 4; u++)
                *(float4*)&sm->Vs[r][h0 + u * 4] = *(const float4*)(vp + u * 4);
            if (tid < 64) sm->pads[tid] = pad[b * TT + s0 + tid];
        }
        __syncthreads();

        // S = Q K^T for this 64x64 tile (each thread 4x4)
        float sacc[4][4] = {};
        #pragma unroll 16
        for (int h = 0; h < 64; h++) {
            const float4 a4 = *(const float4*)&sm->Qs[h][ty << 2];
            const float4 b4 = *(const float4*)&sm->Ks[h][tx << 2];
            const float av[4] = {a4.x, a4.y, a4.z, a4.w};
            const float bv[4] = {b4.x, b4.y, b4.z, b4.w};
            #pragma unroll
            for (int i = 0; i < 4; i++)
                #pragma unroll
                for (int j = 0; j < 4; j++)
                    sacc[i][j] = fmaf(av[i], bv[j], sacc[i][j]);
        }

        // Mask (causal only needed on the diagonal block; padding always)
        const bool diagblk = (s0 == t0);
        float psj[4];
        #pragma unroll
        for (int j = 0; j < 4; j++) psj[j] = sm->pads[(tx << 2) + j];
        #pragma unroll
        for (int i = 0; i < 4; i++) {
            const int r = (ty << 2) + i;
            const float pq = sm->padq[r];
            #pragma unroll
            for (int j = 0; j < 4; j++) {
                const int sc = (tx << 2) + j;
                const bool ok = (pq != 0.f) && (psj[j] != 0.f) &&
                                (!diagblk || (sc <= r));
                if (!ok) sacc[i][j] = -1e9f;
            }
        }

        // Online softmax per row (16 lanes share a row; shfl width 16)
        #pragma unroll
        for (int i = 0; i < 4; i++) {
            const int r = (ty << 2) + i;
            const float mold = sm->m_s[r];  // read BEFORE shfl barrier
            float rm = fmaxf(fmaxf(sacc[i][0], sacc[i][1]),
                             fmaxf(sacc[i][2], sacc[i][3]));
            rm = fmaxf(rm, __shfl_xor_sync(0xffffffffu, rm, 1));
            rm = fmaxf(rm, __shfl_xor_sync(0xffffffffu, rm, 2));
            rm = fmaxf(rm, __shfl_xor_sync(0xffffffffu, rm, 4));
            rm = fmaxf(rm, __shfl_xor_sync(0xffffffffu, rm, 8));
            const float mnew = fmaxf(mold, rm);
            const float alpha = __expf(mold - mnew);
            float rs = 0.f;
            #pragma unroll
            for (int j = 0; j < 4; j++) {
                const float p = __expf(sacc[i][j] - mnew);
                sacc[i][j] = p;
                rs += p;
            }
            rs += __shfl_xor_sync(0xffffffffu, rs, 1);
            rs += __shfl_xor_sync(0xffffffffu, rs, 2);
            rs += __shfl_xor_sync(0xffffffffu, rs, 4);
            rs += __shfl_xor_sync(0xffffffffu, rs, 8);
            if (tx == 0) {
                sm->m_s[r] = mnew;
                sm->l_s[r] = sm->l_s[r] * alpha + rs;
            }
            #pragma unroll
            for (int j = 0; j < 4; j++) o[i][j] *= alpha;
        }

        // Write P transposed: Ps[s][r]
        #pragma unroll
        for (int i = 0; i < 4; i++)
            #pragma unroll
            for (int j = 0; j < 4; j++)
                sm->Ps[(tx << 2) + j][(ty << 2) + i] = sacc[i][j];
        __syncthreads();

        // O += P V (each thread 4 rows x 4 h)
        #pragma unroll 16
        for (int s = 0; s < 64; s++) {
            const float4 a4 = *(const float4*)&sm->Ps[s][ty << 2];
            const float4 b4 = *(const float4*)&sm->Vs[s][tx << 2];
            const float av[4] = {a4.x, a4.y, a4.z, a4.w};
            const float bv[4] = {b4.x, b4.y, b4.z, b4.w};
            #pragma unroll
            for (int i = 0; i < 4; i++)
                #pragma unroll
                for (int j = 0; j < 4; j++)
                    o[i][j] = fmaf(av[i], bv[j], o[i][j]);
        }
        __syncthreads();  // before next tile overwrites Ks/Vs/Ps
    }

    // Finalize
    #pragma unroll
    for (int i = 0; i < 4; i++) {
        const int r = (ty << 2) + i;
        const float linv = 1.f / sm->l_s[r];
        const int t = t0 + r;
        float4 ov;
        ov.x = o[i][0] * linv; ov.y = o[i][1] * linv;
        ov.z = o[i][2] * linv; ov.w = o[i][3] * linv;
        *(float4*)(out + ((size_t)((b * TT + t) * NHEAD + n)) * HDIM + (tx << 2)) = ov;
    }
}

// ---------------------------------------------------------------------------
// Host launch
// ---------------------------------------------------------------------------
extern "C" void kernel_launch(void* const* d_in, const int* in_sizes, int n_in,
                              void* d_out, int out_size)
{
    (void)in_sizes; (void)n_in; (void)out_size;
    const float* x         = (const float*)d_in[0];
    const float* padding   = (const float*)d_in[1];
    const float* rms_scale = (const float*)d_in[2];
    const float* pds       = (const float*)d_in[3];
    const float* wq        = (const float*)d_in[4];
    const float* bq        = (const float*)d_in[5];
    const float* wk        = (const float*)d_in[6];
    const float* bk        = (const float*)d_in[7];
    const float* wv        = (const float*)d_in[8];
    const float* bv        = (const float*)d_in[9];
    const float* wo        = (const float*)d_in[10];
    const float* bo        = (const float*)d_in[11];
    const float* ln_gamma  = (const float*)d_in[12];
    const float* ln_beta   = (const float*)d_in[13];
    const float* w1        = (const float*)d_in[14];
    const float* b1        = (const float*)d_in[15];
    const float* w2        = (const float*)d_in[16];
    const float* b2        = (const float*)d_in[17];
    float* out = (float*)d_out;

    float *xn, *q, *k, *v, *ao, *ar, *hn, *h1;
    cudaGetSymbolAddress((void**)&xn, g_xn);
    cudaGetSymbolAddress((void**)&q,  g_q);
    cudaGetSymbolAddress((void**)&k,  g_k);
    cudaGetSymbolAddress((void**)&v,  g_v);
    cudaGetSymbolAddress((void**)&ao, g_ao);
    cudaGetSymbolAddress((void**)&ar, g_ar);
    cudaGetSymbolAddress((void**)&hn, g_hn);
    cudaGetSymbolAddress((void**)&h1, g_h1);

    const int flash_smem = (int)sizeof(FlashSmem);
    cudaFuncSetAttribute(flash_kernel,
                         cudaFuncAttributeMaxDynamicSharedMemorySize, flash_smem);

    // 1. RMSNorm
    rmsnorm_kernel<<<MM, 256>>>(x, rms_scale, xn);

    // 2. QKV projections (q fused with per-dim softplus scale)
    dim3 gD(DD / 128, MM / 128);
    sgemm_kernel<1, false><<<gD, 256>>>(xn, wq, bq, pds,    q, MM, DD, DD);
    sgemm_kernel<0, false><<<gD, 256>>>(xn, wk, bk, nullptr, k, MM, DD, DD);
    sgemm_kernel<0, false><<<gD, 256>>>(xn, wv, bv, nullptr, v, MM, DD, DD);

    // 3. Flash attention
    flash_kernel<<<dim3(TT / 64, BB * NHEAD), 256, flash_smem>>>(q, k, v, padding, ao);

    // 4. Output projection (B^T orientation) + bias + residual(x)
    sgemm_kernel<2, true><<<gD, 256>>>(ao, wo, bo, x, ar, MM, DD, DD);

    // 5. LayerNorm
    layernorm_kernel<<<MM, 256>>>(ar, ln_gamma, ln_beta, hn);

    // 6. FFN up + ReLU
    dim3 gF(FF / 128, MM / 128);
    sgemm_kernel<3, false><<<gF, 256>>>(hn, w1, b1, nullptr, h1, MM, FF, DD);

    // 7. FFN down + bias + residual(ar) -> final output
    sgemm_kernel<2, false><<<gD, 256>>>(h1, w2, b2, ar, out, MM, DD, FF);
}

// round 3
// speedup vs baseline: 3.0877x; 3.0877x over previous
#include <cuda_runtime.h>
#include <cstdint>
#include <math.h>

// Problem constants
#define BB 8
#define TT 1024
#define DD 1024
#define NHEAD 16
#define HDIM 64
#define FF 4096
#define MM (BB * TT)   // 8192

// ---------------------------------------------------------------------------
// Scratch (device globals)
// ---------------------------------------------------------------------------
__device__ float g_xn[MM * DD];
__device__ float g_q [MM * DD];
__device__ float g_k [MM * DD];
__device__ float g_v [MM * DD];
__device__ float g_ao[MM * DD];
__device__ float g_ar[MM * DD];
__device__ float g_hn[MM * DD];
__device__ float g_h1[MM * FF];
// transposed / rounded weights: [N][K] K-major
__device__ float g_wqt[DD * DD];
__device__ float g_wkt[DD * DD];
__device__ float g_wvt[DD * DD];
__device__ float g_wot[DD * DD];
__device__ float g_w1t[FF * DD];
__device__ float g_w2t[DD * FF];

// ---------------------------------------------------------------------------
// Helpers
// ---------------------------------------------------------------------------
__device__ __forceinline__ float rtf32(float x) {
    uint32_t u;
    asm("cvt.rna.tf32.f32 %0, %1;" : "=r"(u) : "f"(x));
    return __uint_as_float(u);
}

__device__ __forceinline__ uint32_t s2u(const void* p) {
    uint32_t a;
    asm("{ .reg .u64 t; cvta.to.shared.u64 t, %1; cvt.u32.u64 %0, t; }"
        : "=r"(a) : "l"(p));
    return a;
}

__device__ __forceinline__ void cp_async16(uint32_t saddr, const void* gaddr) {
    asm volatile("cp.async.cg.shared.global [%0], [%1], 16;"
                 :: "r"(saddr), "l"(gaddr));
}
__device__ __forceinline__ void cp_commit() {
    asm volatile("cp.async.commit_group;");
}
template <int N>
__device__ __forceinline__ void cp_wait() {
    asm volatile("cp.async.wait_group %0;" :: "n"(N));
}

__device__ __forceinline__ void ldsm4(uint32_t& r0, uint32_t& r1,
                                      uint32_t& r2, uint32_t& r3, uint32_t addr) {
    asm volatile("ldmatrix.sync.aligned.m8n8.x4.shared.b16 {%0,%1,%2,%3}, [%4];"
                 : "=r"(r0), "=r"(r1), "=r"(r2), "=r"(r3) : "r"(addr));
}

__device__ __forceinline__ void mma_tf32(float* c, const uint32_t* a,
                                         uint32_t b0, uint32_t b1) {
    asm volatile(
        "mma.sync.aligned.m16n8k8.row.col.f32.tf32.tf32.f32 "
        "{%0,%1,%2,%3}, {%4,%5,%6,%7}, {%8,%9}, {%0,%1,%2,%3};"
        : "+f"(c[0]), "+f"(c[1]), "+f"(c[2]), "+f"(c[3])
        : "r"(a[0]), "r"(a[1]), "r"(a[2]), "r"(a[3]), "r"(b0), "r"(b1));
}

// ---------------------------------------------------------------------------
// Prep kernels: transpose + round weights into [N][K] K-major
// ---------------------------------------------------------------------------
__global__ __launch_bounds__(256) void transpose_round_kernel(
    const float* __restrict__ in, float* __restrict__ out, int R, int C)
{
    __shared__ float t[32][33];
    const int bx = blockIdx.x << 5, by = blockIdx.y << 5;
    const int txx = threadIdx.x, tyy = threadIdx.y;
    #pragma unroll
    for (int j = 0; j < 32; j += 8)
        t[tyy + j][txx] = rtf32(in[(size_t)(by + tyy + j) * C + bx + txx]);
    __syncthreads();
    #pragma unroll
    for (int j = 0; j < 32; j += 8)
        out[(size_t)(bx + tyy + j) * R + by + txx] = t[txx][tyy + j];
}

__global__ __launch_bounds__(256) void round_copy_kernel(
    const float* __restrict__ in, float* __restrict__ out, int n4)
{
    const int i = blockIdx.x * 256 + threadIdx.x;
    if (i < n4) {
        float4 v = ((const float4*)in)[i];
        v.x = rtf32(v.x); v.y = rtf32(v.y); v.z = rtf32(v.z); v.w = rtf32(v.w);
        ((float4*)out)[i] = v;
    }
}

// ---------------------------------------------------------------------------
// RMSNorm (tf32-rounded output)
// ---------------------------------------------------------------------------
__global__ __launch_bounds__(256) void rmsnorm_kernel(
    const float* __restrict__ x, const float* __restrict__ scale,
    float* __restrict__ out)
{
    const int row = blockIdx.x;
    const int tid = threadIdx.x;
    const float4 v = ((const float4*)(x + (size_t)row * DD))[tid];
    float ss = v.x * v.x + v.y * v.y + v.z * v.z + v.w * v.w;
    #pragma unroll
    for (int m = 16; m; m >>= 1) ss += __shfl_xor_sync(0xffffffffu, ss, m);
    __shared__ float sred[8];
    if ((tid & 31) == 0) sred[tid >> 5] = ss;
    __syncthreads();
    float tot = 0.f;
    #pragma unroll
    for (int i = 0; i < 8; i++) tot += sred[i];
    const float r = rsqrtf(tot * (1.0f / DD) + 1e-6f);
    const float4 s4 = ((const float4*)scale)[tid];
    float4 o;
    o.x = rtf32(v.x * r * s4.x); o.y = rtf32(v.y * r * s4.y);
    o.z = rtf32(v.z * r * s4.z); o.w = rtf32(v.w * r * s4.w);
    ((float4*)(out + (size_t)row * DD))[tid] = o;
}

// ---------------------------------------------------------------------------
// LayerNorm (tf32-rounded output)
// ---------------------------------------------------------------------------
__global__ __launch_bounds__(256) void layernorm_kernel(
    const float* __restrict__ x, const float* __restrict__ gamma,
    const float* __restrict__ beta, float* __restrict__ out)
{
    const int row = blockIdx.x;
    const int tid = threadIdx.x;
    const float4 v = ((const float4*)(x + (size_t)row * DD))[tid];
    float s  = v.x + v.y + v.z + v.w;
    float ss = v.x * v.x + v.y * v.y + v.z * v.z + v.w * v.w;
    #pragma unroll
    for (int m = 16; m; m >>= 1) {
        s  += __shfl_xor_sync(0xffffffffu, s,  m);
        ss += __shfl_xor_sync(0xffffffffu, ss, m);
    }
    __shared__ float sr1[8], sr2[8];
    if ((tid & 31) == 0) { sr1[tid >> 5] = s; sr2[tid >> 5] = ss; }
    __syncthreads();
    float S = 0.f, SS = 0.f;
    #pragma unroll
    for (int i = 0; i < 8; i++) { S += sr1[i]; SS += sr2[i]; }
    const float mean = S * (1.0f / DD);
    const float var  = SS * (1.0f / DD) - mean * mean;
    const float r = rsqrtf(var + 1e-5f);
    const float4 g4 = ((const float4*)gamma)[tid];
    const float4 b4 = ((const float4*)beta)[tid];
    float4 o;
    o.x = rtf32((v.x - mean) * r * g4.x + b4.x);
    o.y = rtf32((v.y - mean) * r * g4.y + b4.y);
    o.z = rtf32((v.z - mean) * r * g4.z + b4.z);
    o.w = rtf32((v.w - mean) * r * g4.w + b4.w);
    ((float4*)(out + (size_t)row * DD))[tid] = o;
}

// ---------------------------------------------------------------------------
// mma.sync tf32 GEMM: C[M,N] = A[M,K] @ Bw^T  (Bw stored [N][K] K-major)
// CTA tile 128x128, BK=32, 3-stage cp.async pipeline, 8 warps (32x64 each).
// EPI: 0=+bias  1=(+bias)*qscale  2=+bias+residual  3=relu(+bias)+tf32round
// ---------------------------------------------------------------------------
__device__ __forceinline__ float softplus_f(float x) {
    return (x > 15.f) ? x : log1pf(__expf(x));
}

#define GSTAGE 32768              // bytes per stage (A 16KB + B 16KB)
#define GEMM_SMEM_BYTES (3 * GSTAGE)

template <int EPI>
__global__ __launch_bounds__(256, 2) void mma_gemm_kernel(
    const float* __restrict__ A, const float* __restrict__ Bw,
    const float* __restrict__ bias, const float* __restrict__ extra,
    float* __restrict__ C, int M, int N, int K)
{
    extern __shared__ char gsm[];
    const uint32_t smbase = s2u(gsm);
    const int tid = threadIdx.x;
    const int lane = tid & 31;
    const int wid = tid >> 5;
    const int m0 = blockIdx.y << 7;
    const int n0 = blockIdx.x << 7;
    const int wm = (wid & 3) << 5;   // warp m offset (0..96)
    const int wn = (wid >> 2) << 6;  // warp n offset (0/64)

    // ---- loader precompute: 4 A chunks + 4 B chunks (16B each) per thread
    uint32_t a_soff[4], b_soff[4];
    const float* a_g[4]; const float* b_g[4];
    #pragma unroll
    for (int u = 0; u < 4; u++) {
        const int qch = tid + u * 256;          // 0..1023
        const int m = qch >> 3, kc = qch & 7;
        const uint32_t sw = (uint32_t)(kc ^ (m & 7));
        a_soff[u] = (uint32_t)(m * 128) + (sw << 4);
        b_soff[u] = a_soff[u] + 16384u;
        a_g[u] = A  + (size_t)(m0 + m) * K + kc * 4;
        b_g[u] = Bw + (size_t)(n0 + m) * K + kc * 4;
    }

    // ---- fragment address precompute (ldmatrix row addresses)
    const int arow = wm + (lane & 15);
    const uint32_t acadd = (uint32_t)(lane >> 4);       // chunk add 0/1
    const uint32_t aswz = (uint32_t)(arow & 7);
    const uint32_t aoff = (uint32_t)(arow * 128);
    const int brow = wn + ((lane >> 4) << 3) + (lane & 7);
    const uint32_t bcc = (uint32_t)((lane >> 3) & 1);
    const uint32_t bswz = (uint32_t)(brow & 7);
    const uint32_t boff = (uint32_t)(brow * 128) + 16384u;

    float acc[2][8][4];
    #pragma unroll
    for (int i = 0; i < 2; i++)
        #pragma unroll
        for (int j = 0; j < 8; j++)
            #pragma unroll
            for (int t = 0; t < 4; t++) acc[i][j][t] = 0.f;

    const int nk = K >> 5;

    // prologue: stages 0 and 1
    #pragma unroll
    for (int s = 0; s < 2; s++) {
        const uint32_t sb = smbase + (uint32_t)s * GSTAGE;
        #pragma unroll
        for (int u = 0; u < 4; u++) {
            cp_async16(sb + a_soff[u], a_g[u] + s * 32);
            cp_async16(sb + b_soff[u], b_g[u] + s * 32);
        }
        cp_commit();
    }

    int sidx = 0;  // stage index of current kc (kc % 3)
    for (int kc = 0; kc < nk; kc++) {
        if (kc == nk - 1) cp_wait<0>(); else cp_wait<1>();
        __syncthreads();
        if (kc + 2 < nk) {
            const int s2 = (sidx + 2 >= 3) ? sidx - 1 : sidx + 2;
            const uint32_t sb = smbase + (uint32_t)s2 * GSTAGE;
            #pragma unroll
            for (int u = 0; u < 4; u++) {
                cp_async16(sb + a_soff[u], a_g[u] + (kc + 2) * 32);
                cp_async16(sb + b_soff[u], b_g[u] + (kc + 2) * 32);
            }
            cp_commit();
        }
        const uint32_t sb = smbase + (uint32_t)sidx * GSTAGE;
        #pragma unroll
        for (int ks = 0; ks < 4; ks++) {
            const uint32_t kc0 = (uint32_t)(2 * ks);
            uint32_t af[2][4];
            #pragma unroll
            for (int i = 0; i < 2; i++) {
                const uint32_t addr = sb + aoff + (uint32_t)(i * 2048) +
                                      (((kc0 + acadd) ^ aswz) << 4);
                ldsm4(af[i][0], af[i][1], af[i][2], af[i][3], addr);
            }
            #pragma unroll
            for (int jp = 0; jp < 4; jp++) {
                uint32_t b0, b1, b2, b3;
                const uint32_t addr = sb + boff + (uint32_t)(jp * 2048) +
                                      (((kc0 + bcc) ^ bswz) << 4);
                ldsm4(b0, b1, b2, b3, addr);
                #pragma unroll
                for (int i = 0; i < 2; i++) {
                    mma_tf32(acc[i][2 * jp + 0], af[i], b0, b1);
                    mma_tf32(acc[i][2 * jp + 1], af[i], b2, b3);
                }
            }
        }
        sidx = (sidx == 2) ? 0 : sidx + 1;
    }

    // ---- epilogue
    const int g = lane >> 2, tg = lane & 3;
    #pragma unroll
    for (int i = 0; i < 2; i++) {
        #pragma unroll
        for (int j = 0; j < 8; j++) {
            const int col = n0 + wn + j * 8 + tg * 2;
            const float2 b2 = *(const float2*)(bias + col);
            float sx = 1.f, sy = 1.f;
            if (EPI == 1) {
                const float c = 0.18033688f;  // log2(e)/sqrt(64)
                sx = c * softplus_f(extra[col & 63]);
                sy = c * softplus_f(extra[(col + 1) & 63]);
            }
            #pragma unroll
            for (int h = 0; h < 2; h++) {
                const int row = m0 + wm + i * 16 + g + h * 8;
                float vx = acc[i][j][2 * h + 0] + b2.x;
                float vy = acc[i][j][2 * h + 1] + b2.y;
                if (EPI == 1) { vx *= sx; vy *= sy; }
                if (EPI == 2) {
                    const float2 r2 = *(const float2*)(extra + (size_t)row * N + col);
                    vx += r2.x; vy += r2.y;
                }
                if (EPI == 3) {
                    vx = rtf32(fmaxf(vx, 0.f));
                    vy = rtf32(fmaxf(vy, 0.f));
                }
                float2 o2; o2.x = vx; o2.y = vy;
                *(float2*)(C + (size_t)row * N + col) = o2;
            }
        }
    }
}

// ---------------------------------------------------------------------------
// Flash attention (fp32 FFMA), output tf32-rounded
// ---------------------------------------------------------------------------
#define FPAD 68
struct FlashSmem {
    float Qs[64][FPAD];
    float Ks[64][FPAD];
    float Vs[64][FPAD];
    float Ps[64][FPAD];
    float m_s[64];
    float l_s[64];
    float padq[64];
    float pads[64];
};

__global__ __launch_bounds__(256) void flash_kernel(
    const float* __restrict__ q, const float* __restrict__ k,
    const float* __restrict__ v, const float* __restrict__ pad,
    float* __restrict__ out)
{
    extern __shared__ char smraw[];
    FlashSmem* sm = (FlashSmem*)smraw;
    const int tid = threadIdx.x;
    const int tx = tid & 15;
    const int ty = tid >> 4;
    const int t0 = blockIdx.x << 6;
    const int bn = blockIdx.y;
    const int b = bn >> 4, n = bn & 15;

    {
        const int r = tid >> 2;
        const int h0 = (tid & 3) << 4;
        const float* qp = q + ((size_t)((b * TT + t0 + r) * NHEAD + n)) * HDIM + h0;
        #pragma unroll
        for (int u = 0; u < 4; u++) {
            const float4 qv = *(const float4*)(qp + u * 4);
            sm->Qs[h0 + u * 4 + 0][r] = qv.x;
            sm->Qs[h0 + u * 4 + 1][r] = qv.y;
            sm->Qs[h0 + u * 4 + 2][r] = qv.z;
            sm->Qs[h0 + u * 4 + 3][r] = qv.w;
        }
    }
    if (tid < 64) {
        sm->m_s[tid] = -1e30f;
        sm->l_s[tid] = 0.f;
        sm->padq[tid] = pad[b * TT + t0 + tid];
    }
    float o[4][4] = {};

    for (int s0 = 0; s0 <= t0; s0 += 64) {
        {
            const int r = tid >> 2;
            const int h0 = (tid & 3) << 4;
            const float* kp = k + ((size_t)((b * TT + s0 + r) * NHEAD + n)) * HDIM + h0;
            #pragma unroll
            for (int u = 0; u < 4; u++) {
                const float4 kv = *(const float4*)(kp + u * 4);
                sm->Ks[h0 + u * 4 + 0][r] = kv.x;
                sm->Ks[h0 + u * 4 + 1][r] = kv.y;
                sm->Ks[h0 + u * 4 + 2][r] = kv.z;
                sm->Ks[h0 + u * 4 + 3][r] = kv.w;
            }
            const float* vp = v + ((size_t)((b * TT + s0 + r) * NHEAD + n)) * HDIM + h0;
            #pragma unroll
            for (int u = 0; u < 4; u++)
                *(float4*)&sm->Vs[r][h0 + u * 4] = *(const float4*)(vp + u * 4);
            if (tid < 64) sm->pads[tid] = pad[b * TT + s0 + tid];
        }
        __syncthreads();

        float sacc[4][4] = {};
        #pragma unroll 16
        for (int h = 0; h < 64; h++) {
            const float4 a4 = *(const float4*)&sm->Qs[h][ty << 2];
            const float4 b4 = *(const float4*)&sm->Ks[h][tx << 2];
            const float av[4] = {a4.x, a4.y, a4.z, a4.w};
            const float bv[4] = {b4.x, b4.y, b4.z, b4.w};
            #pragma unroll
            for (int i = 0; i < 4; i++)
                #pragma unroll
                for (int j = 0; j < 4; j++)
                    sacc[i][j] = fmaf(av[i], bv[j], sacc[i][j]);
        }

        const bool diagblk = (s0 == t0);
        float psj[4];
        #pragma unroll
        for (int j = 0; j < 4; j++) psj[j] = sm->pads[(tx << 2) + j];
        #pragma unroll
        for (int i = 0; i < 4; i++) {
            const int rr = (ty << 2) + i;
            const float pq = sm->padq[rr];
            #pragma unroll
            for (int j = 0; j < 4; j++) {
                const int sc = (tx << 2) + j;
                const bool ok = (pq != 0.f) && (psj[j] != 0.f) &&
                                (!diagblk || (sc <= rr));
                if (!ok) sacc[i][j] = -1e9f;
            }
        }

        #pragma unroll
        for (int i = 0; i < 4; i++) {
            const int rr = (ty << 2) + i;
            const float mold = sm->m_s[rr];
            float rm = fmaxf(fmaxf(sacc[i][0], sacc[i][1]),
                             fmaxf(sacc[i][2], sacc[i][3]));
            rm = fmaxf(rm, __shfl_xor_sync(0xffffffffu, rm, 1));
            rm = fmaxf(rm, __shfl_xor_sync(0xffffffffu, rm, 2));
            rm = fmaxf(rm, __shfl_xor_sync(0xffffffffu, rm, 4));
            rm = fmaxf(rm, __shfl_xor_sync(0xffffffffu, rm, 8));
            const float mnew = fmaxf(mold, rm);
            const float alpha = __expf(mold - mnew);
            float rs = 0.f;
            #pragma unroll
            for (int j = 0; j < 4; j++) {
                const float p = __expf(sacc[i][j] - mnew);
                sacc[i][j] = p;
                rs += p;
            }
            rs += __shfl_xor_sync(0xffffffffu, rs, 1);
            rs += __shfl_xor_sync(0xffffffffu, rs, 2);
            rs += __shfl_xor_sync(0xffffffffu, rs, 4);
            rs += __shfl_xor_sync(0xffffffffu, rs, 8);
            if (tx == 0) {
                sm->m_s[rr] = mnew;
                sm->l_s[rr] = sm->l_s[rr] * alpha + rs;
            }
            #pragma unroll
            for (int j = 0; j < 4; j++) o[i][j] *= alpha;
        }

        #pragma unroll
        for (int i = 0; i < 4; i++)
            #pragma unroll
            for (int j = 0; j < 4; j++)
                sm->Ps[(tx << 2) + j][(ty << 2) + i] = sacc[i][j];
        __syncthreads();

        #pragma unroll 16
        for (int s = 0; s < 64; s++) {
            const float4 a4 = *(const float4*)&sm->Ps[s][ty << 2];
            const float4 b4 = *(const float4*)&sm->Vs[s][tx << 2];
            const float av[4] = {a4.x, a4.y, a4.z, a4.w};
            const float bv[4] = {b4.x, b4.y, b4.z, b4.w};
            #pragma unroll
            for (int i = 0; i < 4; i++)
                #pragma unroll
                for (int j = 0; j < 4; j++)
                    o[i][j] = fmaf(av[i], bv[j], o[i][j]);
        }
        __syncthreads();
    }

    #pragma unroll
    for (int i = 0; i < 4; i++) {
        const int rr = (ty << 2) + i;
        const float linv = 1.f / sm->l_s[rr];
        const int t = t0 + rr;
        float4 ov;
        ov.x = rtf32(o[i][0] * linv); ov.y = rtf32(o[i][1] * linv);
        ov.z = rtf32(o[i][2] * linv); ov.w = rtf32(o[i][3] * linv);
        *(float4*)(out + ((size_t)((b * TT + t) * NHEAD + n)) * HDIM + (tx << 2)) = ov;
    }
}

// ---------------------------------------------------------------------------
// Host launch
// ---------------------------------------------------------------------------
extern "C" void kernel_launch(void* const* d_in, const int* in_sizes, int n_in,
                              void* d_out, int out_size)
{
    (void)in_sizes; (void)n_in; (void)out_size;
    const float* x         = (const float*)d_in[0];
    const float* padding   = (const float*)d_in[1];
    const float* rms_scale = (const float*)d_in[2];
    const float* pds       = (const float*)d_in[3];
    const float* wq        = (const float*)d_in[4];
    const float* bq        = (const float*)d_in[5];
    const float* wk        = (const float*)d_in[6];
    const float* bk        = (const float*)d_in[7];
    const float* wv        = (const float*)d_in[8];
    const float* bv        = (const float*)d_in[9];
    const float* wo        = (const float*)d_in[10];
    const float* bo        = (const float*)d_in[11];
    const float* ln_gamma  = (const float*)d_in[12];
    const float* ln_beta   = (const float*)d_in[13];
    const float* w1        = (const float*)d_in[14];
    const float* b1        = (const float*)d_in[15];
    const float* w2        = (const float*)d_in[16];
    const float* b2        = (const float*)d_in[17];
    float* out = (float*)d_out;

    float *xn, *q, *k, *v, *ao, *ar, *hn, *h1;
    float *wqt, *wkt, *wvt, *wot, *w1t, *w2t;
    cudaGetSymbolAddress((void**)&xn, g_xn);
    cudaGetSymbolAddress((void**)&q,  g_q);
    cudaGetSymbolAddress((void**)&k,  g_k);
    cudaGetSymbolAddress((void**)&v,  g_v);
    cudaGetSymbolAddress((void**)&ao, g_ao);
    cudaGetSymbolAddress((void**)&ar, g_ar);
    cudaGetSymbolAddress((void**)&hn, g_hn);
    cudaGetSymbolAddress((void**)&h1, g_h1);
    cudaGetSymbolAddress((void**)&wqt, g_wqt);
    cudaGetSymbolAddress((void**)&wkt, g_wkt);
    cudaGetSymbolAddress((void**)&wvt, g_wvt);
    cudaGetSymbolAddress((void**)&wot, g_wot);
    cudaGetSymbolAddress((void**)&w1t, g_w1t);
    cudaGetSymbolAddress((void**)&w2t, g_w2t);

    static int attr_done = 0;
    if (!attr_done) {
        cudaFuncSetAttribute(flash_kernel,
            cudaFuncAttributeMaxDynamicSharedMemorySize, (int)sizeof(FlashSmem));
        cudaFuncSetAttribute(mma_gemm_kernel<0>,
            cudaFuncAttributeMaxDynamicSharedMemorySize, GEMM_SMEM_BYTES);
        cudaFuncSetAttribute(mma_gemm_kernel<1>,
            cudaFuncAttributeMaxDynamicSharedMemorySize, GEMM_SMEM_BYTES);
        cudaFuncSetAttribute(mma_gemm_kernel<2>,
            cudaFuncAttributeMaxDynamicSharedMemorySize, GEMM_SMEM_BYTES);
        cudaFuncSetAttribute(mma_gemm_kernel<3>,
            cudaFuncAttributeMaxDynamicSharedMemorySize, GEMM_SMEM_BYTES);
        attr_done = 1;
    }

    // 0. Weight prep: transpose+round to [N][K] K-major (wo: round only)
    dim3 tb(32, 8);
    transpose_round_kernel<<<dim3(DD / 32, DD / 32), tb>>>(wq, wqt, DD, DD);
    transpose_round_kernel<<<dim3(DD / 32, DD / 32), tb>>>(wk, wkt, DD, DD);
    transpose_round_kernel<<<dim3(DD / 32, DD / 32), tb>>>(wv, wvt, DD, DD);
    transpose_round_kernel<<<dim3(FF / 32, DD / 32), tb>>>(w1, w1t, DD, FF);
    transpose_round_kernel<<<dim3(DD / 32, FF / 32), tb>>>(w2, w2t, FF, DD);
    round_copy_kernel<<<(DD * DD / 4 + 255) / 256, 256>>>(wo, wot, DD * DD / 4);

    // 1. RMSNorm (rounded)
    rmsnorm_kernel<<<MM, 256>>>(x, rms_scale, xn);

    // 2. QKV projections (mma.sync tf32)
    dim3 gD(DD / 128, MM / 128);
    mma_gemm_kernel<1><<<gD, 256, GEMM_SMEM_BYTES>>>(xn, wqt, bq, pds,    q, MM, DD, DD);
    mma_gemm_kernel<0><<<gD, 256, GEMM_SMEM_BYTES>>>(xn, wkt, bk, nullptr, k, MM, DD, DD);
    mma_gemm_kernel<0><<<gD, 256, GEMM_SMEM_BYTES>>>(xn, wvt, bv, nullptr, v, MM, DD, DD);

    // 3. Flash attention (fp32, rounded output)
    flash_kernel<<<dim3(TT / 64, BB * NHEAD), 256, (int)sizeof(FlashSmem)>>>(
        q, k, v, padding, ao);

    // 4. Output projection + bias + residual(x)
    mma_gemm_kernel<2><<<gD, 256, GEMM_SMEM_BYTES>>>(ao, wot, bo, x, ar, MM, DD, DD);

    // 5. LayerNorm (rounded)
    layernorm_kernel<<<MM, 256>>>(ar, ln_gamma, ln_beta, hn);

    // 6. FFN up + ReLU (rounded)
    dim3 gF(FF / 128, MM / 128);
    mma_gemm_kernel<3><<<gF, 256, GEMM_SMEM_BYTES>>>(hn, w1t, b1, nullptr, h1, MM, FF, DD);

    // 7. FFN down + bias + residual(ar) -> output
    mma_gemm_kernel<2><<<gD, 256, GEMM_SMEM_BYTES>>>(h1, w2t, b2, ar, out, MM, DD, FF);
}

// round 4
// speedup vs baseline: 3.9336x; 1.2740x over previous
#include <cuda_runtime.h>
#include <cstdint>
#include <math.h>

// Problem constants
#define BB 8
#define TT 1024
#define DD 1024
#define NHEAD 16
#define HDIM 64
#define FF 4096
#define MM (BB * TT)   // 8192
#define QKVN 3072

// ---------------------------------------------------------------------------
// Scratch (device globals)
// ---------------------------------------------------------------------------
__device__ float g_xn [MM * DD];
__device__ float g_qkv[MM * QKVN];
__device__ float g_ao [MM * DD];
__device__ float g_ar [MM * DD];
__device__ float g_hn [MM * DD];
__device__ float g_h1 [MM * FF];
__device__ float g_wqkvt[QKVN * DD];   // [3072][1024] K-major (q|k|v)
__device__ float g_bqkv [QKVN];
__device__ float g_wot[DD * DD];
__device__ float g_w1t[FF * DD];
__device__ float g_w2t[DD * FF];

// ---------------------------------------------------------------------------
// Helpers
// ---------------------------------------------------------------------------
__device__ __forceinline__ float rtf32(float x) {
    uint32_t u;
    asm("cvt.rna.tf32.f32 %0, %1;" : "=r"(u) : "f"(x));
    return __uint_as_float(u);
}

__device__ __forceinline__ uint32_t s2u(const void* p) {
    uint32_t a;
    asm("{ .reg .u64 t; cvta.to.shared.u64 t, %1; cvt.u32.u64 %0, t; }"
        : "=r"(a) : "l"(p));
    return a;
}

__device__ __forceinline__ void cp_async16(uint32_t saddr, const void* gaddr) {
    asm volatile("cp.async.cg.shared.global [%0], [%1], 16;"
                 :: "r"(saddr), "l"(gaddr));
}
__device__ __forceinline__ void cp_commit() {
    asm volatile("cp.async.commit_group;");
}
template <int N>
__device__ __forceinline__ void cp_wait() {
    asm volatile("cp.async.wait_group %0;" :: "n"(N));
}

__device__ __forceinline__ void ldsm4(uint32_t& r0, uint32_t& r1,
                                      uint32_t& r2, uint32_t& r3, uint32_t addr) {
    asm volatile("ldmatrix.sync.aligned.m8n8.x4.shared.b16 {%0,%1,%2,%3}, [%4];"
                 : "=r"(r0), "=r"(r1), "=r"(r2), "=r"(r3) : "r"(addr));
}

__device__ __forceinline__ void mma_tf32(float* c, const uint32_t* a,
                                         uint32_t b0, uint32_t b1) {
    asm volatile(
        "mma.sync.aligned.m16n8k8.row.col.f32.tf32.tf32.f32 "
        "{%0,%1,%2,%3}, {%4,%5,%6,%7}, {%8,%9}, {%0,%1,%2,%3};"
        : "+f"(c[0]), "+f"(c[1]), "+f"(c[2]), "+f"(c[3])
        : "r"(a[0]), "r"(a[1]), "r"(a[2]), "r"(a[3]), "r"(b0), "r"(b1));
}

// ---------------------------------------------------------------------------
// Prep kernels
// ---------------------------------------------------------------------------
__global__ __launch_bounds__(256) void transpose_round_kernel(
    const float* __restrict__ in, float* __restrict__ out, int R, int C)
{
    __shared__ float t[32][33];
    const int bx = blockIdx.x << 5, by = blockIdx.y << 5;
    const int txx = threadIdx.x, tyy = threadIdx.y;
    #pragma unroll
    for (int j = 0; j < 32; j += 8)
        t[tyy + j][txx] = rtf32(in[(size_t)(by + tyy + j) * C + bx + txx]);
    __syncthreads();
    #pragma unroll
    for (int j = 0; j < 32; j += 8)
        out[(size_t)(bx + tyy + j) * R + by + txx] = t[txx][tyy + j];
}

__global__ __launch_bounds__(256) void round_copy_kernel(
    const float* __restrict__ in, float* __restrict__ out, int n4)
{
    const int i = blockIdx.x * 256 + threadIdx.x;
    if (i < n4) {
        float4 v = ((const float4*)in)[i];
        v.x = rtf32(v.x); v.y = rtf32(v.y); v.z = rtf32(v.z); v.w = rtf32(v.w);
        ((float4*)out)[i] = v;
    }
}

__global__ __launch_bounds__(256) void concat_bias_kernel(
    const float* __restrict__ bq, const float* __restrict__ bk,
    const float* __restrict__ bv, float* __restrict__ out)
{
    const int i = blockIdx.x * 256 + threadIdx.x;
    if (i < QKVN)
        out[i] = (i < 1024) ? bq[i] : (i < 2048) ? bk[i - 1024] : bv[i - 2048];
}

// ---------------------------------------------------------------------------
// RMSNorm / LayerNorm (tf32-rounded outputs)
// ---------------------------------------------------------------------------
__global__ __launch_bounds__(256) void rmsnorm_kernel(
    const float* __restrict__ x, const float* __restrict__ scale,
    float* __restrict__ out)
{
    const int row = blockIdx.x;
    const int tid = threadIdx.x;
    const float4 v = ((const float4*)(x + (size_t)row * DD))[tid];
    float ss = v.x * v.x + v.y * v.y + v.z * v.z + v.w * v.w;
    #pragma unroll
    for (int m = 16; m; m >>= 1) ss += __shfl_xor_sync(0xffffffffu, ss, m);
    __shared__ float sred[8];
    if ((tid & 31) == 0) sred[tid >> 5] = ss;
    __syncthreads();
    float tot = 0.f;
    #pragma unroll
    for (int i = 0; i < 8; i++) tot += sred[i];
    const float r = rsqrtf(tot * (1.0f / DD) + 1e-6f);
    const float4 s4 = ((const float4*)scale)[tid];
    float4 o;
    o.x = rtf32(v.x * r * s4.x); o.y = rtf32(v.y * r * s4.y);
    o.z = rtf32(v.z * r * s4.z); o.w = rtf32(v.w * r * s4.w);
    ((float4*)(out + (size_t)row * DD))[tid] = o;
}

__global__ __launch_bounds__(256) void layernorm_kernel(
    const float* __restrict__ x, const float* __restrict__ gamma,
    const float* __restrict__ beta, float* __restrict__ out)
{
    const int row = blockIdx.x;
    const int tid = threadIdx.x;
    const float4 v = ((const float4*)(x + (size_t)row * DD))[tid];
    float s  = v.x + v.y + v.z + v.w;
    float ss = v.x * v.x + v.y * v.y + v.z * v.z + v.w * v.w;
    #pragma unroll
    for (int m = 16; m; m >>= 1) {
        s  += __shfl_xor_sync(0xffffffffu, s,  m);
        ss += __shfl_xor_sync(0xffffffffu, ss, m);
    }
    __shared__ float sr1[8], sr2[8];
    if ((tid & 31) == 0) { sr1[tid >> 5] = s; sr2[tid >> 5] = ss; }
    __syncthreads();
    float S = 0.f, SS = 0.f;
    #pragma unroll
    for (int i = 0; i < 8; i++) { S += sr1[i]; SS += sr2[i]; }
    const float mean = S * (1.0f / DD);
    const float var  = SS * (1.0f / DD) - mean * mean;
    const float r = rsqrtf(var + 1e-5f);
    const float4 g4 = ((const float4*)gamma)[tid];
    const float4 b4 = ((const float4*)beta)[tid];
    float4 o;
    o.x = rtf32((v.x - mean) * r * g4.x + b4.x);
    o.y = rtf32((v.y - mean) * r * g4.y + b4.y);
    o.z = rtf32((v.z - mean) * r * g4.z + b4.z);
    o.w = rtf32((v.w - mean) * r * g4.w + b4.w);
    ((float4*)(out + (size_t)row * DD))[tid] = o;
}

// ---------------------------------------------------------------------------
// mma.sync tf32 GEMM (as R3, + RND flag + qscale guarded to col<1024)
// ---------------------------------------------------------------------------
__device__ __forceinline__ float softplus_f(float x) {
    return (x > 15.f) ? x : log1pf(__expf(x));
}

#define GSTAGE 32768
#define GEMM_SMEM_BYTES (3 * GSTAGE)

template <int EPI, bool RND>
__global__ __launch_bounds__(256, 2) void mma_gemm_kernel(
    const float* __restrict__ A, const float* __restrict__ Bw,
    const float* __restrict__ bias, const float* __restrict__ extra,
    float* __restrict__ C, int M, int N, int K)
{
    extern __shared__ char gsm[];
    const uint32_t smbase = s2u(gsm);
    const int tid = threadIdx.x;
    const int lane = tid & 31;
    const int wid = tid >> 5;
    const int m0 = blockIdx.y << 7;
    const int n0 = blockIdx.x << 7;
    const int wm = (wid & 3) << 5;
    const int wn = (wid >> 2) << 6;

    uint32_t a_soff[4], b_soff[4];
    const float* a_g[4]; const float* b_g[4];
    #pragma unroll
    for (int u = 0; u < 4; u++) {
        const int qch = tid + u * 256;
        const int m = qch >> 3, kc = qch & 7;
        const uint32_t sw = (uint32_t)(kc ^ (m & 7));
        a_soff[u] = (uint32_t)(m * 128) + (sw << 4);
        b_soff[u] = a_soff[u] + 16384u;
        a_g[u] = A  + (size_t)(m0 + m) * K + kc * 4;
        b_g[u] = Bw + (size_t)(n0 + m) * K + kc * 4;
    }

    const int arow = wm + (lane & 15);
    const uint32_t acadd = (uint32_t)(lane >> 4);
    const uint32_t aswz = (uint32_t)(arow & 7);
    const uint32_t aoff = (uint32_t)(arow * 128);
    const int brow = wn + ((lane >> 4) << 3) + (lane & 7);
    const uint32_t bcc = (uint32_t)((lane >> 3) & 1);
    const uint32_t bswz = (uint32_t)(brow & 7);
    const uint32_t boff = (uint32_t)(brow * 128) + 16384u;

    float acc[2][8][4];
    #pragma unroll
    for (int i = 0; i < 2; i++)
        #pragma unroll
        for (int j = 0; j < 8; j++)
            #pragma unroll
            for (int t = 0; t < 4; t++) acc[i][j][t] = 0.f;

    const int nk = K >> 5;
    #pragma unroll
    for (int s = 0; s < 2; s++) {
        const uint32_t sb = smbase + (uint32_t)s * GSTAGE;
        #pragma unroll
        for (int u = 0; u < 4; u++) {
            cp_async16(sb + a_soff[u], a_g[u] + s * 32);
            cp_async16(sb + b_soff[u], b_g[u] + s * 32);
        }
        cp_commit();
    }

    int sidx = 0;
    for (int kc = 0; kc < nk; kc++) {
        if (kc == nk - 1) cp_wait<0>(); else cp_wait<1>();
        __syncthreads();
        if (kc + 2 < nk) {
            const int s2 = (sidx + 2 >= 3) ? sidx - 1 : sidx + 2;
            const uint32_t sb = smbase + (uint32_t)s2 * GSTAGE;
            #pragma unroll
            for (int u = 0; u < 4; u++) {
                cp_async16(sb + a_soff[u], a_g[u] + (kc + 2) * 32);
                cp_async16(sb + b_soff[u], b_g[u] + (kc + 2) * 32);
            }
            cp_commit();
        }
        const uint32_t sb = smbase + (uint32_t)sidx * GSTAGE;
        #pragma unroll
        for (int ks = 0; ks < 4; ks++) {
            const uint32_t kc0 = (uint32_t)(2 * ks);
            uint32_t af[2][4];
            #pragma unroll
            for (int i = 0; i < 2; i++) {
                const uint32_t addr = sb + aoff + (uint32_t)(i * 2048) +
                                      (((kc0 + acadd) ^ aswz) << 4);
                ldsm4(af[i][0], af[i][1], af[i][2], af[i][3], addr);
            }
            #pragma unroll
            for (int jp = 0; jp < 4; jp++) {
                uint32_t b0, b1, b2, b3;
                const uint32_t addr = sb + boff + (uint32_t)(jp * 2048) +
                                      (((kc0 + bcc) ^ bswz) << 4);
                ldsm4(b0, b1, b2, b3, addr);
                #pragma unroll
                for (int i = 0; i < 2; i++) {
                    mma_tf32(acc[i][2 * jp + 0], af[i], b0, b1);
                    mma_tf32(acc[i][2 * jp + 1], af[i], b2, b3);
                }
            }
        }
        sidx = (sidx == 2) ? 0 : sidx + 1;
    }

    const int g = lane >> 2, tg = lane & 3;
    #pragma unroll
    for (int i = 0; i < 2; i++) {
        #pragma unroll
        for (int j = 0; j < 8; j++) {
            const int col = n0 + wn + j * 8 + tg * 2;
            const float2 b2 = *(const float2*)(bias + col);
            float sx = 1.f, sy = 1.f;
            if (EPI == 1) {
                if (col < 1024) {
                    const float c = 0.18033688f;  // log2(e)/sqrt(64)
                    sx = c * softplus_f(extra[col & 63]);
                    sy = c * softplus_f(extra[(col + 1) & 63]);
                }
            }
            #pragma unroll
            for (int h = 0; h < 2; h++) {
                const int row = m0 + wm + i * 16 + g + h * 8;
                float vx = acc[i][j][2 * h + 0] + b2.x;
                float vy = acc[i][j][2 * h + 1] + b2.y;
                if (EPI == 1) { vx *= sx; vy *= sy; }
                if (EPI == 2) {
                    const float2 r2 = *(const float2*)(extra + (size_t)row * N + col);
                    vx += r2.x; vy += r2.y;
                }
                if (EPI == 3) { vx = fmaxf(vx, 0.f); vy = fmaxf(vy, 0.f); }
                if (RND) { vx = rtf32(vx); vy = rtf32(vy); }
                float2 o2; o2.x = vx; o2.y = vy;
                *(float2*)(C + (size_t)row * N + col) = o2;
            }
        }
    }
}

// ---------------------------------------------------------------------------
// Flash attention with tf32 mma.sync. 64x64 tiles. 256 threads (8 warps).
// Warp tile: 16 rows x 32 cols. qkv buffer rows [t][3072].
// ---------------------------------------------------------------------------
// smem float offsets
#define FQO 0
#define FKO 4096
#define FVO 8192
#define FPO 12288
#define FMO 16384
#define FLO 16448
#define FRO 16512   // rpart[2][64]
#define FSO 16640   // spart[2][64]
#define FPQ 16768
#define FPS 16832
#define FLASH_FLOATS 16896
#define FLASH_SMEM_BYTES (FLASH_FLOATS * 4)

__device__ __forceinline__ uint32_t fswz(int row, int chunk) {
    return (uint32_t)(row * 256 + ((chunk ^ (row & 7)) << 4));
}

__global__ __launch_bounds__(256) void flash_kernel(
    const float* __restrict__ qkv, const float* __restrict__ pad,
    float* __restrict__ out)
{
    extern __shared__ float sf[];
    const uint32_t sbase = s2u(sf);
    const int tid = threadIdx.x;
    const int lane = tid & 31;
    const int wid = tid >> 5;
    const int wm = (wid & 3) << 4;        // 0,16,32,48
    const int wn = (wid >> 2) << 5;       // 0,32
    const int g = lane >> 2, tg = lane & 3;
    const int t0 = blockIdx.x << 6;
    const int bn = blockIdx.y;
    const int b = bn >> 4, n = bn & 15;

    // fragment address constants
    const int arow = wm + (lane & 15);
    const uint32_t acadd = (uint32_t)(lane >> 4);
    const uint32_t aswz = (uint32_t)(arow & 7);
    const uint32_t qbase = sbase + FQO * 4 + (uint32_t)(arow * 256);
    const uint32_t pbase = sbase + FPO * 4 + (uint32_t)(arow * 256);
    const int brw = ((lane >> 4) << 3) + (lane & 7);
    const uint32_t bcc = (uint32_t)((lane >> 3) & 1);

    // ---- load Q tile (rows t0..t0+63), rounded already (GEMM epilogue)
    {
        const int r = tid >> 2;
        const int c0 = (tid & 3) << 2;
        const float* qp = qkv + (size_t)(b * TT + t0 + r) * QKVN + n * 64;
        #pragma unroll
        for (int u = 0; u < 4; u++) {
            const int c = c0 + u;
            *(float4*)((char*)sf + FQO * 4 + fswz(r, c)) =
                *(const float4*)(qp + c * 4);
        }
    }
    if (tid < 64) {
        sf[FMO + tid] = -1e30f;
        sf[FLO + tid] = 0.f;
        sf[FPQ + tid] = pad[b * TT + t0 + tid];
    }

    float o[4][4];
    #pragma unroll
    for (int j = 0; j < 4; j++)
        #pragma unroll
        for (int c = 0; c < 4; c++) o[j][c] = 0.f;

    const int r0l = wm + g;          // local row (0..63)
    const int r1l = r0l + 8;

    for (int s0 = 0; s0 <= t0; s0 += 64) {
        // ---- load K tile + V^T tile + pads
        {
            const int r = tid >> 2;
            const int c0 = (tid & 3) << 2;
            const float* kp = qkv + (size_t)(b * TT + s0 + r) * QKVN + 1024 + n * 64;
            #pragma unroll
            for (int u = 0; u < 4; u++) {
                const int c = c0 + u;
                *(float4*)((char*)sf + FKO * 4 + fswz(r, c)) =
                    *(const float4*)(kp + c * 4);
            }
            // V^T: rows h, cols s
            const int s = tid >> 2;
            const int hc = (tid & 3) << 4;
            const float* vp = qkv + (size_t)(b * TT + s0 + s) * QKVN + 2048 + n * 64 + hc;
            const int cs = s >> 2, si = s & 3;
            #pragma unroll
            for (int j = 0; j < 4; j++) {
                const float4 vv = *(const float4*)(vp + j * 4);
                const int h = hc + j * 4;
                sf[FVO + (h + 0) * 64 + ((cs ^ ((h + 0) & 7)) << 2) + si] = vv.x;
                sf[FVO + (h + 1) * 64 + ((cs ^ ((h + 1) & 7)) << 2) + si] = vv.y;
                sf[FVO + (h + 2) * 64 + ((cs ^ ((h + 2) & 7)) << 2) + si] = vv.z;
                sf[FVO + (h + 3) * 64 + ((cs ^ ((h + 3) & 7)) << 2) + si] = vv.w;
            }
            if (tid < 64) sf[FPS + tid] = pad[b * TT + s0 + tid];
        }
        __syncthreads();

        // ---- S = Q K^T (warp tile 16x32)
        float sacc[4][4];
        #pragma unroll
        for (int j = 0; j < 4; j++)
            #pragma unroll
            for (int c = 0; c < 4; c++) sacc[j][c] = 0.f;
        #pragma unroll
        for (int ks = 0; ks < 8; ks++) {
            const uint32_t kc0 = (uint32_t)(2 * ks);
            uint32_t af[4];
            ldsm4(af[0], af[1], af[2], af[3],
                  qbase + (((kc0 + acadd) ^ aswz) << 4));
            #pragma unroll
            for (int jp = 0; jp < 2; jp++) {
                const int brow = wn + jp * 16 + brw;
                uint32_t b0, b1, b2, b3;
                ldsm4(b0, b1, b2, b3,
                      sbase + FKO * 4 + (uint32_t)(brow * 256) +
                      (((kc0 + bcc) ^ (uint32_t)(brow & 7)) << 4));
                mma_tf32(sacc[2 * jp + 0], af, b0, b1);
                mma_tf32(sacc[2 * jp + 1], af, b2, b3);
            }
        }

        // ---- mask
        const float pq0 = sf[FPQ + r0l], pq1 = sf[FPQ + r1l];
        const int rg0 = t0 + r0l, rg1 = t0 + r1l;
        #pragma unroll
        for (int j = 0; j < 4; j++) {
            const int cl = wn + j * 8 + 2 * tg;
            const int cg = s0 + cl;
            const float ps0 = sf[FPS + cl], ps1 = sf[FPS + cl + 1];
            if (!(pq0 != 0.f && ps0 != 0.f && cg     <= rg0)) sacc[j][0] = -1e9f;
            if (!(pq0 != 0.f && ps1 != 0.f && cg + 1 <= rg0)) sacc[j][1] = -1e9f;
            if (!(pq1 != 0.f && ps0 != 0.f && cg     <= rg1)) sacc[j][2] = -1e9f;
            if (!(pq1 != 0.f && ps1 != 0.f && cg + 1 <= rg1)) sacc[j][3] = -1e9f;
        }

        // ---- warp-level row max
        float m0 = -1e30f, m1 = -1e30f;
        #pragma unroll
        for (int j = 0; j < 4; j++) {
            m0 = fmaxf(m0, fmaxf(sacc[j][0], sacc[j][1]));
            m1 = fmaxf(m1, fmaxf(sacc[j][2], sacc[j][3]));
        }
        m0 = fmaxf(m0, __shfl_xor_sync(0xffffffffu, m0, 1));
        m0 = fmaxf(m0, __shfl_xor_sync(0xffffffffu, m0, 2));
        m1 = fmaxf(m1, __shfl_xor_sync(0xffffffffu, m1, 1));
        m1 = fmaxf(m1, __shfl_xor_sync(0xffffffffu, m1, 2));
        if (tg == 0) {
            sf[FRO + (wn >> 5) * 64 + r0l] = m0;
            sf[FRO + (wn >> 5) * 64 + r1l] = m1;
        }
        __syncthreads();

        // ---- combine, exp, P store
        const float mold0 = sf[FMO + r0l], mold1 = sf[FMO + r1l];
        const float mn0 = fmaxf(mold0, fmaxf(sf[FRO + r0l], sf[FRO + 64 + r0l]));
        const float mn1 = fmaxf(mold1, fmaxf(sf[FRO + r1l], sf[FRO + 64 + r1l]));
        const float alpha0 = __expf(mold0 - mn0);
        const float alpha1 = __expf(mold1 - mn1);
        float sum0 = 0.f, sum1 = 0.f;
        #pragma unroll
        for (int j = 0; j < 4; j++) {
            const int cl = wn + j * 8 + 2 * tg;
            const int cc = cl >> 2, ci = cl & 3;  // ci in {0,2}
            float p00 = __expf(sacc[j][0] - mn0);
            float p01 = __expf(sacc[j][1] - mn0);
            float p10 = __expf(sacc[j][2] - mn1);
            float p11 = __expf(sacc[j][3] - mn1);
            sum0 += p00 + p01;
            sum1 += p10 + p11;
            sf[FPO + r0l * 64 + ((cc ^ (r0l & 7)) << 2) + ci + 0] = rtf32(p00);
            sf[FPO + r0l * 64 + ((cc ^ (r0l & 7)) << 2) + ci + 1] = rtf32(p01);
            sf[FPO + r1l * 64 + ((cc ^ (r1l & 7)) << 2) + ci + 0] = rtf32(p10);
            sf[FPO + r1l * 64 + ((cc ^ (r1l & 7)) << 2) + ci + 1] = rtf32(p11);
        }
        sum0 += __shfl_xor_sync(0xffffffffu, sum0, 1);
        sum0 += __shfl_xor_sync(0xffffffffu, sum0, 2);
        sum1 += __shfl_xor_sync(0xffffffffu, sum1, 1);
        sum1 += __shfl_xor_sync(0xffffffffu, sum1, 2);
        if (tg == 0) {
            sf[FSO + (wn >> 5) * 64 + r0l] = sum0;
            sf[FSO + (wn >> 5) * 64 + r1l] = sum1;
        }
        __syncthreads();

        // ---- update m/l (one writer set: warps with wn==0, lane tg==0)
        if (wn == 0 && tg == 0) {
            sf[FLO + r0l] = sf[FLO + r0l] * alpha0 + sf[FSO + r0l] + sf[FSO + 64 + r0l];
            sf[FLO + r1l] = sf[FLO + r1l] * alpha1 + sf[FSO + r1l] + sf[FSO + 64 + r1l];
            sf[FMO + r0l] = mn0;
            sf[FMO + r1l] = mn1;
        }

        // ---- rescale O
        #pragma unroll
        for (int j = 0; j < 4; j++) {
            o[j][0] *= alpha0; o[j][1] *= alpha0;
            o[j][2] *= alpha1; o[j][3] *= alpha1;
        }

        // ---- O += P V   (A = P rows t, B = V^T rows h)
        #pragma unroll
        for (int ks = 0; ks < 8; ks++) {
            const uint32_t kc0 = (uint32_t)(2 * ks);
            uint32_t af[4];
            ldsm4(af[0], af[1], af[2], af[3],
                  pbase + (((kc0 + acadd) ^ aswz) << 4));
            #pragma unroll
            for (int jp = 0; jp < 2; jp++) {
                const int brow = wn + jp * 16 + brw;
                uint32_t b0, b1, b2, b3;
                ldsm4(b0, b1, b2, b3,
                      sbase + FVO * 4 + (uint32_t)(brow * 256) +
                      (((kc0 + bcc) ^ (uint32_t)(brow & 7)) << 4));
                mma_tf32(o[2 * jp + 0], af, b0, b1);
                mma_tf32(o[2 * jp + 1], af, b2, b3);
            }
        }
        __syncthreads();
    }

    // ---- finalize
    const float inv0 = 1.f / sf[FLO + r0l];
    const float inv1 = 1.f / sf[FLO + r1l];
    const size_t row0 = (size_t)(b * TT + t0 + r0l);
    const size_t row1 = (size_t)(b * TT + t0 + r1l);
    #pragma unroll
    for (int j = 0; j < 4; j++) {
        const int d = n * 64 + wn + j * 8 + 2 * tg;
        float2 o0, o1;
        o0.x = rtf32(o[j][0] * inv0); o0.y = rtf32(o[j][1] * inv0);
        o1.x = rtf32(o[j][2] * inv1); o1.y = rtf32(o[j][3] * inv1);
        *(float2*)(out + row0 * DD + d) = o0;
        *(float2*)(out + row1 * DD + d) = o1;
    }
}

// ---------------------------------------------------------------------------
// Host launch
// ---------------------------------------------------------------------------
extern "C" void kernel_launch(void* const* d_in, const int* in_sizes, int n_in,
                              void* d_out, int out_size)
{
    (void)in_sizes; (void)n_in; (void)out_size;
    const float* x         = (const float*)d_in[0];
    const float* padding   = (const float*)d_in[1];
    const float* rms_scale = (const float*)d_in[2];
    const float* pds       = (const float*)d_in[3];
    const float* wq        = (const float*)d_in[4];
    const float* bq        = (const float*)d_in[5];
    const float* wk        = (const float*)d_in[6];
    const float* bk        = (const float*)d_in[7];
    const float* wv        = (const float*)d_in[8];
    const float* bv        = (const float*)d_in[9];
    const float* wo        = (const float*)d_in[10];
    const float* bo        = (const float*)d_in[11];
    const float* ln_gamma  = (const float*)d_in[12];
    const float* ln_beta   = (const float*)d_in[13];
    const float* w1        = (const float*)d_in[14];
    const float* b1        = (const float*)d_in[15];
    const float* w2        = (const float*)d_in[16];
    const float* b2        = (const float*)d_in[17];
    float* out = (float*)d_out;

    float *xn, *qkv, *ao, *ar, *hn, *h1;
    float *wqkvt, *bqkv, *wot, *w1t, *w2t;
    cudaGetSymbolAddress((void**)&xn,  g_xn);
    cudaGetSymbolAddress((void**)&qkv, g_qkv);
    cudaGetSymbolAddress((void**)&ao,  g_ao);
    cudaGetSymbolAddress((void**)&ar,  g_ar);
    cudaGetSymbolAddress((void**)&hn,  g_hn);
    cudaGetSymbolAddress((void**)&h1,  g_h1);
    cudaGetSymbolAddress((void**)&wqkvt, g_wqkvt);
    cudaGetSymbolAddress((void**)&bqkv,  g_bqkv);
    cudaGetSymbolAddress((void**)&wot, g_wot);
    cudaGetSymbolAddress((void**)&w1t, g_w1t);
    cudaGetSymbolAddress((void**)&w2t, g_w2t);

    static int attr_done = 0;
    if (!attr_done) {
        cudaFuncSetAttribute(flash_kernel,
            cudaFuncAttributeMaxDynamicSharedMemorySize, FLASH_SMEM_BYTES);
        cudaFuncSetAttribute(mma_gemm_kernel<0, true>,
            cudaFuncAttributeMaxDynamicSharedMemorySize, GEMM_SMEM_BYTES);
        cudaFuncSetAttribute(mma_gemm_kernel<1, true>,
            cudaFuncAttributeMaxDynamicSharedMemorySize, GEMM_SMEM_BYTES);
        cudaFuncSetAttribute(mma_gemm_kernel<2, false>,
            cudaFuncAttributeMaxDynamicSharedMemorySize, GEMM_SMEM_BYTES);
        cudaFuncSetAttribute(mma_gemm_kernel<3, true>,
            cudaFuncAttributeMaxDynamicSharedMemorySize, GEMM_SMEM_BYTES);
        attr_done = 1;
    }

    // 0. Weight prep
    dim3 tb(32, 8);
    transpose_round_kernel<<<dim3(DD / 32, DD / 32), tb>>>(wq, wqkvt, DD, DD);
    transpose_round_kernel<<<dim3(DD / 32, DD / 32), tb>>>(wk, wqkvt + 1024 * DD, DD, DD);
    transpose_round_kernel<<<dim3(DD / 32, DD / 32), tb>>>(wv, wqkvt + 2048 * DD, DD, DD);
    transpose_round_kernel<<<dim3(FF / 32, DD / 32), tb>>>(w1, w1t, DD, FF);
    transpose_round_kernel<<<dim3(DD / 32, FF / 32), tb>>>(w2, w2t, FF, DD);
    round_copy_kernel<<<(DD * DD / 4 + 255) / 256, 256>>>(wo, wot, DD * DD / 4);
    concat_bias_kernel<<<(QKVN + 255) / 256, 256>>>(bq, bk, bv, bqkv);

    // 1. RMSNorm
    rmsnorm_kernel<<<MM, 256>>>(x, rms_scale, xn);

    // 2. Fused QKV projection (rounded outputs; qscale on q cols)
    dim3 gQKV(QKVN / 128, MM / 128);
    mma_gemm_kernel<1, true><<<gQKV, 256, GEMM_SMEM_BYTES>>>(
        xn, wqkvt, bqkv, pds, qkv, MM, QKVN, DD);

    // 3. Flash attention (tensor cores)
    flash_kernel<<<dim3(TT / 64, BB * NHEAD), 256, FLASH_SMEM_BYTES>>>(
        qkv, padding, ao);

    // 4. Output projection + bias + residual(x)
    dim3 gD(DD / 128, MM / 128);
    mma_gemm_kernel<2, false><<<gD, 256, GEMM_SMEM_BYTES>>>(
        ao, wot, bo, x, ar, MM, DD, DD);

    // 5. LayerNorm
    layernorm_kernel<<<MM, 256>>>(ar, ln_gamma, ln_beta, hn);

    // 6. FFN up + ReLU (rounded)
    dim3 gF(FF / 128, MM / 128);
    mma_gemm_kernel<3, true><<<gF, 256, GEMM_SMEM_BYTES>>>(
        hn, w1t, b1, nullptr, h1, MM, FF, DD);

    // 7. FFN down + bias + residual(ar) -> output
    mma_gemm_kernel<2, false><<<gD, 256, GEMM_SMEM_BYTES>>>(
        h1, w2t, b2, ar, out, MM, DD, FF);
}

// round 6
// speedup vs baseline: 7.1566x; 1.8194x over previous
#include <cuda_runtime.h>
#include <cuda_fp16.h>
#include <cstdint>
#include <math.h>

// Problem constants
#define BB 8
#define TT 1024
#define DD 1024
#define NHEAD 16
#define HDIM 64
#define FF 4096
#define MM (BB * TT)   // 8192
#define QKVN 3072

// ---------------------------------------------------------------------------
// Scratch (device globals)
// ---------------------------------------------------------------------------
__device__ __half g_xn [MM * DD];
__device__ __half g_qkv[MM * QKVN];
__device__ __half g_ao [MM * DD];
__device__ float  g_ar [MM * DD];
__device__ __half g_hn [MM * DD];
__device__ __half g_h1 [MM * FF];
__device__ __half g_wqkvt[QKVN * DD];   // [3072][1024] K-major (q|k|v)
__device__ float  g_bqkv [QKVN];
__device__ __half g_wot[DD * DD];
__device__ __half g_w1t[FF * DD];
__device__ __half g_w2t[DD * FF];

// ---------------------------------------------------------------------------
// Helpers
// ---------------------------------------------------------------------------
__device__ __forceinline__ uint32_t s2u(const void* p) {
    uint32_t a;
    asm("{ .reg .u64 t; cvta.to.shared.u64 t, %1; cvt.u32.u64 %0, t; }"
        : "=r"(a) : "l"(p));
    return a;
}

__device__ __forceinline__ void cp_async16(uint32_t saddr, const void* gaddr) {
    asm volatile("cp.async.cg.shared.global [%0], [%1], 16;"
                 :: "r"(saddr), "l"(gaddr));
}
__device__ __forceinline__ void cp_commit() {
    asm volatile("cp.async.commit_group;");
}
template <int N>
__device__ __forceinline__ void cp_wait() {
    asm volatile("cp.async.wait_group %0;" :: "n"(N));
}

__device__ __forceinline__ void ldsm4(uint32_t& r0, uint32_t& r1,
                                      uint32_t& r2, uint32_t& r3, uint32_t addr) {
    asm volatile("ldmatrix.sync.aligned.m8n8.x4.shared.b16 {%0,%1,%2,%3}, [%4];"
                 : "=r"(r0), "=r"(r1), "=r"(r2), "=r"(r3) : "r"(addr));
}

// fp16 MMA m16n8k16, fp32 accumulate
__device__ __forceinline__ void mma_f16(float* c, const uint32_t* a,
                                        uint32_t b0, uint32_t b1) {
    asm volatile(
        "mma.sync.aligned.m16n8k16.row.col.f32.f16.f16.f32 "
        "{%0,%1,%2,%3}, {%4,%5,%6,%7}, {%8,%9}, {%0,%1,%2,%3};"
        : "+f"(c[0]), "+f"(c[1]), "+f"(c[2]), "+f"(c[3])
        : "r"(a[0]), "r"(a[1]), "r"(a[2]), "r"(a[3]), "r"(b0), "r"(b1));
}

// ---------------------------------------------------------------------------
// Prep kernels
// ---------------------------------------------------------------------------
__global__ __launch_bounds__(256) void transpose_half_kernel(
    const float* __restrict__ in, __half* __restrict__ out, int R, int C)
{
    __shared__ float t[32][33];
    const int bx = blockIdx.x << 5, by = blockIdx.y << 5;
    const int txx = threadIdx.x, tyy = threadIdx.y;
    #pragma unroll
    for (int j = 0; j < 32; j += 8)
        t[tyy + j][txx] = in[(size_t)(by + tyy + j) * C + bx + txx];
    __syncthreads();
    #pragma unroll
    for (int j = 0; j < 32; j += 8)
        out[(size_t)(bx + tyy + j) * R + by + txx] = __float2half_rn(t[txx][tyy + j]);
}

__global__ __launch_bounds__(256) void copy_half_kernel(
    const float* __restrict__ in, __half* __restrict__ out, int n4)
{
    const int i = blockIdx.x * 256 + threadIdx.x;
    if (i < n4) {
        const float4 v = ((const float4*)in)[i];
        __half2* o2 = (__half2*)(out + (size_t)i * 4);
        o2[0] = __floats2half2_rn(v.x, v.y);
        o2[1] = __floats2half2_rn(v.z, v.w);
    }
}

__global__ __launch_bounds__(256) void concat_bias_kernel(
    const float* __restrict__ bq, const float* __restrict__ bk,
    const float* __restrict__ bv, float* __restrict__ out)
{
    const int i = blockIdx.x * 256 + threadIdx.x;
    if (i < QKVN)
        out[i] = (i < 1024) ? bq[i] : (i < 2048) ? bk[i - 1024] : bv[i - 2048];
}

// ---------------------------------------------------------------------------
// RMSNorm / LayerNorm (half outputs)
// ---------------------------------------------------------------------------
__global__ __launch_bounds__(256) void rmsnorm_kernel(
    const float* __restrict__ x, const float* __restrict__ scale,
    __half* __restrict__ out)
{
    const int row = blockIdx.x;
    const int tid = threadIdx.x;
    const float4 v = ((const float4*)(x + (size_t)row * DD))[tid];
    float ss = v.x * v.x + v.y * v.y + v.z * v.z + v.w * v.w;
    #pragma unroll
    for (int m = 16; m; m >>= 1) ss += __shfl_xor_sync(0xffffffffu, ss, m);
    __shared__ float sred[8];
    if ((tid & 31) == 0) sred[tid >> 5] = ss;
    __syncthreads();
    float tot = 0.f;
    #pragma unroll
    for (int i = 0; i < 8; i++) tot += sred[i];
    const float r = rsqrtf(tot * (1.0f / DD) + 1e-6f);
    const float4 s4 = ((const float4*)scale)[tid];
    __half2* o2 = (__half2*)(out + (size_t)row * DD) + tid * 2;
    o2[0] = __floats2half2_rn(v.x * r * s4.x, v.y * r * s4.y);
    o2[1] = __floats2half2_rn(v.z * r * s4.z, v.w * r * s4.w);
}

__global__ __launch_bounds__(256) void layernorm_kernel(
    const float* __restrict__ x, const float* __restrict__ gamma,
    const float* __restrict__ beta, __half* __restrict__ out)
{
    const int row = blockIdx.x;
    const int tid = threadIdx.x;
    const float4 v = ((const float4*)(x + (size_t)row * DD))[tid];
    float s  = v.x + v.y + v.z + v.w;
    float ss = v.x * v.x + v.y * v.y + v.z * v.z + v.w * v.w;
    #pragma unroll
    for (int m = 16; m; m >>= 1) {
        s  += __shfl_xor_sync(0xffffffffu, s,  m);
        ss += __shfl_xor_sync(0xffffffffu, ss, m);
    }
    __shared__ float sr1[8], sr2[8];
    if ((tid & 31) == 0) { sr1[tid >> 5] = s; sr2[tid >> 5] = ss; }
    __syncthreads();
    float S = 0.f, SS = 0.f;
    #pragma unroll
    for (int i = 0; i < 8; i++) { S += sr1[i]; SS += sr2[i]; }
    const float mean = S * (1.0f / DD);
    const float var  = SS * (1.0f / DD) - mean * mean;
    const float r = rsqrtf(var + 1e-5f);
    const float4 g4 = ((const float4*)gamma)[tid];
    const float4 b4 = ((const float4*)beta)[tid];
    __half2* o2 = (__half2*)(out + (size_t)row * DD) + tid * 2;
    o2[0] = __floats2half2_rn((v.x - mean) * r * g4.x + b4.x,
                              (v.y - mean) * r * g4.y + b4.y);
    o2[1] = __floats2half2_rn((v.z - mean) * r * g4.z + b4.z,
                              (v.w - mean) * r * g4.w + b4.w);
}

// ---------------------------------------------------------------------------
// fp16 mma.sync GEMM: C[M,N] = A[M,K] @ Bw^T (Bw [N][K] K-major, half)
// CTA tile 128x128, BK=64 halfs (128B rows), 3-stage cp.async, 8 warps.
// EPI: 0=+bias 1=(+bias)*qscale(col<1024) 2=+bias+residual(float) 3=relu(+bias)
// OUTH: write half (else float)
// ---------------------------------------------------------------------------
__device__ __forceinline__ float softplus_f(float x) {
    return (x > 15.f) ? x : log1pf(__expf(x));
}

#define GSTAGE 32768
#define GEMM_SMEM_BYTES (3 * GSTAGE)

template <int EPI, bool OUTH>
__global__ __launch_bounds__(256, 2) void mma_gemm_kernel(
    const __half* __restrict__ A, const __half* __restrict__ Bw,
    const float* __restrict__ bias, const float* __restrict__ extra,
    void* __restrict__ Cv, int M, int N, int K)
{
    extern __shared__ char gsm[];
    const uint32_t smbase = s2u(gsm);
    const int tid = threadIdx.x;
    const int lane = tid & 31;
    const int wid = tid >> 5;
    const int m0 = blockIdx.y << 7;
    const int n0 = blockIdx.x << 7;
    const int wm = (wid & 3) << 5;
    const int wn = (wid >> 2) << 6;

    // loaders: A tile 128 rows x 128B (16KB) at 0, B at 16KB. 8 chunks/row.
    uint32_t a_soff[4], b_soff[4];
    const __half* a_g[4]; const __half* b_g[4];
    #pragma unroll
    for (int u = 0; u < 4; u++) {
        const int qch = tid + u * 256;          // 0..1023
        const int m = qch >> 3, kc = qch & 7;
        const uint32_t sw = (uint32_t)(kc ^ (m & 7));
        a_soff[u] = (uint32_t)(m * 128) + (sw << 4);
        b_soff[u] = a_soff[u] + 16384u;
        a_g[u] = A  + (size_t)(m0 + m) * K + kc * 8;
        b_g[u] = Bw + (size_t)(n0 + m) * K + kc * 8;
    }

    const int arow = wm + (lane & 15);
    const uint32_t acadd = (uint32_t)(lane >> 4);
    const uint32_t aswz = (uint32_t)(arow & 7);
    const uint32_t aoff = (uint32_t)(arow * 128);
    const int brow = wn + ((lane >> 4) << 3) + (lane & 7);
    const uint32_t bcc = (uint32_t)((lane >> 3) & 1);
    const uint32_t bswz = (uint32_t)(brow & 7);
    const uint32_t boff = (uint32_t)(brow * 128) + 16384u;

    float acc[2][8][4];
    #pragma unroll
    for (int i = 0; i < 2; i++)
        #pragma unroll
        for (int j = 0; j < 8; j++)
            #pragma unroll
            for (int t = 0; t < 4; t++) acc[i][j][t] = 0.f;

    const int nk = K >> 6;   // BK = 64 halfs
    #pragma unroll
    for (int s = 0; s < 2; s++) {
        const uint32_t sb = smbase + (uint32_t)s * GSTAGE;
        #pragma unroll
        for (int u = 0; u < 4; u++) {
            cp_async16(sb + a_soff[u], a_g[u] + s * 64);
            cp_async16(sb + b_soff[u], b_g[u] + s * 64);
        }
        cp_commit();
    }

    int sidx = 0;
    for (int kc = 0; kc < nk; kc++) {
        if (kc == nk - 1) cp_wait<0>(); else cp_wait<1>();
        __syncthreads();
        if (kc + 2 < nk) {
            const int s2 = (sidx + 2 >= 3) ? sidx - 1 : sidx + 2;
            const uint32_t sb = smbase + (uint32_t)s2 * GSTAGE;
            #pragma unroll
            for (int u = 0; u < 4; u++) {
                cp_async16(sb + a_soff[u], a_g[u] + (kc + 2) * 64);
                cp_async16(sb + b_soff[u], b_g[u] + (kc + 2) * 64);
            }
            cp_commit();
        }
        const uint32_t sb = smbase + (uint32_t)sidx * GSTAGE;
        #pragma unroll
        for (int ks = 0; ks < 4; ks++) {           // k16 steps
            const uint32_t kc0 = (uint32_t)(2 * ks);
            uint32_t af[2][4];
            #pragma unroll
            for (int i = 0; i < 2; i++) {
                const uint32_t addr = sb + aoff + (uint32_t)(i * 2048) +
                                      (((kc0 + acadd) ^ aswz) << 4);
                ldsm4(af[i][0], af[i][1], af[i][2], af[i][3], addr);
            }
            #pragma unroll
            for (int jp = 0; jp < 4; jp++) {       // n16 groups
                uint32_t b0, b1, b2, b3;
                const uint32_t addr = sb + boff + (uint32_t)(jp * 2048) +
                                      (((kc0 + bcc) ^ bswz) << 4);
                ldsm4(b0, b1, b2, b3, addr);
                #pragma unroll
                for (int i = 0; i < 2; i++) {
                    mma_f16(acc[i][2 * jp + 0], af[i], b0, b1);
                    mma_f16(acc[i][2 * jp + 1], af[i], b2, b3);
                }
            }
        }
        sidx = (sidx == 2) ? 0 : sidx + 1;
    }

    // epilogue
    const int g = lane >> 2, tg = lane & 3;
    #pragma unroll
    for (int i = 0; i < 2; i++) {
        #pragma unroll
        for (int j = 0; j < 8; j++) {
            const int col = n0 + wn + j * 8 + tg * 2;
            const float2 b2 = *(const float2*)(bias + col);
            float sx = 1.f, sy = 1.f;
            if (EPI == 1) {
                if (col < 1024) {
                    const float c = 0.18033688f;  // log2(e)/sqrt(64)
                    sx = c * softplus_f(extra[col & 63]);
                    sy = c * softplus_f(extra[(col + 1) & 63]);
                }
            }
            #pragma unroll
            for (int h = 0; h < 2; h++) {
                const int row = m0 + wm + i * 16 + g + h * 8;
                float vx = acc[i][j][2 * h + 0] + b2.x;
                float vy = acc[i][j][2 * h + 1] + b2.y;
                if (EPI == 1) { vx *= sx; vy *= sy; }
                if (EPI == 2) {
                    const float2 r2 = *(const float2*)(extra + (size_t)row * N + col);
                    vx += r2.x; vy += r2.y;
                }
                if (EPI == 3) { vx = fmaxf(vx, 0.f); vy = fmaxf(vy, 0.f); }
                if (OUTH) {
                    *(__half2*)((__half*)Cv + (size_t)row * N + col) =
                        __floats2half2_rn(vx, vy);
                } else {
                    float2 o2; o2.x = vx; o2.y = vy;
                    *(float2*)((float*)Cv + (size_t)row * N + col) = o2;
                }
            }
        }
    }
}

// ---------------------------------------------------------------------------
// Flash attention, fp16 mma. 64x64 tiles, 256 threads (8 warps, 16x32 each).
// ---------------------------------------------------------------------------
// byte offsets in dynamic smem
#define FQO 0
#define FKO 8192
#define FVO 16384
#define FPO 24576
#define FM_I 8192    // float index (byte 32768)
#define FL_I 8256
#define FR_I 8320    // [2][64]
#define FS_I 8448    // [2][64]
#define FPQ_I 8576
#define FPS_I 8640
#define FLASH_SMEM_BYTES 34816

__global__ __launch_bounds__(256) void flash_kernel(
    const __half* __restrict__ qkv, const float* __restrict__ pad,
    __half* __restrict__ out)
{
    extern __shared__ float sf[];
    const uint32_t sbase = s2u(sf);
    const int tid = threadIdx.x;
    const int lane = tid & 31;
    const int wid = tid >> 5;
    const int wm = (wid & 3) << 4;        // 0..48
    const int wn = (wid >> 2) << 5;       // 0/32
    const int g = lane >> 2, tg = lane & 3;
    const int t0 = blockIdx.x << 6;
    const int bn = blockIdx.y;
    const int b = bn >> 4, n = bn & 15;

    const int arow = wm + (lane & 15);
    const uint32_t acadd = (uint32_t)(lane >> 4);
    const uint32_t aswz = (uint32_t)(arow & 7);
    const uint32_t qbase = sbase + FQO + (uint32_t)(arow * 128);
    const uint32_t pbase = sbase + FPO + (uint32_t)(arow * 128);
    const int brw = ((lane >> 4) << 3) + (lane & 7);
    const uint32_t bcc = (uint32_t)((lane >> 3) & 1);

    // ---- load Q (64 rows x 64 halfs = 128B rows, swizzled)
    {
        const int r = tid >> 2;
        const int c0 = (tid & 3) << 1;
        const __half* qp = qkv + (size_t)(b * TT + t0 + r) * QKVN + n * 64;
        #pragma unroll
        for (int u = 0; u < 2; u++) {
            const int c = c0 + u;
            *(uint4*)((char*)sf + FQO + r * 128 + ((c ^ (r & 7)) << 4)) =
                *(const uint4*)(qp + c * 8);
        }
    }
    if (tid < 64) {
        sf[FM_I + tid] = -1e30f;
        sf[FL_I + tid] = 0.f;
        sf[FPQ_I + tid] = pad[b * TT + t0 + tid];
    }

    float o[4][4];
    #pragma unroll
    for (int j = 0; j < 4; j++)
        #pragma unroll
        for (int c = 0; c < 4; c++) o[j][c] = 0.f;

    const int r0l = wm + g;
    const int r1l = r0l + 8;

    for (int s0 = 0; s0 <= t0; s0 += 64) {
        // ---- load K + V^T + pads
        {
            const int r = tid >> 2;
            const int c0 = (tid & 3) << 1;
            const __half* kp = qkv + (size_t)(b * TT + s0 + r) * QKVN + 1024 + n * 64;
            #pragma unroll
            for (int u = 0; u < 2; u++) {
                const int c = c0 + u;
                *(uint4*)((char*)sf + FKO + r * 128 + ((c ^ (r & 7)) << 4)) =
                    *(const uint4*)(kp + c * 8);
            }
            // V^T[h][s]
            const int s = tid >> 2;
            const int hc = (tid & 3) << 4;
            const __half* vp = qkv + (size_t)(b * TT + s0 + s) * QKVN + 2048 + n * 64 + hc;
            __half vr[16];
            *(uint4*)&vr[0] = *(const uint4*)(vp);
            *(uint4*)&vr[8] = *(const uint4*)(vp + 8);
            __half* vt = (__half*)((char*)sf + FVO);
            const int cs = s >> 3, si = s & 7;
            #pragma unroll
            for (int j = 0; j < 16; j++) {
                const int h = hc + j;
                vt[h * 64 + ((cs ^ (h & 7)) << 3) + si] = vr[j];
            }
            if (tid < 64) sf[FPS_I + tid] = pad[b * TT + s0 + tid];
        }
        __syncthreads();

        // ---- S = Q K^T (warp tile 16x32), k = h = 64 -> 4 k16 steps
        float sacc[4][4];
        #pragma unroll
        for (int j = 0; j < 4; j++)
            #pragma unroll
            for (int c = 0; c < 4; c++) sacc[j][c] = 0.f;
        #pragma unroll
        for (int ks = 0; ks < 4; ks++) {
            const uint32_t kc0 = (uint32_t)(2 * ks);
            uint32_t af[4];
            ldsm4(af[0], af[1], af[2], af[3],
                  qbase + (((kc0 + acadd) ^ aswz) << 4));
            #pragma unroll
            for (int jp = 0; jp < 2; jp++) {
                const int brow = wn + jp * 16 + brw;
                uint32_t b0, b1, b2, b3;
                ldsm4(b0, b1, b2, b3,
                      sbase + FKO + (uint32_t)(brow * 128) +
                      (((kc0 + bcc) ^ (uint32_t)(brow & 7)) << 4));
                mma_f16(sacc[2 * jp + 0], af, b0, b1);
                mma_f16(sacc[2 * jp + 1], af, b2, b3);
            }
        }

        // ---- mask
        const float pq0 = sf[FPQ_I + r0l], pq1 = sf[FPQ_I + r1l];
        const int rg0 = t0 + r0l, rg1 = t0 + r1l;
        #pragma unroll
        for (int j = 0; j < 4; j++) {
            const int cl = wn + j * 8 + 2 * tg;
            const int cg = s0 + cl;
            const float ps0 = sf[FPS_I + cl], ps1 = sf[FPS_I + cl + 1];
            if (!(pq0 != 0.f && ps0 != 0.f && cg     <= rg0)) sacc[j][0] = -1e9f;
            if (!(pq0 != 0.f && ps1 != 0.f && cg + 1 <= rg0)) sacc[j][1] = -1e9f;
            if (!(pq1 != 0.f && ps0 != 0.f && cg     <= rg1)) sacc[j][2] = -1e9f;
            if (!(pq1 != 0.f && ps1 != 0.f && cg + 1 <= rg1)) sacc[j][3] = -1e9f;
        }

        // ---- warp row max
        float m0 = -1e30f, m1 = -1e30f;
        #pragma unroll
        for (int j = 0; j < 4; j++) {
            m0 = fmaxf(m0, fmaxf(sacc[j][0], sacc[j][1]));
            m1 = fmaxf(m1, fmaxf(sacc[j][2], sacc[j][3]));
        }
        m0 = fmaxf(m0, __shfl_xor_sync(0xffffffffu, m0, 1));
        m0 = fmaxf(m0, __shfl_xor_sync(0xffffffffu, m0, 2));
        m1 = fmaxf(m1, __shfl_xor_sync(0xffffffffu, m1, 1));
        m1 = fmaxf(m1, __shfl_xor_sync(0xffffffffu, m1, 2));
        if (tg == 0) {
            sf[FR_I + (wn >> 5) * 64 + r0l] = m0;
            sf[FR_I + (wn >> 5) * 64 + r1l] = m1;
        }
        __syncthreads();

        // ---- combine, exp, store P (half)
        const float mold0 = sf[FM_I + r0l], mold1 = sf[FM_I + r1l];
        const float mn0 = fmaxf(mold0, fmaxf(sf[FR_I + r0l], sf[FR_I + 64 + r0l]));
        const float mn1 = fmaxf(mold1, fmaxf(sf[FR_I + r1l], sf[FR_I + 64 + r1l]));
        const float alpha0 = __expf(mold0 - mn0);
        const float alpha1 = __expf(mold1 - mn1);
        float sum0 = 0.f, sum1 = 0.f;
        __half* pp = (__half*)((char*)sf + FPO);
        #pragma unroll
        for (int j = 0; j < 4; j++) {
            const int cl = wn + j * 8 + 2 * tg;
            const int cc = cl >> 3, ci = cl & 7;
            float p00 = __expf(sacc[j][0] - mn0);
            float p01 = __expf(sacc[j][1] - mn0);
            float p10 = __expf(sacc[j][2] - mn1);
            float p11 = __expf(sacc[j][3] - mn1);
            sum0 += p00 + p01;
            sum1 += p10 + p11;
            *(__half2*)&pp[r0l * 64 + ((cc ^ (r0l & 7)) << 3) + ci] =
                __floats2half2_rn(p00, p01);
            *(__half2*)&pp[r1l * 64 + ((cc ^ (r1l & 7)) << 3) + ci] =
                __floats2half2_rn(p10, p11);
        }
        sum0 += __shfl_xor_sync(0xffffffffu, sum0, 1);
        sum0 += __shfl_xor_sync(0xffffffffu, sum0, 2);
        sum1 += __shfl_xor_sync(0xffffffffu, sum1, 1);
        sum1 += __shfl_xor_sync(0xffffffffu, sum1, 2);
        if (tg == 0) {
            sf[FS_I + (wn >> 5) * 64 + r0l] = sum0;
            sf[FS_I + (wn >> 5) * 64 + r1l] = sum1;
        }
        __syncthreads();

        if (wn == 0 && tg == 0) {
            sf[FL_I + r0l] = sf[FL_I + r0l] * alpha0 + sf[FS_I + r0l] + sf[FS_I + 64 + r0l];
            sf[FL_I + r1l] = sf[FL_I + r1l] * alpha1 + sf[FS_I + r1l] + sf[FS_I + 64 + r1l];
            sf[FM_I + r0l] = mn0;
            sf[FM_I + r1l] = mn1;
        }

        #pragma unroll
        for (int j = 0; j < 4; j++) {
            o[j][0] *= alpha0; o[j][1] *= alpha0;
            o[j][2] *= alpha1; o[j][3] *= alpha1;
        }

        // ---- O += P V  (k = s = 64 -> 4 k16 steps, B = V^T rows h)
        #pragma unroll
        for (int ks = 0; ks < 4; ks++) {
            const uint32_t kc0 = (uint32_t)(2 * ks);
            uint32_t af[4];
            ldsm4(af[0], af[1], af[2], af[3],
                  pbase + (((kc0 + acadd) ^ aswz) << 4));
            #pragma unroll
            for (int jp = 0; jp < 2; jp++) {
                const int brow = wn + jp * 16 + brw;
                uint32_t b0, b1, b2, b3;
                ldsm4(b0, b1, b2, b3,
                      sbase + FVO + (uint32_t)(brow * 128) +
                      (((kc0 + bcc) ^ (uint32_t)(brow & 7)) << 4));
                mma_f16(o[2 * jp + 0], af, b0, b1);
                mma_f16(o[2 * jp + 1], af, b2, b3);
            }
        }
        __syncthreads();
    }

    // ---- finalize (half out)
    const float inv0 = 1.f / sf[FL_I + r0l];
    const float inv1 = 1.f / sf[FL_I + r1l];
    const size_t row0 = (size_t)(b * TT + t0 + r0l);
    const size_t row1 = (size_t)(b * TT + t0 + r1l);
    #pragma unroll
    for (int j = 0; j < 4; j++) {
        const int d = n * 64 + wn + j * 8 + 2 * tg;
        *(__half2*)(out + row0 * DD + d) =
            __floats2half2_rn(o[j][0] * inv0, o[j][1] * inv0);
        *(__half2*)(out + row1 * DD + d) =
            __floats2half2_rn(o[j][2] * inv1, o[j][3] * inv1);
    }
}

// ---------------------------------------------------------------------------
// Host launch
// ---------------------------------------------------------------------------
extern "C" void kernel_launch(void* const* d_in, const int* in_sizes, int n_in,
                              void* d_out, int out_size)
{
    (void)in_sizes; (void)n_in; (void)out_size;
    const float* x         = (const float*)d_in[0];
    const float* padding   = (const float*)d_in[1];
    const float* rms_scale = (const float*)d_in[2];
    const float* pds       = (const float*)d_in[3];
    const float* wq        = (const float*)d_in[4];
    const float* bq        = (const float*)d_in[5];
    const float* wk        = (const float*)d_in[6];
    const float* bk        = (const float*)d_in[7];
    const float* wv        = (const float*)d_in[8];
    const float* bv        = (const float*)d_in[9];
    const float* wo        = (const float*)d_in[10];
    const float* bo        = (const float*)d_in[11];
    const float* ln_gamma  = (const float*)d_in[12];
    const float* ln_beta   = (const float*)d_in[13];
    const float* w1        = (const float*)d_in[14];
    const float* b1        = (const float*)d_in[15];
    const float* w2        = (const float*)d_in[16];
    const float* b2        = (const float*)d_in[17];
    float* out = (float*)d_out;

    __half *xn, *qkv, *ao, *hn, *h1, *wqkvt, *wot, *w1t, *w2t;
    float *ar, *bqkv;
    cudaGetSymbolAddress((void**)&xn,  g_xn);
    cudaGetSymbolAddress((void**)&qkv, g_qkv);
    cudaGetSymbolAddress((void**)&ao,  g_ao);
    cudaGetSymbolAddress((void**)&ar,  g_ar);
    cudaGetSymbolAddress((void**)&hn,  g_hn);
    cudaGetSymbolAddress((void**)&h1,  g_h1);
    cudaGetSymbolAddress((void**)&wqkvt, g_wqkvt);
    cudaGetSymbolAddress((void**)&bqkv,  g_bqkv);
    cudaGetSymbolAddress((void**)&wot, g_wot);
    cudaGetSymbolAddress((void**)&w1t, g_w1t);
    cudaGetSymbolAddress((void**)&w2t, g_w2t);

    static int attr_done = 0;
    if (!attr_done) {
        cudaFuncSetAttribute(flash_kernel,
            cudaFuncAttributeMaxDynamicSharedMemorySize, FLASH_SMEM_BYTES);
        cudaFuncSetAttribute(mma_gemm_kernel<0, true>,
            cudaFuncAttributeMaxDynamicSharedMemorySize, GEMM_SMEM_BYTES);
        cudaFuncSetAttribute(mma_gemm_kernel<1, true>,
            cudaFuncAttributeMaxDynamicSharedMemorySize, GEMM_SMEM_BYTES);
        cudaFuncSetAttribute(mma_gemm_kernel<2, false>,
            cudaFuncAttributeMaxDynamicSharedMemorySize, GEMM_SMEM_BYTES);
        cudaFuncSetAttribute(mma_gemm_kernel<3, true>,
            cudaFuncAttributeMaxDynamicSharedMemorySize, GEMM_SMEM_BYTES);
        attr_done = 1;
    }

    // 0. Weight prep (half, transposed to [N][K])
    dim3 tb(32, 8);
    transpose_half_kernel<<<dim3(DD / 32, DD / 32), tb>>>(wq, wqkvt, DD, DD);
    transpose_half_kernel<<<dim3(DD / 32, DD / 32), tb>>>(wk, wqkvt + 1024 * DD, DD, DD);
    transpose_half_kernel<<<dim3(DD / 32, DD / 32), tb>>>(wv, wqkvt + 2048 * DD, DD, DD);
    transpose_half_kernel<<<dim3(FF / 32, DD / 32), tb>>>(w1, w1t, DD, FF);
    transpose_half_kernel<<<dim3(DD / 32, FF / 32), tb>>>(w2, w2t, FF, DD);
    copy_half_kernel<<<(DD * DD / 4 + 255) / 256, 256>>>(wo, wot, DD * DD / 4);
    concat_bias_kernel<<<(QKVN + 255) / 256, 256>>>(bq, bk, bv, bqkv);

    // 1. RMSNorm (half out)
    rmsnorm_kernel<<<MM, 256>>>(x, rms_scale, xn);

    // 2. Fused QKV projection (half out; qscale on q cols)
    dim3 gQKV(QKVN / 128, MM / 128);
    mma_gemm_kernel<1, true><<<gQKV, 256, GEMM_SMEM_BYTES>>>(
        xn, wqkvt, bqkv, pds, qkv, MM, QKVN, DD);

    // 3. Flash attention (fp16 mma)
    flash_kernel<<<dim3(TT / 64, BB * NHEAD), 256, FLASH_SMEM_BYTES>>>(
        qkv, padding, ao);

    // 4. Output projection + bias + residual(x) -> ar (float)
    dim3 gD(DD / 128, MM / 128);
    mma_gemm_kernel<2, false><<<gD, 256, GEMM_SMEM_BYTES>>>(
        ao, wot, bo, x, ar, MM, DD, DD);

    // 5. LayerNorm (half out)
    layernorm_kernel<<<MM, 256>>>(ar, ln_gamma, ln_beta, hn);

    // 6. FFN up + ReLU (half out)
    dim3 gF(FF / 128, MM / 128);
    mma_gemm_kernel<3, true><<<gF, 256, GEMM_SMEM_BYTES>>>(
        hn, w1t, b1, nullptr, h1, MM, FF, DD);

    // 7. FFN down + bias + residual(ar) -> output (float)
    mma_gemm_kernel<2, false><<<gD, 256, GEMM_SMEM_BYTES>>>(
        h1, w2t, b2, ar, out, MM, DD, FF);
}

// round 7
// speedup vs baseline: 7.2286x; 1.0101x over previous
#include <cuda_runtime.h>
#include <cuda_fp16.h>
#include <cstdint>
#include <math.h>

// Problem constants
#define BB 8
#define TT 1024
#define DD 1024
#define NHEAD 16
#define HDIM 64
#define FF 4096
#define MM (BB * TT)   // 8192
#define QKVN 3072

// ---------------------------------------------------------------------------
// Scratch (device globals)
// ---------------------------------------------------------------------------
__device__ __half g_xn [MM * DD];
__device__ __half g_qkv[MM * QKVN];
__device__ __half g_ao [MM * DD];
__device__ float  g_ar [MM * DD];
__device__ __half g_hn [MM * DD];
__device__ __half g_h1 [MM * FF];
__device__ __half g_wqkvt[QKVN * DD];   // [3072][1024] K-major (q|k|v)
__device__ float  g_bqkv [QKVN];
__device__ __half g_wot[DD * DD];
__device__ __half g_w1t[FF * DD];
__device__ __half g_w2t[DD * FF];

// ---------------------------------------------------------------------------
// Helpers
// ---------------------------------------------------------------------------
__device__ __forceinline__ uint32_t s2u(const void* p) {
    uint32_t a;
    asm("{ .reg .u64 t; cvta.to.shared.u64 t, %1; cvt.u32.u64 %0, t; }"
        : "=r"(a) : "l"(p));
    return a;
}

__device__ __forceinline__ void cp_async16(uint32_t saddr, const void* gaddr) {
    asm volatile("cp.async.cg.shared.global [%0], [%1], 16;"
                 :: "r"(saddr), "l"(gaddr));
}
__device__ __forceinline__ void cp_commit() {
    asm volatile("cp.async.commit_group;");
}
template <int N>
__device__ __forceinline__ void cp_wait() {
    asm volatile("cp.async.wait_group %0;" :: "n"(N));
}

__device__ __forceinline__ void ldsm4(uint32_t& r0, uint32_t& r1,
                                      uint32_t& r2, uint32_t& r3, uint32_t addr) {
    asm volatile("ldmatrix.sync.aligned.m8n8.x4.shared.b16 {%0,%1,%2,%3}, [%4];"
                 : "=r"(r0), "=r"(r1), "=r"(r2), "=r"(r3) : "r"(addr));
}

// fp16 MMA m16n8k16, fp32 accumulate
__device__ __forceinline__ void mma_f16(float* c, const uint32_t* a,
                                        uint32_t b0, uint32_t b1) {
    asm volatile(
        "mma.sync.aligned.m16n8k16.row.col.f32.f16.f16.f32 "
        "{%0,%1,%2,%3}, {%4,%5,%6,%7}, {%8,%9}, {%0,%1,%2,%3};"
        : "+f"(c[0]), "+f"(c[1]), "+f"(c[2]), "+f"(c[3])
        : "r"(a[0]), "r"(a[1]), "r"(a[2]), "r"(a[3]), "r"(b0), "r"(b1));
}

__device__ __forceinline__ uint32_t pkh2(float a, float b) {
    const __half2 h = __floats2half2_rn(a, b);
    return *(const uint32_t*)&h;
}

// ---------------------------------------------------------------------------
// Fused prep kernel: all weight transposes/conversions + bias concat
// ---------------------------------------------------------------------------
__device__ __forceinline__ void transpose_tile(
    const float* __restrict__ in, __half* __restrict__ out,
    int bx, int by, int C, int R, float (*t)[33], int tid)
{
    const int txx = tid & 31, tyy = tid >> 5;
    #pragma unroll
    for (int j = 0; j < 32; j += 8)
        t[tyy + j][txx] = in[(size_t)(by + tyy + j) * C + bx + txx];
    __syncthreads();
    #pragma unroll
    for (int j = 0; j < 32; j += 8)
        out[(size_t)(bx + tyy + j) * R + by + txx] = __float2half_rn(t[txx][tyy + j]);
}

#define PREP_BLOCKS 12300

__global__ __launch_bounds__(256) void prep_kernel(
    const float* __restrict__ wq, const float* __restrict__ wk,
    const float* __restrict__ wv, const float* __restrict__ w1,
    const float* __restrict__ w2, const float* __restrict__ wo,
    const float* __restrict__ bq, const float* __restrict__ bk,
    const float* __restrict__ bv,
    __half* __restrict__ wqkvt, __half* __restrict__ w1t,
    __half* __restrict__ w2t, __half* __restrict__ wot,
    float* __restrict__ bqkv)
{
    __shared__ float t[32][33];
    const int id = blockIdx.x;
    const int tid = threadIdx.x;

    if (id < 3072) {                       // wq/wk/wv transpose 1024x1024
        const int w = id >> 10, tt = id & 1023;
        const float* in = (w == 0) ? wq : (w == 1) ? wk : wv;
        __half* outp = wqkvt + (size_t)w * 1024 * DD;
        transpose_tile(in, outp, (tt & 31) << 5, (tt >> 5) << 5, DD, DD, t, tid);
    } else if (id < 7168) {                // w1 [D][F] -> w1t [F][D]
        const int tt = id - 3072;
        transpose_tile(w1, w1t, (tt & 127) << 5, (tt >> 7) << 5, FF, DD, t, tid);
    } else if (id < 11264) {               // w2 [F][D] -> w2t [D][F]
        const int tt = id - 7168;
        transpose_tile(w2, w2t, (tt & 31) << 5, (tt >> 5) << 5, DD, FF, t, tid);
    } else if (id < 12288) {               // wo convert copy (already [N][K])
        const int i = (id - 11264) * 1024 + tid * 4;
        const float4 v = *(const float4*)(wo + i);
        __half2* o2 = (__half2*)(wot + i);
        o2[0] = __floats2half2_rn(v.x, v.y);
        o2[1] = __floats2half2_rn(v.z, v.w);
    } else {                               // bias concat
        const int i = (id - 12288) * 256 + tid;
        if (i < QKVN)
            bqkv[i] = (i < 1024) ? bq[i] : (i < 2048) ? bk[i - 1024] : bv[i - 2048];
    }
}

// ---------------------------------------------------------------------------
// RMSNorm / LayerNorm (half outputs)
// ---------------------------------------------------------------------------
__global__ __launch_bounds__(256) void rmsnorm_kernel(
    const float* __restrict__ x, const float* __restrict__ scale,
    __half* __restrict__ out)
{
    const int row = blockIdx.x;
    const int tid = threadIdx.x;
    const float4 v = ((const float4*)(x + (size_t)row * DD))[tid];
    float ss = v.x * v.x + v.y * v.y + v.z * v.z + v.w * v.w;
    #pragma unroll
    for (int m = 16; m; m >>= 1) ss += __shfl_xor_sync(0xffffffffu, ss, m);
    __shared__ float sred[8];
    if ((tid & 31) == 0) sred[tid >> 5] = ss;
    __syncthreads();
    float tot = 0.f;
    #pragma unroll
    for (int i = 0; i < 8; i++) tot += sred[i];
    const float r = rsqrtf(tot * (1.0f / DD) + 1e-6f);
    const float4 s4 = ((const float4*)scale)[tid];
    __half2* o2 = (__half2*)(out + (size_t)row * DD) + tid * 2;
    o2[0] = __floats2half2_rn(v.x * r * s4.x, v.y * r * s4.y);
    o2[1] = __floats2half2_rn(v.z * r * s4.z, v.w * r * s4.w);
}

__global__ __launch_bounds__(256) void layernorm_kernel(
    const float* __restrict__ x, const float* __restrict__ gamma,
    const float* __restrict__ beta, __half* __restrict__ out)
{
    const int row = blockIdx.x;
    const int tid = threadIdx.x;
    const float4 v = ((const float4*)(x + (size_t)row * DD))[tid];
    float s  = v.x + v.y + v.z + v.w;
    float ss = v.x * v.x + v.y * v.y + v.z * v.z + v.w * v.w;
    #pragma unroll
    for (int m = 16; m; m >>= 1) {
        s  += __shfl_xor_sync(0xffffffffu, s,  m);
        ss += __shfl_xor_sync(0xffffffffu, ss, m);
    }
    __shared__ float sr1[8], sr2[8];
    if ((tid & 31) == 0) { sr1[tid >> 5] = s; sr2[tid >> 5] = ss; }
    __syncthreads();
    float S = 0.f, SS = 0.f;
    #pragma unroll
    for (int i = 0; i < 8; i++) { S += sr1[i]; SS += sr2[i]; }
    const float mean = S * (1.0f / DD);
    const float var  = SS * (1.0f / DD) - mean * mean;
    const float r = rsqrtf(var + 1e-5f);
    const float4 g4 = ((const float4*)gamma)[tid];
    const float4 b4 = ((const float4*)beta)[tid];
    __half2* o2 = (__half2*)(out + (size_t)row * DD) + tid * 2;
    o2[0] = __floats2half2_rn((v.x - mean) * r * g4.x + b4.x,
                              (v.y - mean) * r * g4.y + b4.y);
    o2[1] = __floats2half2_rn((v.z - mean) * r * g4.z + b4.z,
                              (v.w - mean) * r * g4.w + b4.w);
}

// ---------------------------------------------------------------------------
// fp16 mma.sync GEMM (unchanged from R5 — proven)
// ---------------------------------------------------------------------------
__device__ __forceinline__ float softplus_f(float x) {
    return (x > 15.f) ? x : log1pf(__expf(x));
}

#define GSTAGE 32768
#define GEMM_SMEM_BYTES (3 * GSTAGE)

template <int EPI, bool OUTH>
__global__ __launch_bounds__(256, 2) void mma_gemm_kernel(
    const __half* __restrict__ A, const __half* __restrict__ Bw,
    const float* __restrict__ bias, const float* __restrict__ extra,
    void* __restrict__ Cv, int M, int N, int K)
{
    extern __shared__ char gsm[];
    const uint32_t smbase = s2u(gsm);
    const int tid = threadIdx.x;
    const int lane = tid & 31;
    const int wid = tid >> 5;
    const int m0 = blockIdx.y << 7;
    const int n0 = blockIdx.x << 7;
    const int wm = (wid & 3) << 5;
    const int wn = (wid >> 2) << 6;

    uint32_t a_soff[4], b_soff[4];
    const __half* a_g[4]; const __half* b_g[4];
    #pragma unroll
    for (int u = 0; u < 4; u++) {
        const int qch = tid + u * 256;
        const int m = qch >> 3, kc = qch & 7;
        const uint32_t sw = (uint32_t)(kc ^ (m & 7));
        a_soff[u] = (uint32_t)(m * 128) + (sw << 4);
        b_soff[u] = a_soff[u] + 16384u;
        a_g[u] = A  + (size_t)(m0 + m) * K + kc * 8;
        b_g[u] = Bw + (size_t)(n0 + m) * K + kc * 8;
    }

    const int arow = wm + (lane & 15);
    const uint32_t acadd = (uint32_t)(lane >> 4);
    const uint32_t aswz = (uint32_t)(arow & 7);
    const uint32_t aoff = (uint32_t)(arow * 128);
    const int brow = wn + ((lane >> 4) << 3) + (lane & 7);
    const uint32_t bcc = (uint32_t)((lane >> 3) & 1);
    const uint32_t bswz = (uint32_t)(brow & 7);
    const uint32_t boff = (uint32_t)(brow * 128) + 16384u;

    float acc[2][8][4];
    #pragma unroll
    for (int i = 0; i < 2; i++)
        #pragma unroll
        for (int j = 0; j < 8; j++)
            #pragma unroll
            for (int t = 0; t < 4; t++) acc[i][j][t] = 0.f;

    const int nk = K >> 6;
    #pragma unroll
    for (int s = 0; s < 2; s++) {
        const uint32_t sb = smbase + (uint32_t)s * GSTAGE;
        #pragma unroll
        for (int u = 0; u < 4; u++) {
            cp_async16(sb + a_soff[u], a_g[u] + s * 64);
            cp_async16(sb + b_soff[u], b_g[u] + s * 64);
        }
        cp_commit();
    }

    int sidx = 0;
    for (int kc = 0; kc < nk; kc++) {
        if (kc == nk - 1) cp_wait<0>(); else cp_wait<1>();
        __syncthreads();
        if (kc + 2 < nk) {
            const int s2 = (sidx + 2 >= 3) ? sidx - 1 : sidx + 2;
            const uint32_t sb = smbase + (uint32_t)s2 * GSTAGE;
            #pragma unroll
            for (int u = 0; u < 4; u++) {
                cp_async16(sb + a_soff[u], a_g[u] + (kc + 2) * 64);
                cp_async16(sb + b_soff[u], b_g[u] + (kc + 2) * 64);
            }
            cp_commit();
        }
        const uint32_t sb = smbase + (uint32_t)sidx * GSTAGE;
        #pragma unroll
        for (int ks = 0; ks < 4; ks++) {
            const uint32_t kc0 = (uint32_t)(2 * ks);
            uint32_t af[2][4];
            #pragma unroll
            for (int i = 0; i < 2; i++) {
                const uint32_t addr = sb + aoff + (uint32_t)(i * 2048) +
                                      (((kc0 + acadd) ^ aswz) << 4);
                ldsm4(af[i][0], af[i][1], af[i][2], af[i][3], addr);
            }
            #pragma unroll
            for (int jp = 0; jp < 4; jp++) {
                uint32_t b0, b1, b2, b3;
                const uint32_t addr = sb + boff + (uint32_t)(jp * 2048) +
                                      (((kc0 + bcc) ^ bswz) << 4);
                ldsm4(b0, b1, b2, b3, addr);
                #pragma unroll
                for (int i = 0; i < 2; i++) {
                    mma_f16(acc[i][2 * jp + 0], af[i], b0, b1);
                    mma_f16(acc[i][2 * jp + 1], af[i], b2, b3);
                }
            }
        }
        sidx = (sidx == 2) ? 0 : sidx + 1;
    }

    const int g = lane >> 2, tg = lane & 3;
    #pragma unroll
    for (int i = 0; i < 2; i++) {
        #pragma unroll
        for (int j = 0; j < 8; j++) {
            const int col = n0 + wn + j * 8 + tg * 2;
            const float2 b2 = *(const float2*)(bias + col);
            float sx = 1.f, sy = 1.f;
            if (EPI == 1) {
                if (col < 1024) {
                    const float c = 0.18033688f;  // log2(e)/sqrt(64)
                    sx = c * softplus_f(extra[col & 63]);
                    sy = c * softplus_f(extra[(col + 1) & 63]);
                }
            }
            #pragma unroll
            for (int h = 0; h < 2; h++) {
                const int row = m0 + wm + i * 16 + g + h * 8;
                float vx = acc[i][j][2 * h + 0] + b2.x;
                float vy = acc[i][j][2 * h + 1] + b2.y;
                if (EPI == 1) { vx *= sx; vy *= sy; }
                if (EPI == 2) {
                    const float2 r2 = *(const float2*)(extra + (size_t)row * N + col);
                    vx += r2.x; vy += r2.y;
                }
                if (EPI == 3) { vx = fmaxf(vx, 0.f); vy = fmaxf(vy, 0.f); }
                if (OUTH) {
                    *(__half2*)((__half*)Cv + (size_t)row * N + col) =
                        __floats2half2_rn(vx, vy);
                } else {
                    float2 o2; o2.x = vx; o2.y = vy;
                    *(float2*)((float*)Cv + (size_t)row * N + col) = o2;
                }
            }
        }
    }
}

// ---------------------------------------------------------------------------
// Flash attention v2: warp-local softmax, P kept in registers (FA2 layout
// trick: C-fragment of S reused directly as A-fragment for PV).
// 8 warps: (wid&3) -> 16-row group, (wid>>2) -> s-half (32 cols of the tile).
// Per-warp O is 16x64 over its own s-half; halves merged once at the end.
// ---------------------------------------------------------------------------
// byte offsets
#define FL_Q 0
#define FL_K 8192
#define FL_V 16384
// staging (floats) reuses [0, 32768) after the loop
#define FL_PQ_I 8192    // float idx (byte 32768): padq[64]
#define FL_PS_I 8256    // pads[64]
#define FL_M_I  8320    // m[2][64]
#define FL_L_I  8448    // l[2][64]
#define FLASH_SMEM_BYTES (32768 + 1792)

__global__ __launch_bounds__(256) void flash_kernel(
    const __half* __restrict__ qkv, const float* __restrict__ pad,
    __half* __restrict__ out)
{
    extern __shared__ float sf[];
    char* smc = (char*)sf;
    const uint32_t sbase = s2u(sf);
    const int tid = threadIdx.x;
    const int lane = tid & 31;
    const int wid = tid >> 5;
    const int wm = (wid & 3) << 4;        // row group 0..48
    const int sh = wid >> 2;              // s-half 0/1
    const int g = lane >> 2, tg = lane & 3;
    const int t0 = blockIdx.x << 6;
    const int b = blockIdx.y >> 4, n = blockIdx.y & 15;

    const int arow = wm + (lane & 15);
    const uint32_t acadd = (uint32_t)(lane >> 4);
    const uint32_t aswz = (uint32_t)(arow & 7);
    const uint32_t qbase = sbase + FL_Q + (uint32_t)(arow * 128);
    const int brw = ((lane >> 4) << 3) + (lane & 7);
    const uint32_t bcc = (uint32_t)((lane >> 3) & 1);

    // ---- load Q (64 rows x 64 halfs, swizzled 128B rows)
    {
        const int r = tid >> 2;
        const int c0 = (tid & 3) << 1;
        const __half* qp = qkv + (size_t)(b * TT + t0 + r) * QKVN + n * 64;
        #pragma unroll
        for (int u = 0; u < 2; u++) {
            const int c = c0 + u;
            *(uint4*)(smc + FL_Q + r * 128 + ((c ^ (r & 7)) << 4)) =
                *(const uint4*)(qp + c * 8);
        }
    }
    if (tid < 64) sf[FL_PQ_I + tid] = pad[b * TT + t0 + tid];

    float o[8][4];
    #pragma unroll
    for (int j = 0; j < 8; j++)
        #pragma unroll
        for (int c = 0; c < 4; c++) o[j][c] = 0.f;
    float m0 = -1e30f, m1 = -1e30f, l0 = 0.f, l1 = 0.f;
    const int r0l = wm + g, r1l = r0l + 8;

    for (int s0 = 0; s0 <= t0; s0 += 64) {
        // ---- load K + V^T + pads
        {
            const int r = tid >> 2;
            const int c0 = (tid & 3) << 1;
            const __half* kp = qkv + (size_t)(b * TT + s0 + r) * QKVN + 1024 + n * 64;
            #pragma unroll
            for (int u = 0; u < 2; u++) {
                const int c = c0 + u;
                *(uint4*)(smc + FL_K + r * 128 + ((c ^ (r & 7)) << 4)) =
                    *(const uint4*)(kp + c * 8);
            }
            const int s = tid >> 2;
            const int hc = (tid & 3) << 4;
            const __half* vp = qkv + (size_t)(b * TT + s0 + s) * QKVN + 2048 + n * 64 + hc;
            __half vr[16];
            *(uint4*)&vr[0] = *(const uint4*)(vp);
            *(uint4*)&vr[8] = *(const uint4*)(vp + 8);
            __half* vt = (__half*)(smc + FL_V);
            const int cs = s >> 3, si = s & 7;
            #pragma unroll
            for (int j = 0; j < 16; j++) {
                const int h = hc + j;
                vt[h * 64 + ((cs ^ (h & 7)) << 3) + si] = vr[j];
            }
            if (tid < 64) sf[FL_PS_I + tid] = pad[b * TT + s0 + tid];
        }
        __syncthreads();

        // ---- S = Q K^T for warp's 16 rows x 32 s-cols
        float sacc[4][4];
        #pragma unroll
        for (int j = 0; j < 4; j++)
            #pragma unroll
            for (int c = 0; c < 4; c++) sacc[j][c] = 0.f;
        #pragma unroll
        for (int ks = 0; ks < 4; ks++) {
            const uint32_t kc0 = (uint32_t)(2 * ks);
            uint32_t af[4];
            ldsm4(af[0], af[1], af[2], af[3],
                  qbase + (((kc0 + acadd) ^ aswz) << 4));
            #pragma unroll
            for (int jp = 0; jp < 2; jp++) {
                const int brow = sh * 32 + jp * 16 + brw;
                uint32_t b0, b1, b2, b3;
                ldsm4(b0, b1, b2, b3,
                      sbase + FL_K + (uint32_t)(brow * 128) +
                      (((kc0 + bcc) ^ (uint32_t)(brow & 7)) << 4));
                mma_f16(sacc[2 * jp + 0], af, b0, b1);
                mma_f16(sacc[2 * jp + 1], af, b2, b3);
            }
        }

        // ---- mask (causal + padding)
        const float pq0 = sf[FL_PQ_I + r0l], pq1 = sf[FL_PQ_I + r1l];
        const int rg0 = t0 + r0l, rg1 = t0 + r1l;
        #pragma unroll
        for (int j = 0; j < 4; j++) {
            const int cl = sh * 32 + j * 8 + 2 * tg;
            const int cg = s0 + cl;
            const float ps0 = sf[FL_PS_I + cl], ps1 = sf[FL_PS_I + cl + 1];
            if (!(pq0 != 0.f && ps0 != 0.f && cg     <= rg0)) sacc[j][0] = -1e9f;
            if (!(pq0 != 0.f && ps1 != 0.f && cg + 1 <= rg0)) sacc[j][1] = -1e9f;
            if (!(pq1 != 0.f && ps0 != 0.f && cg     <= rg1)) sacc[j][2] = -1e9f;
            if (!(pq1 != 0.f && ps1 != 0.f && cg + 1 <= rg1)) sacc[j][3] = -1e9f;
        }

        // ---- warp-local online softmax (reduce over the 4 tg lanes)
        float rm0 = -1e30f, rm1 = -1e30f;
        #pragma unroll
        for (int j = 0; j < 4; j++) {
            rm0 = fmaxf(rm0, fmaxf(sacc[j][0], sacc[j][1]));
            rm1 = fmaxf(rm1, fmaxf(sacc[j][2], sacc[j][3]));
        }
        rm0 = fmaxf(rm0, __shfl_xor_sync(0xffffffffu, rm0, 1));
        rm0 = fmaxf(rm0, __shfl_xor_sync(0xffffffffu, rm0, 2));
        rm1 = fmaxf(rm1, __shfl_xor_sync(0xffffffffu, rm1, 1));
        rm1 = fmaxf(rm1, __shfl_xor_sync(0xffffffffu, rm1, 2));
        const float mn0 = fmaxf(m0, rm0), mn1 = fmaxf(m1, rm1);
        const float alpha0 = __expf(m0 - mn0), alpha1 = __expf(m1 - mn1);
        m0 = mn0; m1 = mn1;
        float rs0 = 0.f, rs1 = 0.f;
        #pragma unroll
        for (int j = 0; j < 4; j++) {
            sacc[j][0] = __expf(sacc[j][0] - mn0);
            sacc[j][1] = __expf(sacc[j][1] - mn0);
            sacc[j][2] = __expf(sacc[j][2] - mn1);
            sacc[j][3] = __expf(sacc[j][3] - mn1);
            rs0 += sacc[j][0] + sacc[j][1];
            rs1 += sacc[j][2] + sacc[j][3];
        }
        rs0 += __shfl_xor_sync(0xffffffffu, rs0, 1);
        rs0 += __shfl_xor_sync(0xffffffffu, rs0, 2);
        rs1 += __shfl_xor_sync(0xffffffffu, rs1, 1);
        rs1 += __shfl_xor_sync(0xffffffffu, rs1, 2);
        l0 = l0 * alpha0 + rs0;
        l1 = l1 * alpha1 + rs1;
        #pragma unroll
        for (int j = 0; j < 8; j++) {
            o[j][0] *= alpha0; o[j][1] *= alpha0;
            o[j][2] *= alpha1; o[j][3] *= alpha1;
        }

        // ---- pack P into A-fragments (C->A layout identity)
        uint32_t pa[2][4];
        #pragma unroll
        for (int ks = 0; ks < 2; ks++) {
            pa[ks][0] = pkh2(sacc[2 * ks][0],     sacc[2 * ks][1]);
            pa[ks][1] = pkh2(sacc[2 * ks][2],     sacc[2 * ks][3]);
            pa[ks][2] = pkh2(sacc[2 * ks + 1][0], sacc[2 * ks + 1][1]);
            pa[ks][3] = pkh2(sacc[2 * ks + 1][2], sacc[2 * ks + 1][3]);
        }

        // ---- O += P V over warp's s-half (k chunks 4sh..4sh+3)
        #pragma unroll
        for (int ks = 0; ks < 2; ks++) {
            const uint32_t kc0 = (uint32_t)(2 * (2 * sh + ks));
            #pragma unroll
            for (int jp = 0; jp < 4; jp++) {
                const int brow = jp * 16 + brw;
                uint32_t b0, b1, b2, b3;
                ldsm4(b0, b1, b2, b3,
                      sbase + FL_V + (uint32_t)(brow * 128) +
                      (((kc0 + bcc) ^ (uint32_t)(brow & 7)) << 4));
                mma_f16(o[2 * jp + 0], pa[ks], b0, b1);
                mma_f16(o[2 * jp + 1], pa[ks], b2, b3);
            }
        }
        __syncthreads();
    }

    // ---- merge the two s-halves
    if (tg == 0) {
        sf[FL_M_I + sh * 64 + r0l] = m0;
        sf[FL_M_I + sh * 64 + r1l] = m1;
        sf[FL_L_I + sh * 64 + r0l] = l0;
        sf[FL_L_I + sh * 64 + r1l] = l1;
    }
    __syncthreads();
    const float mo0 = sf[FL_M_I + (1 - sh) * 64 + r0l];
    const float mo1 = sf[FL_M_I + (1 - sh) * 64 + r1l];
    const float mf0 = fmaxf(m0, mo0), mf1 = fmaxf(m1, mo1);
    const float f0 = __expf(m0 - mf0), f1 = __expf(m1 - mf1);
    float* stg = sf + sh * 4096;   // staging overwrites Q/K/V (done with them)
    #pragma unroll
    for (int j = 0; j < 8; j++) {
        const int col = j * 8 + 2 * tg;
        stg[r0l * 64 + col + 0] = o[j][0] * f0;
        stg[r0l * 64 + col + 1] = o[j][1] * f0;
        stg[r1l * 64 + col + 0] = o[j][2] * f1;
        stg[r1l * 64 + col + 1] = o[j][3] * f1;
    }
    __syncthreads();
    if (sh == 0) {
        const float lo0 = sf[FL_L_I + 64 + r0l], lo1 = sf[FL_L_I + 64 + r1l];
        const float inv0 = 1.f / (l0 * f0 + lo0 * __expf(mo0 - mf0));
        const float inv1 = 1.f / (l1 * f1 + lo1 * __expf(mo1 - mf1));
        const size_t row0 = (size_t)(b * TT + t0 + r0l);
        const size_t row1 = (size_t)(b * TT + t0 + r1l);
        #pragma unroll
        for (int j = 0; j < 8; j++) {
            const int col = j * 8 + 2 * tg;
            const float v00 = (sf[r0l * 64 + col + 0] + sf[4096 + r0l * 64 + col + 0]) * inv0;
            const float v01 = (sf[r0l * 64 + col + 1] + sf[4096 + r0l * 64 + col + 1]) * inv0;
            const float v10 = (sf[r1l * 64 + col + 0] + sf[4096 + r1l * 64 + col + 0]) * inv1;
            const float v11 = (sf[r1l * 64 + col + 1] + sf[4096 + r1l * 64 + col + 1]) * inv1;
            *(__half2*)(out + row0 * DD + n * 64 + col) = __floats2half2_rn(v00, v01);
            *(__half2*)(out + row1 * DD + n * 64 + col) = __floats2half2_rn(v10, v11);
        }
    }
}

// ---------------------------------------------------------------------------
// Host launch
// ---------------------------------------------------------------------------
extern "C" void kernel_launch(void* const* d_in, const int* in_sizes, int n_in,
                              void* d_out, int out_size)
{
    (void)in_sizes; (void)n_in; (void)out_size;
    const float* x         = (const float*)d_in[0];
    const float* padding   = (const float*)d_in[1];
    const float* rms_scale = (const float*)d_in[2];
    const float* pds       = (const float*)d_in[3];
    const float* wq        = (const float*)d_in[4];
    const float* bq        = (const float*)d_in[5];
    const float* wk        = (const float*)d_in[6];
    const float* bk        = (const float*)d_in[7];
    const float* wv        = (const float*)d_in[8];
    const float* bv        = (const float*)d_in[9];
    const float* wo        = (const float*)d_in[10];
    const float* bo        = (const float*)d_in[11];
    const float* ln_gamma  = (const float*)d_in[12];
    const float* ln_beta   = (const float*)d_in[13];
    const float* w1        = (const float*)d_in[14];
    const float* b1        = (const float*)d_in[15];
    const float* w2        = (const float*)d_in[16];
    const float* b2        = (const float*)d_in[17];
    float* out = (float*)d_out;

    __half *xn, *qkv, *ao, *hn, *h1, *wqkvt, *wot, *w1t, *w2t;
    float *ar, *bqkv;
    cudaGetSymbolAddress((void**)&xn,  g_xn);
    cudaGetSymbolAddress((void**)&qkv, g_qkv);
    cudaGetSymbolAddress((void**)&ao,  g_ao);
    cudaGetSymbolAddress((void**)&ar,  g_ar);
    cudaGetSymbolAddress((void**)&hn,  g_hn);
    cudaGetSymbolAddress((void**)&h1,  g_h1);
    cudaGetSymbolAddress((void**)&wqkvt, g_wqkvt);
    cudaGetSymbolAddress((void**)&bqkv,  g_bqkv);
    cudaGetSymbolAddress((void**)&wot, g_wot);
    cudaGetSymbolAddress((void**)&w1t, g_w1t);
    cudaGetSymbolAddress((void**)&w2t, g_w2t);

    static int attr_done = 0;
    if (!attr_done) {
        cudaFuncSetAttribute(flash_kernel,
            cudaFuncAttributeMaxDynamicSharedMemorySize, FLASH_SMEM_BYTES);
        cudaFuncSetAttribute(mma_gemm_kernel<1, true>,
            cudaFuncAttributeMaxDynamicSharedMemorySize, GEMM_SMEM_BYTES);
        cudaFuncSetAttribute(mma_gemm_kernel<2, false>,
            cudaFuncAttributeMaxDynamicSharedMemorySize, GEMM_SMEM_BYTES);
        cudaFuncSetAttribute(mma_gemm_kernel<3, true>,
            cudaFuncAttributeMaxDynamicSharedMemorySize, GEMM_SMEM_BYTES);
        attr_done = 1;
    }

    // 0. Fused weight prep (single launch)
    prep_kernel<<<PREP_BLOCKS, 256>>>(wq, wk, wv, w1, w2, wo, bq, bk, bv,
                                      wqkvt, w1t, w2t, wot, bqkv);

    // 1. RMSNorm (half out)
    rmsnorm_kernel<<<MM, 256>>>(x, rms_scale, xn);

    // 2. Fused QKV projection
    dim3 gQKV(QKVN / 128, MM / 128);
    mma_gemm_kernel<1, true><<<gQKV, 256, GEMM_SMEM_BYTES>>>(
        xn, wqkvt, bqkv, pds, qkv, MM, QKVN, DD);

    // 3. Flash attention v2
    flash_kernel<<<dim3(TT / 64, BB * NHEAD), 256, FLASH_SMEM_BYTES>>>(
        qkv, padding, ao);

    // 4. Output projection + bias + residual(x) -> ar (float)
    dim3 gD(DD / 128, MM / 128);
    mma_gemm_kernel<2, false><<<gD, 256, GEMM_SMEM_BYTES>>>(
        ao, wot, bo, x, ar, MM, DD, DD);

    // 5. LayerNorm (half out)
    layernorm_kernel<<<MM, 256>>>(ar, ln_gamma, ln_beta, hn);

    // 6. FFN up + ReLU (half out)
    dim3 gF(FF / 128, MM / 128);
    mma_gemm_kernel<3, true><<<gF, 256, GEMM_SMEM_BYTES>>>(
        hn, w1t, b1, nullptr, h1, MM, FF, DD);

    // 7. FFN down + bias + residual(ar) -> output (float)
    mma_gemm_kernel<2, false><<<gD, 256, GEMM_SMEM_BYTES>>>(
        h1, w2t, b2, ar, out, MM, DD, FF);
}

// round 8
// speedup vs baseline: 7.7306x; 1.0695x over previous
#include <cuda_runtime.h>
#include <cuda_fp16.h>
#include <cstdint>
#include <math.h>

// Problem constants
#define BB 8
#define TT 1024
#define DD 1024
#define NHEAD 16
#define HDIM 64
#define FF 4096
#define MM (BB * TT)   // 8192
#define QKVN 3072

// ---------------------------------------------------------------------------
// Scratch (device globals)
// ---------------------------------------------------------------------------
__device__ __half g_xn [MM * DD];
__device__ __half g_qkv[MM * QKVN];
__device__ __half g_ao [MM * DD];
__device__ float  g_ar [MM * DD];
__device__ __half g_hn [MM * DD];
__device__ __half g_h1 [MM * FF];
__device__ __half g_wqkvt[QKVN * DD];   // [3072][1024] K-major (q|k|v)
__device__ float  g_bqkv [QKVN];
__device__ __half g_wot[DD * DD];
__device__ __half g_w1t[FF * DD];
__device__ __half g_w2t[DD * FF];

// ---------------------------------------------------------------------------
// Helpers
// ---------------------------------------------------------------------------
__device__ __forceinline__ uint32_t s2u(const void* p) {
    uint32_t a;
    asm("{ .reg .u64 t; cvta.to.shared.u64 t, %1; cvt.u32.u64 %0, t; }"
        : "=r"(a) : "l"(p));
    return a;
}

__device__ __forceinline__ void cp_async16(uint32_t saddr, const void* gaddr) {
    asm volatile("cp.async.cg.shared.global [%0], [%1], 16;"
                 :: "r"(saddr), "l"(gaddr));
}
__device__ __forceinline__ void cp_async4(uint32_t saddr, const void* gaddr) {
    asm volatile("cp.async.ca.shared.global [%0], [%1], 4;"
                 :: "r"(saddr), "l"(gaddr));
}
__device__ __forceinline__ void cp_commit() {
    asm volatile("cp.async.commit_group;");
}
template <int N>
__device__ __forceinline__ void cp_wait() {
    asm volatile("cp.async.wait_group %0;" :: "n"(N));
}

__device__ __forceinline__ void ldsm4(uint32_t& r0, uint32_t& r1,
                                      uint32_t& r2, uint32_t& r3, uint32_t addr) {
    asm volatile("ldmatrix.sync.aligned.m8n8.x4.shared.b16 {%0,%1,%2,%3}, [%4];"
                 : "=r"(r0), "=r"(r1), "=r"(r2), "=r"(r3) : "r"(addr));
}
__device__ __forceinline__ void ldsm4t(uint32_t& r0, uint32_t& r1,
                                       uint32_t& r2, uint32_t& r3, uint32_t addr) {
    asm volatile("ldmatrix.sync.aligned.m8n8.x4.trans.shared.b16 {%0,%1,%2,%3}, [%4];"
                 : "=r"(r0), "=r"(r1), "=r"(r2), "=r"(r3) : "r"(addr));
}

// fp16 MMA m16n8k16, fp32 accumulate
__device__ __forceinline__ void mma_f16(float* c, const uint32_t* a,
                                        uint32_t b0, uint32_t b1) {
    asm volatile(
        "mma.sync.aligned.m16n8k16.row.col.f32.f16.f16.f32 "
        "{%0,%1,%2,%3}, {%4,%5,%6,%7}, {%8,%9}, {%0,%1,%2,%3};"
        : "+f"(c[0]), "+f"(c[1]), "+f"(c[2]), "+f"(c[3])
        : "r"(a[0]), "r"(a[1]), "r"(a[2]), "r"(a[3]), "r"(b0), "r"(b1));
}

__device__ __forceinline__ uint32_t pkh2(float a, float b) {
    const __half2 h = __floats2half2_rn(a, b);
    return *(const uint32_t*)&h;
}

// ---------------------------------------------------------------------------
// Fused prep kernel
// ---------------------------------------------------------------------------
__device__ __forceinline__ void transpose_tile(
    const float* __restrict__ in, __half* __restrict__ out,
    int bx, int by, int C, int R, float (*t)[33], int tid)
{
    const int txx = tid & 31, tyy = tid >> 5;
    #pragma unroll
    for (int j = 0; j < 32; j += 8)
        t[tyy + j][txx] = in[(size_t)(by + tyy + j) * C + bx + txx];
    __syncthreads();
    #pragma unroll
    for (int j = 0; j < 32; j += 8)
        out[(size_t)(bx + tyy + j) * R + by + txx] = __float2half_rn(t[txx][tyy + j]);
}

#define PREP_BLOCKS 12300

__global__ __launch_bounds__(256) void prep_kernel(
    const float* __restrict__ wq, const float* __restrict__ wk,
    const float* __restrict__ wv, const float* __restrict__ w1,
    const float* __restrict__ w2, const float* __restrict__ wo,
    const float* __restrict__ bq, const float* __restrict__ bk,
    const float* __restrict__ bv,
    __half* __restrict__ wqkvt, __half* __restrict__ w1t,
    __half* __restrict__ w2t, __half* __restrict__ wot,
    float* __restrict__ bqkv)
{
    __shared__ float t[32][33];
    const int id = blockIdx.x;
    const int tid = threadIdx.x;

    if (id < 3072) {
        const int w = id >> 10, tt = id & 1023;
        const float* in = (w == 0) ? wq : (w == 1) ? wk : wv;
        __half* outp = wqkvt + (size_t)w * 1024 * DD;
        transpose_tile(in, outp, (tt & 31) << 5, (tt >> 5) << 5, DD, DD, t, tid);
    } else if (id < 7168) {
        const int tt = id - 3072;
        transpose_tile(w1, w1t, (tt & 127) << 5, (tt >> 7) << 5, FF, DD, t, tid);
    } else if (id < 11264) {
        const int tt = id - 7168;
        transpose_tile(w2, w2t, (tt & 31) << 5, (tt >> 5) << 5, DD, FF, t, tid);
    } else if (id < 12288) {
        const int i = (id - 11264) * 1024 + tid * 4;
        const float4 v = *(const float4*)(wo + i);
        __half2* o2 = (__half2*)(wot + i);
        o2[0] = __floats2half2_rn(v.x, v.y);
        o2[1] = __floats2half2_rn(v.z, v.w);
    } else {
        const int i = (id - 12288) * 256 + tid;
        if (i < QKVN)
            bqkv[i] = (i < 1024) ? bq[i] : (i < 2048) ? bk[i - 1024] : bv[i - 2048];
    }
}

// ---------------------------------------------------------------------------
// RMSNorm / LayerNorm (half outputs)
// ---------------------------------------------------------------------------
__global__ __launch_bounds__(256) void rmsnorm_kernel(
    const float* __restrict__ x, const float* __restrict__ scale,
    __half* __restrict__ out)
{
    const int row = blockIdx.x;
    const int tid = threadIdx.x;
    const float4 v = ((const float4*)(x + (size_t)row * DD))[tid];
    float ss = v.x * v.x + v.y * v.y + v.z * v.z + v.w * v.w;
    #pragma unroll
    for (int m = 16; m; m >>= 1) ss += __shfl_xor_sync(0xffffffffu, ss, m);
    __shared__ float sred[8];
    if ((tid & 31) == 0) sred[tid >> 5] = ss;
    __syncthreads();
    float tot = 0.f;
    #pragma unroll
    for (int i = 0; i < 8; i++) tot += sred[i];
    const float r = rsqrtf(tot * (1.0f / DD) + 1e-6f);
    const float4 s4 = ((const float4*)scale)[tid];
    __half2* o2 = (__half2*)(out + (size_t)row * DD) + tid * 2;
    o2[0] = __floats2half2_rn(v.x * r * s4.x, v.y * r * s4.y);
    o2[1] = __floats2half2_rn(v.z * r * s4.z, v.w * r * s4.w);
}

__global__ __launch_bounds__(256) void layernorm_kernel(
    const float* __restrict__ x, const float* __restrict__ gamma,
    const float* __restrict__ beta, __half* __restrict__ out)
{
    const int row = blockIdx.x;
    const int tid = threadIdx.x;
    const float4 v = ((const float4*)(x + (size_t)row * DD))[tid];
    float s  = v.x + v.y + v.z + v.w;
    float ss = v.x * v.x + v.y * v.y + v.z * v.z + v.w * v.w;
    #pragma unroll
    for (int m = 16; m; m >>= 1) {
        s  += __shfl_xor_sync(0xffffffffu, s,  m);
        ss += __shfl_xor_sync(0xffffffffu, ss, m);
    }
    __shared__ float sr1[8], sr2[8];
    if ((tid & 31) == 0) { sr1[tid >> 5] = s; sr2[tid >> 5] = ss; }
    __syncthreads();
    float S = 0.f, SS = 0.f;
    #pragma unroll
    for (int i = 0; i < 8; i++) { S += sr1[i]; SS += sr2[i]; }
    const float mean = S * (1.0f / DD);
    const float var  = SS * (1.0f / DD) - mean * mean;
    const float r = rsqrtf(var + 1e-5f);
    const float4 g4 = ((const float4*)gamma)[tid];
    const float4 b4 = ((const float4*)beta)[tid];
    __half2* o2 = (__half2*)(out + (size_t)row * DD) + tid * 2;
    o2[0] = __floats2half2_rn((v.x - mean) * r * g4.x + b4.x,
                              (v.y - mean) * r * g4.y + b4.y);
    o2[1] = __floats2half2_rn((v.z - mean) * r * g4.z + b4.z,
                              (v.w - mean) * r * g4.w + b4.w);
}

// ---------------------------------------------------------------------------
// fp16 mma.sync GEMM (unchanged — proven)
// ---------------------------------------------------------------------------
__device__ __forceinline__ float softplus_f(float x) {
    return (x > 15.f) ? x : log1pf(__expf(x));
}

#define GSTAGE 32768
#define GEMM_SMEM_BYTES (3 * GSTAGE)

template <int EPI, bool OUTH>
__global__ __launch_bounds__(256, 2) void mma_gemm_kernel(
    const __half* __restrict__ A, const __half* __restrict__ Bw,
    const float* __restrict__ bias, const float* __restrict__ extra,
    void* __restrict__ Cv, int M, int N, int K)
{
    extern __shared__ char gsm[];
    const uint32_t smbase = s2u(gsm);
    const int tid = threadIdx.x;
    const int lane = tid & 31;
    const int wid = tid >> 5;
    const int m0 = blockIdx.y << 7;
    const int n0 = blockIdx.x << 7;
    const int wm = (wid & 3) << 5;
    const int wn = (wid >> 2) << 6;

    uint32_t a_soff[4], b_soff[4];
    const __half* a_g[4]; const __half* b_g[4];
    #pragma unroll
    for (int u = 0; u < 4; u++) {
        const int qch = tid + u * 256;
        const int m = qch >> 3, kc = qch & 7;
        const uint32_t sw = (uint32_t)(kc ^ (m & 7));
        a_soff[u] = (uint32_t)(m * 128) + (sw << 4);
        b_soff[u] = a_soff[u] + 16384u;
        a_g[u] = A  + (size_t)(m0 + m) * K + kc * 8;
        b_g[u] = Bw + (size_t)(n0 + m) * K + kc * 8;
    }

    const int arow = wm + (lane & 15);
    const uint32_t acadd = (uint32_t)(lane >> 4);
    const uint32_t aswz = (uint32_t)(arow & 7);
    const uint32_t aoff = (uint32_t)(arow * 128);
    const int brow = wn + ((lane >> 4) << 3) + (lane & 7);
    const uint32_t bcc = (uint32_t)((lane >> 3) & 1);
    const uint32_t bswz = (uint32_t)(brow & 7);
    const uint32_t boff = (uint32_t)(brow * 128) + 16384u;

    float acc[2][8][4];
    #pragma unroll
    for (int i = 0; i < 2; i++)
        #pragma unroll
        for (int j = 0; j < 8; j++)
            #pragma unroll
            for (int t = 0; t < 4; t++) acc[i][j][t] = 0.f;

    const int nk = K >> 6;
    #pragma unroll
    for (int s = 0; s < 2; s++) {
        const uint32_t sb = smbase + (uint32_t)s * GSTAGE;
        #pragma unroll
        for (int u = 0; u < 4; u++) {
            cp_async16(sb + a_soff[u], a_g[u] + s * 64);
            cp_async16(sb + b_soff[u], b_g[u] + s * 64);
        }
        cp_commit();
    }

    int sidx = 0;
    for (int kc = 0; kc < nk; kc++) {
        if (kc == nk - 1) cp_wait<0>(); else cp_wait<1>();
        __syncthreads();
        if (kc + 2 < nk) {
            const int s2 = (sidx + 2 >= 3) ? sidx - 1 : sidx + 2;
            const uint32_t sb = smbase + (uint32_t)s2 * GSTAGE;
            #pragma unroll
            for (int u = 0; u < 4; u++) {
                cp_async16(sb + a_soff[u], a_g[u] + (kc + 2) * 64);
                cp_async16(sb + b_soff[u], b_g[u] + (kc + 2) * 64);
            }
            cp_commit();
        }
        const uint32_t sb = smbase + (uint32_t)sidx * GSTAGE;
        #pragma unroll
        for (int ks = 0; ks < 4; ks++) {
            const uint32_t kc0 = (uint32_t)(2 * ks);
            uint32_t af[2][4];
            #pragma unroll
            for (int i = 0; i < 2; i++) {
                const uint32_t addr = sb + aoff + (uint32_t)(i * 2048) +
                                      (((kc0 + acadd) ^ aswz) << 4);
                ldsm4(af[i][0], af[i][1], af[i][2], af[i][3], addr);
            }
            #pragma unroll
            for (int jp = 0; jp < 4; jp++) {
                uint32_t b0, b1, b2, b3;
                const uint32_t addr = sb + boff + (uint32_t)(jp * 2048) +
                                      (((kc0 + bcc) ^ bswz) << 4);
                ldsm4(b0, b1, b2, b3, addr);
                #pragma unroll
                for (int i = 0; i < 2; i++) {
                    mma_f16(acc[i][2 * jp + 0], af[i], b0, b1);
                    mma_f16(acc[i][2 * jp + 1], af[i], b2, b3);
                }
            }
        }
        sidx = (sidx == 2) ? 0 : sidx + 1;
    }

    const int g = lane >> 2, tg = lane & 3;
    #pragma unroll
    for (int i = 0; i < 2; i++) {
        #pragma unroll
        for (int j = 0; j < 8; j++) {
            const int col = n0 + wn + j * 8 + tg * 2;
            const float2 b2 = *(const float2*)(bias + col);
            float sx = 1.f, sy = 1.f;
            if (EPI == 1) {
                if (col < 1024) {
                    const float c = 0.18033688f;  // log2(e)/sqrt(64)
                    sx = c * softplus_f(extra[col & 63]);
                    sy = c * softplus_f(extra[(col + 1) & 63]);
                }
            }
            #pragma unroll
            for (int h = 0; h < 2; h++) {
                const int row = m0 + wm + i * 16 + g + h * 8;
                float vx = acc[i][j][2 * h + 0] + b2.x;
                float vy = acc[i][j][2 * h + 1] + b2.y;
                if (EPI == 1) { vx *= sx; vy *= sy; }
                if (EPI == 2) {
                    const float2 r2 = *(const float2*)(extra + (size_t)row * N + col);
                    vx += r2.x; vy += r2.y;
                }
                if (EPI == 3) { vx = fmaxf(vx, 0.f); vy = fmaxf(vy, 0.f); }
                if (OUTH) {
                    *(__half2*)((__half*)Cv + (size_t)row * N + col) =
                        __floats2half2_rn(vx, vy);
                } else {
                    float2 o2; o2.x = vx; o2.y = vy;
                    *(float2*)((float*)Cv + (size_t)row * N + col) = o2;
                }
            }
        }
    }
}

// ---------------------------------------------------------------------------
// Flash attention v3: warp-local softmax (FA2 frag reuse), V via ldmatrix.trans
// (no transpose scatter), cp.async double-buffered K/V, longest-tile-first.
// ---------------------------------------------------------------------------
// byte offsets: Q 0..8K; K/V double buffers: K(b)=8192+b*16384, V(b)=16384+b*16384
#define FL_PQ_I 10240   // float idx (byte 40960): padq[64]
#define FL_PS_I 10304   // pads[2][64]
#define FL_M_I  10432   // m[2][64]
#define FL_L_I  10560   // l[2][64]
#define FLASH_SMEM_BYTES 42752

__global__ __launch_bounds__(256) void flash_kernel(
    const __half* __restrict__ qkv, const float* __restrict__ pad,
    __half* __restrict__ out)
{
    extern __shared__ float sf[];
    char* smc = (char*)sf;
    const uint32_t sbase = s2u(sf);
    const int tid = threadIdx.x;
    const int lane = tid & 31;
    const int wid = tid >> 5;
    const int wm = (wid & 3) << 4;
    const int sh = wid >> 2;
    const int g = lane >> 2, tg = lane & 3;
    const int t0 = ((TT >> 6) - 1 - blockIdx.x) << 6;   // longest first
    const int b = blockIdx.y >> 4, n = blockIdx.y & 15;

    const int arow = wm + (lane & 15);
    const uint32_t acadd = (uint32_t)(lane >> 4);
    const uint32_t aswz = (uint32_t)(arow & 7);
    const uint32_t qbase = sbase + (uint32_t)(arow * 128);
    const int brw = ((lane >> 4) << 3) + (lane & 7);
    const uint32_t bcc = (uint32_t)((lane >> 3) & 1);
    // V (trans) fragment addressing
    const int vkr = ((lane >> 3) & 1) * 8 + (lane & 7);
    const int vcc = lane >> 4;

    // loader indices
    const int lr = tid >> 2;
    const int lc0 = (tid & 3) << 1;

    // ---- load Q (swizzled 128B rows) via cp.async + padq
    {
        const __half* qp = qkv + (size_t)(b * TT + t0 + lr) * QKVN + n * 64;
        #pragma unroll
        for (int u = 0; u < 2; u++) {
            const int c = lc0 + u;
            cp_async16(sbase + (uint32_t)(lr * 128 + ((c ^ (lr & 7)) << 4)),
                       qp + c * 8);
        }
        if (tid < 64)
            cp_async4(sbase + (uint32_t)((FL_PQ_I + tid) * 4),
                      pad + b * TT + t0 + tid);
    }
    // ---- prefetch first K/V tile into buf 0
    {
        const __half* kp = qkv + (size_t)(b * TT + lr) * QKVN + 1024 + n * 64;
        const __half* vp = kp + 1024;
        #pragma unroll
        for (int u = 0; u < 2; u++) {
            const int c = lc0 + u;
            const uint32_t so = (uint32_t)(lr * 128 + ((c ^ (lr & 7)) << 4));
            cp_async16(sbase + 8192u + so, kp + c * 8);
            cp_async16(sbase + 16384u + so, vp + c * 8);
        }
        if (tid < 64)
            cp_async4(sbase + (uint32_t)((FL_PS_I + tid) * 4), pad + b * TT + tid);
    }
    cp_commit();

    float o[8][4];
    #pragma unroll
    for (int j = 0; j < 8; j++)
        #pragma unroll
        for (int c = 0; c < 4; c++) o[j][c] = 0.f;
    float m0 = -1e30f, m1 = -1e30f, l0 = 0.f, l1 = 0.f;
    const int r0l = wm + g, r1l = r0l + 8;

    const int nIter = (t0 >> 6) + 1;
    for (int it = 0; it < nIter; it++) {
        const int s0 = it << 6;
        const int buf = it & 1;
        const uint32_t kbuf = sbase + 8192u + (uint32_t)buf * 16384u;
        const uint32_t vbuf = kbuf + 8192u;

        cp_wait<0>();
        __syncthreads();

        // prefetch next tile into other buffer
        if (it + 1 < nIter) {
            const __half* kp = qkv + (size_t)(b * TT + s0 + 64 + lr) * QKVN + 1024 + n * 64;
            const __half* vp = kp + 1024;
            const uint32_t ob = sbase + 8192u + (uint32_t)(buf ^ 1) * 16384u;
            #pragma unroll
            for (int u = 0; u < 2; u++) {
                const int c = lc0 + u;
                const uint32_t so = (uint32_t)(lr * 128 + ((c ^ (lr & 7)) << 4));
                cp_async16(ob + so, kp + c * 8);
                cp_async16(ob + 8192u + so, vp + c * 8);
            }
            if (tid < 64)
                cp_async4(sbase + (uint32_t)((FL_PS_I + (buf ^ 1) * 64 + tid) * 4),
                          pad + b * TT + s0 + 64 + tid);
            cp_commit();
        }

        // ---- S = Q K^T for warp's 16 rows x 32 s-cols
        float sacc[4][4];
        #pragma unroll
        for (int j = 0; j < 4; j++)
            #pragma unroll
            for (int c = 0; c < 4; c++) sacc[j][c] = 0.f;
        #pragma unroll
        for (int ks = 0; ks < 4; ks++) {
            const uint32_t kc0 = (uint32_t)(2 * ks);
            uint32_t af[4];
            ldsm4(af[0], af[1], af[2], af[3],
                  qbase + (((kc0 + acadd) ^ aswz) << 4));
            #pragma unroll
            for (int jp = 0; jp < 2; jp++) {
                const int brow = sh * 32 + jp * 16 + brw;
                uint32_t b0, b1, b2, b3;
                ldsm4(b0, b1, b2, b3,
                      kbuf + (uint32_t)(brow * 128) +
                      (((kc0 + bcc) ^ (uint32_t)(brow & 7)) << 4));
                mma_f16(sacc[2 * jp + 0], af, b0, b1);
                mma_f16(sacc[2 * jp + 1], af, b2, b3);
            }
        }

        // ---- mask (causal + padding)
        const float pq0 = sf[FL_PQ_I + r0l], pq1 = sf[FL_PQ_I + r1l];
        const int rg0 = t0 + r0l, rg1 = t0 + r1l;
        const int psb = FL_PS_I + buf * 64;
        #pragma unroll
        for (int j = 0; j < 4; j++) {
            const int cl = sh * 32 + j * 8 + 2 * tg;
            const int cg = s0 + cl;
            const float ps0 = sf[psb + cl], ps1 = sf[psb + cl + 1];
            if (!(pq0 != 0.f && ps0 != 0.f && cg     <= rg0)) sacc[j][0] = -1e9f;
            if (!(pq0 != 0.f && ps1 != 0.f && cg + 1 <= rg0)) sacc[j][1] = -1e9f;
            if (!(pq1 != 0.f && ps0 != 0.f && cg     <= rg1)) sacc[j][2] = -1e9f;
            if (!(pq1 != 0.f && ps1 != 0.f && cg + 1 <= rg1)) sacc[j][3] = -1e9f;
        }

        // ---- warp-local online softmax
        float rm0 = -1e30f, rm1 = -1e30f;
        #pragma unroll
        for (int j = 0; j < 4; j++) {
            rm0 = fmaxf(rm0, fmaxf(sacc[j][0], sacc[j][1]));
            rm1 = fmaxf(rm1, fmaxf(sacc[j][2], sacc[j][3]));
        }
        rm0 = fmaxf(rm0, __shfl_xor_sync(0xffffffffu, rm0, 1));
        rm0 = fmaxf(rm0, __shfl_xor_sync(0xffffffffu, rm0, 2));
        rm1 = fmaxf(rm1, __shfl_xor_sync(0xffffffffu, rm1, 1));
        rm1 = fmaxf(rm1, __shfl_xor_sync(0xffffffffu, rm1, 2));
        const float mn0 = fmaxf(m0, rm0), mn1 = fmaxf(m1, rm1);
        const float alpha0 = __expf(m0 - mn0), alpha1 = __expf(m1 - mn1);
        m0 = mn0; m1 = mn1;
        float rs0 = 0.f, rs1 = 0.f;
        #pragma unroll
        for (int j = 0; j < 4; j++) {
            sacc[j][0] = __expf(sacc[j][0] - mn0);
            sacc[j][1] = __expf(sacc[j][1] - mn0);
            sacc[j][2] = __expf(sacc[j][2] - mn1);
            sacc[j][3] = __expf(sacc[j][3] - mn1);
            rs0 += sacc[j][0] + sacc[j][1];
            rs1 += sacc[j][2] + sacc[j][3];
        }
        rs0 += __shfl_xor_sync(0xffffffffu, rs0, 1);
        rs0 += __shfl_xor_sync(0xffffffffu, rs0, 2);
        rs1 += __shfl_xor_sync(0xffffffffu, rs1, 1);
        rs1 += __shfl_xor_sync(0xffffffffu, rs1, 2);
        l0 = l0 * alpha0 + rs0;
        l1 = l1 * alpha1 + rs1;
        #pragma unroll
        for (int j = 0; j < 8; j++) {
            o[j][0] *= alpha0; o[j][1] *= alpha0;
            o[j][2] *= alpha1; o[j][3] *= alpha1;
        }

        // ---- pack P into A-fragments
        uint32_t pa[2][4];
        #pragma unroll
        for (int ks = 0; ks < 2; ks++) {
            pa[ks][0] = pkh2(sacc[2 * ks][0],     sacc[2 * ks][1]);
            pa[ks][1] = pkh2(sacc[2 * ks][2],     sacc[2 * ks][3]);
            pa[ks][2] = pkh2(sacc[2 * ks + 1][0], sacc[2 * ks + 1][1]);
            pa[ks][3] = pkh2(sacc[2 * ks + 1][2], sacc[2 * ks + 1][3]);
        }

        // ---- O += P V (V B-fragments via ldmatrix.trans from [s][h] rows)
        #pragma unroll
        for (int ks = 0; ks < 2; ks++) {
            const int kr = sh * 32 + ks * 16 + vkr;
            #pragma unroll
            for (int jp = 0; jp < 4; jp++) {
                const int c = jp * 2 + vcc;
                uint32_t b0, b1, b2, b3;
                ldsm4t(b0, b1, b2, b3,
                       vbuf + (uint32_t)(kr * 128) +
                       (((uint32_t)c ^ (uint32_t)(kr & 7)) << 4));
                mma_f16(o[2 * jp + 0], pa[ks], b0, b1);
                mma_f16(o[2 * jp + 1], pa[ks], b2, b3);
            }
        }
    }

    // ---- merge the two s-halves
    __syncthreads();
    if (tg == 0) {
        sf[FL_M_I + sh * 64 + r0l] = m0;
        sf[FL_M_I + sh * 64 + r1l] = m1;
        sf[FL_L_I + sh * 64 + r0l] = l0;
        sf[FL_L_I + sh * 64 + r1l] = l1;
    }
    __syncthreads();
    const float mo0 = sf[FL_M_I + (1 - sh) * 64 + r0l];
    const float mo1 = sf[FL_M_I + (1 - sh) * 64 + r1l];
    const float mf0 = fmaxf(m0, mo0), mf1 = fmaxf(m1, mo1);
    const float f0 = __expf(m0 - mf0), f1 = __expf(m1 - mf1);
    float* stg = sf + sh * 4096;   // staging reuses Q/K0/V0/K1 region
    #pragma unroll
    for (int j = 0; j < 8; j++) {
        const int col = j * 8 + 2 * tg;
        stg[r0l * 64 + col + 0] = o[j][0] * f0;
        stg[r0l * 64 + col + 1] = o[j][1] * f0;
        stg[r1l * 64 + col + 0] = o[j][2] * f1;
        stg[r1l * 64 + col + 1] = o[j][3] * f1;
    }
    __syncthreads();
    if (sh == 0) {
        const float lo0 = sf[FL_L_I + 64 + r0l], lo1 = sf[FL_L_I + 64 + r1l];
        const float inv0 = 1.f / (l0 * f0 + lo0 * __expf(mo0 - mf0));
        const float inv1 = 1.f / (l1 * f1 + lo1 * __expf(mo1 - mf1));
        const size_t row0 = (size_t)(b * TT + t0 + r0l);
        const size_t row1 = (size_t)(b * TT + t0 + r1l);
        #pragma unroll
        for (int j = 0; j < 8; j++) {
            const int col = j * 8 + 2 * tg;
            const float v00 = (sf[r0l * 64 + col + 0] + sf[4096 + r0l * 64 + col + 0]) * inv0;
            const float v01 = (sf[r0l * 64 + col + 1] + sf[4096 + r0l * 64 + col + 1]) * inv0;
            const float v10 = (sf[r1l * 64 + col + 0] + sf[4096 + r1l * 64 + col + 0]) * inv1;
            const float v11 = (sf[r1l * 64 + col + 1] + sf[4096 + r1l * 64 + col + 1]) * inv1;
            *(__half2*)(out + row0 * DD + n * 64 + col) = __floats2half2_rn(v00, v01);
            *(__half2*)(out + row1 * DD + n * 64 + col) = __floats2half2_rn(v10, v11);
        }
    }
}

// ---------------------------------------------------------------------------
// Host launch
// ---------------------------------------------------------------------------
extern "C" void kernel_launch(void* const* d_in, const int* in_sizes, int n_in,
                              void* d_out, int out_size)
{
    (void)in_sizes; (void)n_in; (void)out_size;
    const float* x         = (const float*)d_in[0];
    const float* padding   = (const float*)d_in[1];
    const float* rms_scale = (const float*)d_in[2];
    const float* pds       = (const float*)d_in[3];
    const float* wq        = (const float*)d_in[4];
    const float* bq        = (const float*)d_in[5];
    const float* wk        = (const float*)d_in[6];
    const float* bk        = (const float*)d_in[7];
    const float* wv        = (const float*)d_in[8];
    const float* bv        = (const float*)d_in[9];
    const float* wo        = (const float*)d_in[10];
    const float* bo        = (const float*)d_in[11];
    const float* ln_gamma  = (const float*)d_in[12];
    const float* ln_beta   = (const float*)d_in[13];
    const float* w1        = (const float*)d_in[14];
    const float* b1        = (const float*)d_in[15];
    const float* w2        = (const float*)d_in[16];
    const float* b2        = (const float*)d_in[17];
    float* out = (float*)d_out;

    __half *xn, *qkv, *ao, *hn, *h1, *wqkvt, *wot, *w1t, *w2t;
    float *ar, *bqkv;
    cudaGetSymbolAddress((void**)&xn,  g_xn);
    cudaGetSymbolAddress((void**)&qkv, g_qkv);
    cudaGetSymbolAddress((void**)&ao,  g_ao);
    cudaGetSymbolAddress((void**)&ar,  g_ar);
    cudaGetSymbolAddress((void**)&hn,  g_hn);
    cudaGetSymbolAddress((void**)&h1,  g_h1);
    cudaGetSymbolAddress((void**)&wqkvt, g_wqkvt);
    cudaGetSymbolAddress((void**)&bqkv,  g_bqkv);
    cudaGetSymbolAddress((void**)&wot, g_wot);
    cudaGetSymbolAddress((void**)&w1t, g_w1t);
    cudaGetSymbolAddress((void**)&w2t, g_w2t);

    static int attr_done = 0;
    if (!attr_done) {
        cudaFuncSetAttribute(flash_kernel,
            cudaFuncAttributeMaxDynamicSharedMemorySize, FLASH_SMEM_BYTES);
        cudaFuncSetAttribute(mma_gemm_kernel<1, true>,
            cudaFuncAttributeMaxDynamicSharedMemorySize, GEMM_SMEM_BYTES);
        cudaFuncSetAttribute(mma_gemm_kernel<2, false>,
            cudaFuncAttributeMaxDynamicSharedMemorySize, GEMM_SMEM_BYTES);
        cudaFuncSetAttribute(mma_gemm_kernel<3, true>,
            cudaFuncAttributeMaxDynamicSharedMemorySize, GEMM_SMEM_BYTES);
        attr_done = 1;
    }

    // 0. Fused weight prep
    prep_kernel<<<PREP_BLOCKS, 256>>>(wq, wk, wv, w1, w2, wo, bq, bk, bv,
                                      wqkvt, w1t, w2t, wot, bqkv);

    // 1. RMSNorm
    rmsnorm_kernel<<<MM, 256>>>(x, rms_scale, xn);

    // 2. Fused QKV projection
    dim3 gQKV(QKVN / 128, MM / 128);
    mma_gemm_kernel<1, true><<<gQKV, 256, GEMM_SMEM_BYTES>>>(
        xn, wqkvt, bqkv, pds, qkv, MM, QKVN, DD);

    // 3. Flash attention v3
    flash_kernel<<<dim3(TT / 64, BB * NHEAD), 256, FLASH_SMEM_BYTES>>>(
        qkv, padding, ao);

    // 4. Output projection + bias + residual(x)
    dim3 gD(DD / 128, MM / 128);
    mma_gemm_kernel<2, false><<<gD, 256, GEMM_SMEM_BYTES>>>(
        ao, wot, bo, x, ar, MM, DD, DD);

    // 5. LayerNorm
    layernorm_kernel<<<MM, 256>>>(ar, ln_gamma, ln_beta, hn);

    // 6. FFN up + ReLU
    dim3 gF(FF / 128, MM / 128);
    mma_gemm_kernel<3, true><<<gF, 256, GEMM_SMEM_BYTES>>>(
        hn, w1t, b1, nullptr, h1, MM, FF, DD);

    // 7. FFN down + bias + residual(ar) -> output
    mma_gemm_kernel<2, false><<<gD, 256, GEMM_SMEM_BYTES>>>(
        h1, w2t, b2, ar, out, MM, DD, FF);
}

// round 9
// speedup vs baseline: 7.9471x; 1.0280x over previous
#include <cuda_runtime.h>
#include <cuda_fp16.h>
#include <cstdint>
#include <math.h>

// Problem constants
#define BB 8
#define TT 1024
#define DD 1024
#define NHEAD 16
#define HDIM 64
#define FF 4096
#define MM (BB * TT)   // 8192
#define QKVN 3072

// ---------------------------------------------------------------------------
// Scratch (device globals)
// ---------------------------------------------------------------------------
__device__ __half g_xn [MM * DD];
__device__ __half g_qkv[MM * QKVN];
__device__ __half g_ao [MM * DD];
__device__ float  g_ar [MM * DD];
__device__ __half g_hn [MM * DD];
__device__ __half g_h1 [MM * FF];
__device__ __half g_wqkvt[QKVN * DD];   // [3072][1024] K-major (q|k|v)
__device__ float  g_bqkv [QKVN];
__device__ __half g_wot[DD * DD];
__device__ __half g_w1t[FF * DD];
__device__ __half g_w2t[DD * FF];

// ---------------------------------------------------------------------------
// Helpers
// ---------------------------------------------------------------------------
__device__ __forceinline__ uint32_t s2u(const void* p) {
    uint32_t a;
    asm("{ .reg .u64 t; cvta.to.shared.u64 t, %1; cvt.u32.u64 %0, t; }"
        : "=r"(a) : "l"(p));
    return a;
}

__device__ __forceinline__ void cp_async16(uint32_t saddr, const void* gaddr) {
    asm volatile("cp.async.cg.shared.global [%0], [%1], 16;"
                 :: "r"(saddr), "l"(gaddr));
}
__device__ __forceinline__ void cp_async4(uint32_t saddr, const void* gaddr) {
    asm volatile("cp.async.ca.shared.global [%0], [%1], 4;"
                 :: "r"(saddr), "l"(gaddr));
}
__device__ __forceinline__ void cp_commit() {
    asm volatile("cp.async.commit_group;");
}
template <int N>
__device__ __forceinline__ void cp_wait() {
    asm volatile("cp.async.wait_group %0;" :: "n"(N));
}

__device__ __forceinline__ void ldsm4(uint32_t& r0, uint32_t& r1,
                                      uint32_t& r2, uint32_t& r3, uint32_t addr) {
    asm volatile("ldmatrix.sync.aligned.m8n8.x4.shared.b16 {%0,%1,%2,%3}, [%4];"
                 : "=r"(r0), "=r"(r1), "=r"(r2), "=r"(r3) : "r"(addr));
}
__device__ __forceinline__ void ldsm4t(uint32_t& r0, uint32_t& r1,
                                       uint32_t& r2, uint32_t& r3, uint32_t addr) {
    asm volatile("ldmatrix.sync.aligned.m8n8.x4.trans.shared.b16 {%0,%1,%2,%3}, [%4];"
                 : "=r"(r0), "=r"(r1), "=r"(r2), "=r"(r3) : "r"(addr));
}

// fp16 MMA m16n8k16, fp32 accumulate
__device__ __forceinline__ void mma_f16(float* c, const uint32_t* a,
                                        uint32_t b0, uint32_t b1) {
    asm volatile(
        "mma.sync.aligned.m16n8k16.row.col.f32.f16.f16.f32 "
        "{%0,%1,%2,%3}, {%4,%5,%6,%7}, {%8,%9}, {%0,%1,%2,%3};"
        : "+f"(c[0]), "+f"(c[1]), "+f"(c[2]), "+f"(c[3])
        : "r"(a[0]), "r"(a[1]), "r"(a[2]), "r"(a[3]), "r"(b0), "r"(b1));
}

__device__ __forceinline__ uint32_t pkh2(float a, float b) {
    const __half2 h = __floats2half2_rn(a, b);
    return *(const uint32_t*)&h;
}

// ---------------------------------------------------------------------------
// Fused prep kernel
// ---------------------------------------------------------------------------
__device__ __forceinline__ void transpose_tile(
    const float* __restrict__ in, __half* __restrict__ out,
    int bx, int by, int C, int R, float (*t)[33], int tid)
{
    const int txx = tid & 31, tyy = tid >> 5;
    #pragma unroll
    for (int j = 0; j < 32; j += 8)
        t[tyy + j][txx] = in[(size_t)(by + tyy + j) * C + bx + txx];
    __syncthreads();
    #pragma unroll
    for (int j = 0; j < 32; j += 8)
        out[(size_t)(bx + tyy + j) * R + by + txx] = __float2half_rn(t[txx][tyy + j]);
}

#define PREP_BLOCKS 12300

__global__ __launch_bounds__(256) void prep_kernel(
    const float* __restrict__ wq, const float* __restrict__ wk,
    const float* __restrict__ wv, const float* __restrict__ w1,
    const float* __restrict__ w2, const float* __restrict__ wo,
    const float* __restrict__ bq, const float* __restrict__ bk,
    const float* __restrict__ bv,
    __half* __restrict__ wqkvt, __half* __restrict__ w1t,
    __half* __restrict__ w2t, __half* __restrict__ wot,
    float* __restrict__ bqkv)
{
    __shared__ float t[32][33];
    const int id = blockIdx.x;
    const int tid = threadIdx.x;

    if (id < 3072) {
        const int w = id >> 10, tt = id & 1023;
        const float* in = (w == 0) ? wq : (w == 1) ? wk : wv;
        __half* outp = wqkvt + (size_t)w * 1024 * DD;
        transpose_tile(in, outp, (tt & 31) << 5, (tt >> 5) << 5, DD, DD, t, tid);
    } else if (id < 7168) {
        const int tt = id - 3072;
        transpose_tile(w1, w1t, (tt & 127) << 5, (tt >> 7) << 5, FF, DD, t, tid);
    } else if (id < 11264) {
        const int tt = id - 7168;
        transpose_tile(w2, w2t, (tt & 31) << 5, (tt >> 5) << 5, DD, FF, t, tid);
    } else if (id < 12288) {
        const int i = (id - 11264) * 1024 + tid * 4;
        const float4 v = *(const float4*)(wo + i);
        __half2* o2 = (__half2*)(wot + i);
        o2[0] = __floats2half2_rn(v.x, v.y);
        o2[1] = __floats2half2_rn(v.z, v.w);
    } else {
        const int i = (id - 12288) * 256 + tid;
        if (i < QKVN)
            bqkv[i] = (i < 1024) ? bq[i] : (i < 2048) ? bk[i - 1024] : bv[i - 2048];
    }
}

// ---------------------------------------------------------------------------
// RMSNorm / LayerNorm (half outputs)
// ---------------------------------------------------------------------------
__global__ __launch_bounds__(256) void rmsnorm_kernel(
    const float* __restrict__ x, const float* __restrict__ scale,
    __half* __restrict__ out)
{
    const int row = blockIdx.x;
    const int tid = threadIdx.x;
    const float4 v = ((const float4*)(x + (size_t)row * DD))[tid];
    float ss = v.x * v.x + v.y * v.y + v.z * v.z + v.w * v.w;
    #pragma unroll
    for (int m = 16; m; m >>= 1) ss += __shfl_xor_sync(0xffffffffu, ss, m);
    __shared__ float sred[8];
    if ((tid & 31) == 0) sred[tid >> 5] = ss;
    __syncthreads();
    float tot = 0.f;
    #pragma unroll
    for (int i = 0; i < 8; i++) tot += sred[i];
    const float r = rsqrtf(tot * (1.0f / DD) + 1e-6f);
    const float4 s4 = ((const float4*)scale)[tid];
    __half2* o2 = (__half2*)(out + (size_t)row * DD) + tid * 2;
    o2[0] = __floats2half2_rn(v.x * r * s4.x, v.y * r * s4.y);
    o2[1] = __floats2half2_rn(v.z * r * s4.z, v.w * r * s4.w);
}

__global__ __launch_bounds__(256) void layernorm_kernel(
    const float* __restrict__ x, const float* __restrict__ gamma,
    const float* __restrict__ beta, __half* __restrict__ out)
{
    const int row = blockIdx.x;
    const int tid = threadIdx.x;
    const float4 v = ((const float4*)(x + (size_t)row * DD))[tid];
    float s  = v.x + v.y + v.z + v.w;
    float ss = v.x * v.x + v.y * v.y + v.z * v.z + v.w * v.w;
    #pragma unroll
    for (int m = 16; m; m >>= 1) {
        s  += __shfl_xor_sync(0xffffffffu, s,  m);
        ss += __shfl_xor_sync(0xffffffffu, ss, m);
    }
    __shared__ float sr1[8], sr2[8];
    if ((tid & 31) == 0) { sr1[tid >> 5] = s; sr2[tid >> 5] = ss; }
    __syncthreads();
    float S = 0.f, SS = 0.f;
    #pragma unroll
    for (int i = 0; i < 8; i++) { S += sr1[i]; SS += sr2[i]; }
    const float mean = S * (1.0f / DD);
    const float var  = SS * (1.0f / DD) - mean * mean;
    const float r = rsqrtf(var + 1e-5f);
    const float4 g4 = ((const float4*)gamma)[tid];
    const float4 b4 = ((const float4*)beta)[tid];
    __half2* o2 = (__half2*)(out + (size_t)row * DD) + tid * 2;
    o2[0] = __floats2half2_rn((v.x - mean) * r * g4.x + b4.x,
                              (v.y - mean) * r * g4.y + b4.y);
    o2[1] = __floats2half2_rn((v.z - mean) * r * g4.z + b4.z,
                              (v.w - mean) * r * g4.w + b4.w);
}

// ---------------------------------------------------------------------------
// fp16 mma.sync GEMM (unchanged — proven)
// ---------------------------------------------------------------------------
__device__ __forceinline__ float softplus_f(float x) {
    return (x > 15.f) ? x : log1pf(__expf(x));
}

#define GSTAGE 32768
#define GEMM_SMEM_BYTES (3 * GSTAGE)

template <int EPI, bool OUTH>
__global__ __launch_bounds__(256, 2) void mma_gemm_kernel(
    const __half* __restrict__ A, const __half* __restrict__ Bw,
    const float* __restrict__ bias, const float* __restrict__ extra,
    void* __restrict__ Cv, int M, int N, int K)
{
    extern __shared__ char gsm[];
    const uint32_t smbase = s2u(gsm);
    const int tid = threadIdx.x;
    const int lane = tid & 31;
    const int wid = tid >> 5;
    const int m0 = blockIdx.y << 7;
    const int n0 = blockIdx.x << 7;
    const int wm = (wid & 3) << 5;
    const int wn = (wid >> 2) << 6;

    uint32_t a_soff[4], b_soff[4];
    const __half* a_g[4]; const __half* b_g[4];
    #pragma unroll
    for (int u = 0; u < 4; u++) {
        const int qch = tid + u * 256;
        const int m = qch >> 3, kc = qch & 7;
        const uint32_t sw = (uint32_t)(kc ^ (m & 7));
        a_soff[u] = (uint32_t)(m * 128) + (sw << 4);
        b_soff[u] = a_soff[u] + 16384u;
        a_g[u] = A  + (size_t)(m0 + m) * K + kc * 8;
        b_g[u] = Bw + (size_t)(n0 + m) * K + kc * 8;
    }

    const int arow = wm + (lane & 15);
    const uint32_t acadd = (uint32_t)(lane >> 4);
    const uint32_t aswz = (uint32_t)(arow & 7);
    const uint32_t aoff = (uint32_t)(arow * 128);
    const int brow = wn + ((lane >> 4) << 3) + (lane & 7);
    const uint32_t bcc = (uint32_t)((lane >> 3) & 1);
    const uint32_t bswz = (uint32_t)(brow & 7);
    const uint32_t boff = (uint32_t)(brow * 128) + 16384u;

    float acc[2][8][4];
    #pragma unroll
    for (int i = 0; i < 2; i++)
        #pragma unroll
        for (int j = 0; j < 8; j++)
            #pragma unroll
            for (int t = 0; t < 4; t++) acc[i][j][t] = 0.f;

    const int nk = K >> 6;
    #pragma unroll
    for (int s = 0; s < 2; s++) {
        const uint32_t sb = smbase + (uint32_t)s * GSTAGE;
        #pragma unroll
        for (int u = 0; u < 4; u++) {
            cp_async16(sb + a_soff[u], a_g[u] + s * 64);
            cp_async16(sb + b_soff[u], b_g[u] + s * 64);
        }
        cp_commit();
    }

    int sidx = 0;
    for (int kc = 0; kc < nk; kc++) {
        if (kc == nk - 1) cp_wait<0>(); else cp_wait<1>();
        __syncthreads();
        if (kc + 2 < nk) {
            const int s2 = (sidx + 2 >= 3) ? sidx - 1 : sidx + 2;
            const uint32_t sb = smbase + (uint32_t)s2 * GSTAGE;
            #pragma unroll
            for (int u = 0; u < 4; u++) {
                cp_async16(sb + a_soff[u], a_g[u] + (kc + 2) * 64);
                cp_async16(sb + b_soff[u], b_g[u] + (kc + 2) * 64);
            }
            cp_commit();
        }
        const uint32_t sb = smbase + (uint32_t)sidx * GSTAGE;
        #pragma unroll
        for (int ks = 0; ks < 4; ks++) {
            const uint32_t kc0 = (uint32_t)(2 * ks);
            uint32_t af[2][4];
            #pragma unroll
            for (int i = 0; i < 2; i++) {
                const uint32_t addr = sb + aoff + (uint32_t)(i * 2048) +
                                      (((kc0 + acadd) ^ aswz) << 4);
                ldsm4(af[i][0], af[i][1], af[i][2], af[i][3], addr);
            }
            #pragma unroll
            for (int jp = 0; jp < 4; jp++) {
                uint32_t b0, b1, b2, b3;
                const uint32_t addr = sb + boff + (uint32_t)(jp * 2048) +
                                      (((kc0 + bcc) ^ bswz) << 4);
                ldsm4(b0, b1, b2, b3, addr);
                #pragma unroll
                for (int i = 0; i < 2; i++) {
                    mma_f16(acc[i][2 * jp + 0], af[i], b0, b1);
                    mma_f16(acc[i][2 * jp + 1], af[i], b2, b3);
                }
            }
        }
        sidx = (sidx == 2) ? 0 : sidx + 1;
    }

    const int g = lane >> 2, tg = lane & 3;
    #pragma unroll
    for (int i = 0; i < 2; i++) {
        #pragma unroll
        for (int j = 0; j < 8; j++) {
            const int col = n0 + wn + j * 8 + tg * 2;
            const float2 b2 = *(const float2*)(bias + col);
            float sx = 1.f, sy = 1.f;
            if (EPI == 1) {
                if (col < 1024) {
                    const float c = 0.18033688f;  // log2(e)/sqrt(64)
                    sx = c * softplus_f(extra[col & 63]);
                    sy = c * softplus_f(extra[(col + 1) & 63]);
                }
            }
            #pragma unroll
            for (int h = 0; h < 2; h++) {
                const int row = m0 + wm + i * 16 + g + h * 8;
                float vx = acc[i][j][2 * h + 0] + b2.x;
                float vy = acc[i][j][2 * h + 1] + b2.y;
                if (EPI == 1) { vx *= sx; vy *= sy; }
                if (EPI == 2) {
                    const float2 r2 = *(const float2*)(extra + (size_t)row * N + col);
                    vx += r2.x; vy += r2.y;
                }
                if (EPI == 3) { vx = fmaxf(vx, 0.f); vy = fmaxf(vy, 0.f); }
                if (OUTH) {
                    *(__half2*)((__half*)Cv + (size_t)row * N + col) =
                        __floats2half2_rn(vx, vy);
                } else {
                    float2 o2; o2.x = vx; o2.y = vy;
                    *(float2*)((float*)Cv + (size_t)row * N + col) = o2;
                }
            }
        }
    }
}

// ---------------------------------------------------------------------------
// Flash attention v4: 128-row Q tile, warp = 16 rows x full 64 s-cols.
// Warp-local softmax over complete rows (no end merge), V via ldmatrix.trans,
// cp.async double-buffered K/V, longest-tile-first, causal-check elision.
// ---------------------------------------------------------------------------
// byte layout: Q 0..16K; K(buf)=16384+buf*16384 (8K), V(buf)=K(buf)+8192 (8K)
#define FL_PQ_I 12288   // float idx (byte 49152): padq[128]
#define FL_PS_I 12416   // pads[2][64]
#define FLASH_SMEM_BYTES 50176

__global__ __launch_bounds__(256) void flash_kernel(
    const __half* __restrict__ qkv, const float* __restrict__ pad,
    __half* __restrict__ out)
{
    extern __shared__ float sf[];
    const uint32_t sbase = s2u(sf);
    const int tid = threadIdx.x;
    const int lane = tid & 31;
    const int wid = tid >> 5;
    const int wm = wid << 4;                      // warp rows 0..112
    const int g = lane >> 2, tg = lane & 3;
    const int t0 = (7 - blockIdx.x) << 7;         // longest first, 128-row tiles
    const int b = blockIdx.y >> 4, n = blockIdx.y & 15;

    const int arow = wm + (lane & 15);
    const uint32_t acadd = (uint32_t)(lane >> 4);
    const uint32_t aswz = (uint32_t)(arow & 7);
    const uint32_t qbase = sbase + (uint32_t)(arow * 128);
    const int brw = ((lane >> 4) << 3) + (lane & 7);
    const uint32_t bcc = (uint32_t)((lane >> 3) & 1);
    const int vkr = ((lane >> 3) & 1) * 8 + (lane & 7);
    const int vcc = lane >> 4;

    // ---- load Q tile (128 rows x 128B, swizzled) + padq
    {
        const int r = tid >> 1;
        const int c0 = (tid & 1) << 2;
        const __half* qp = qkv + (size_t)(b * TT + t0 + r) * QKVN + n * 64;
        #pragma unroll
        for (int u = 0; u < 4; u++) {
            const int c = c0 + u;
            cp_async16(sbase + (uint32_t)(r * 128 + ((c ^ (r & 7)) << 4)),
                       qp + c * 8);
        }
        if (tid < 128)
            cp_async4(sbase + (uint32_t)((FL_PQ_I + tid) * 4),
                      pad + b * TT + t0 + tid);
    }
    // ---- prefetch first K/V tile into buf 0
    {
        const int lr = tid >> 2;
        const int lc0 = (tid & 3) << 1;
        const __half* kp = qkv + (size_t)(b * TT + lr) * QKVN + 1024 + n * 64;
        const __half* vp = kp + 1024;
        #pragma unroll
        for (int u = 0; u < 2; u++) {
            const int c = lc0 + u;
            const uint32_t so = (uint32_t)(lr * 128 + ((c ^ (lr & 7)) << 4));
            cp_async16(sbase + 16384u + so, kp + c * 8);
            cp_async16(sbase + 24576u + so, vp + c * 8);
        }
        if (tid < 64)
            cp_async4(sbase + (uint32_t)((FL_PS_I + tid) * 4), pad + b * TT + tid);
    }
    cp_commit();

    float o[8][4];
    #pragma unroll
    for (int j = 0; j < 8; j++)
        #pragma unroll
        for (int c = 0; c < 4; c++) o[j][c] = 0.f;
    float m0 = -1e30f, m1 = -1e30f, l0 = 0.f, l1 = 0.f;
    const int r0l = wm + g, r1l = r0l + 8;

    const int nIter = (t0 >> 6) + 2;
    for (int it = 0; it < nIter; it++) {
        const int s0 = it << 6;
        const int buf = it & 1;
        const uint32_t kbuf = sbase + 16384u + (uint32_t)buf * 16384u;
        const uint32_t vbuf = kbuf + 8192u;

        cp_wait<0>();
        __syncthreads();

        // prefetch next K/V tile into the other buffer
        if (it + 1 < nIter) {
            const int lr = tid >> 2;
            const int lc0 = (tid & 3) << 1;
            const __half* kp = qkv + (size_t)(b * TT + s0 + 64 + lr) * QKVN + 1024 + n * 64;
            const __half* vp = kp + 1024;
            const uint32_t ob = sbase + 16384u + (uint32_t)(buf ^ 1) * 16384u;
            #pragma unroll
            for (int u = 0; u < 2; u++) {
                const int c = lc0 + u;
                const uint32_t so = (uint32_t)(lr * 128 + ((c ^ (lr & 7)) << 4));
                cp_async16(ob + so, kp + c * 8);
                cp_async16(ob + 8192u + so, vp + c * 8);
            }
            if (tid < 64)
                cp_async4(sbase + (uint32_t)((FL_PS_I + (buf ^ 1) * 64 + tid) * 4),
                          pad + b * TT + s0 + 64 + tid);
            cp_commit();
        }

        // ---- S = Q K^T: warp's 16 rows x 64 s-cols
        float sacc[8][4];
        #pragma unroll
        for (int j = 0; j < 8; j++)
            #pragma unroll
            for (int c = 0; c < 4; c++) sacc[j][c] = 0.f;
        #pragma unroll
        for (int ks = 0; ks < 4; ks++) {
            const uint32_t kc0 = (uint32_t)(2 * ks);
            uint32_t af[4];
            ldsm4(af[0], af[1], af[2], af[3],
                  qbase + (((kc0 + acadd) ^ aswz) << 4));
            #pragma unroll
            for (int jp = 0; jp < 4; jp++) {
                const int brow = jp * 16 + brw;
                uint32_t b0, b1, b2, b3;
                ldsm4(b0, b1, b2, b3,
                      kbuf + (uint32_t)(brow * 128) +
                      (((kc0 + bcc) ^ (uint32_t)(brow & 7)) << 4));
                mma_f16(sacc[2 * jp + 0], af, b0, b1);
                mma_f16(sacc[2 * jp + 1], af, b2, b3);
            }
        }

        // ---- mask (padding always; causal only when tile crosses diagonal)
        const float pq0 = sf[FL_PQ_I + r0l], pq1 = sf[FL_PQ_I + r1l];
        const int rg0 = t0 + r0l, rg1 = t0 + r1l;
        const int psb = FL_PS_I + buf * 64;
        const bool nc = (s0 + 64 <= t0 + wm);  // no causal check needed
        #pragma unroll
        for (int j = 0; j < 8; j++) {
            const int cl = j * 8 + 2 * tg;
            const int cg = s0 + cl;
            const float ps0 = sf[psb + cl], ps1 = sf[psb + cl + 1];
            if (!(pq0 != 0.f && ps0 != 0.f && (nc || cg     <= rg0))) sacc[j][0] = -1e9f;
            if (!(pq0 != 0.f && ps1 != 0.f && (nc || cg + 1 <= rg0))) sacc[j][1] = -1e9f;
            if (!(pq1 != 0.f && ps0 != 0.f && (nc || cg     <= rg1))) sacc[j][2] = -1e9f;
            if (!(pq1 != 0.f && ps1 != 0.f && (nc || cg + 1 <= rg1))) sacc[j][3] = -1e9f;
        }

        // ---- warp-local online softmax (rows complete: only tg lanes share)
        float rm0 = -1e30f, rm1 = -1e30f;
        #pragma unroll
        for (int j = 0; j < 8; j++) {
            rm0 = fmaxf(rm0, fmaxf(sacc[j][0], sacc[j][1]));
            rm1 = fmaxf(rm1, fmaxf(sacc[j][2], sacc[j][3]));
        }
        rm0 = fmaxf(rm0, __shfl_xor_sync(0xffffffffu, rm0, 1));
        rm0 = fmaxf(rm0, __shfl_xor_sync(0xffffffffu, rm0, 2));
        rm1 = fmaxf(rm1, __shfl_xor_sync(0xffffffffu, rm1, 1));
        rm1 = fmaxf(rm1, __shfl_xor_sync(0xffffffffu, rm1, 2));
        const float mn0 = fmaxf(m0, rm0), mn1 = fmaxf(m1, rm1);
        const float alpha0 = __expf(m0 - mn0), alpha1 = __expf(m1 - mn1);
        m0 = mn0; m1 = mn1;
        float rs0 = 0.f, rs1 = 0.f;
        #pragma unroll
        for (int j = 0; j < 8; j++) {
            sacc[j][0] = __expf(sacc[j][0] - mn0);
            sacc[j][1] = __expf(sacc[j][1] - mn0);
            sacc[j][2] = __expf(sacc[j][2] - mn1);
            sacc[j][3] = __expf(sacc[j][3] - mn1);
            rs0 += sacc[j][0] + sacc[j][1];
            rs1 += sacc[j][2] + sacc[j][3];
        }
        rs0 += __shfl_xor_sync(0xffffffffu, rs0, 1);
        rs0 += __shfl_xor_sync(0xffffffffu, rs0, 2);
        rs1 += __shfl_xor_sync(0xffffffffu, rs1, 1);
        rs1 += __shfl_xor_sync(0xffffffffu, rs1, 2);
        l0 = l0 * alpha0 + rs0;
        l1 = l1 * alpha1 + rs1;
        #pragma unroll
        for (int j = 0; j < 8; j++) {
            o[j][0] *= alpha0; o[j][1] *= alpha0;
            o[j][2] *= alpha1; o[j][3] *= alpha1;
        }

        // ---- pack P into 4 k16 A-fragments (C->A layout identity)
        uint32_t pa[4][4];
        #pragma unroll
        for (int ks = 0; ks < 4; ks++) {
            pa[ks][0] = pkh2(sacc[2 * ks][0],     sacc[2 * ks][1]);
            pa[ks][1] = pkh2(sacc[2 * ks][2],     sacc[2 * ks][3]);
            pa[ks][2] = pkh2(sacc[2 * ks + 1][0], sacc[2 * ks + 1][1]);
            pa[ks][3] = pkh2(sacc[2 * ks + 1][2], sacc[2 * ks + 1][3]);
        }

        // ---- O += P V (V B-fragments via ldmatrix.trans from [s][h] rows)
        #pragma unroll
        for (int ks = 0; ks < 4; ks++) {
            const int kr = ks * 16 + vkr;
            #pragma unroll
            for (int jp = 0; jp < 4; jp++) {
                const int c = jp * 2 + vcc;
                uint32_t b0, b1, b2, b3;
                ldsm4t(b0, b1, b2, b3,
                       vbuf + (uint32_t)(kr * 128) +
                       (((uint32_t)c ^ (uint32_t)(kr & 7)) << 4));
                mma_f16(o[2 * jp + 0], pa[ks], b0, b1);
                mma_f16(o[2 * jp + 1], pa[ks], b2, b3);
            }
        }
    }

    // ---- finalize: rows are complete, write directly
    const float inv0 = 1.f / l0;
    const float inv1 = 1.f / l1;
    const size_t row0 = (size_t)(b * TT + t0 + r0l);
    const size_t row1 = (size_t)(b * TT + t0 + r1l);
    #pragma unroll
    for (int j = 0; j < 8; j++) {
        const int col = n * 64 + j * 8 + 2 * tg;
        *(__half2*)(out + row0 * DD + col) =
            __floats2half2_rn(o[j][0] * inv0, o[j][1] * inv0);
        *(__half2*)(out + row1 * DD + col) =
            __floats2half2_rn(o[j][2] * inv1, o[j][3] * inv1);
    }
}

// ---------------------------------------------------------------------------
// Host launch
// ---------------------------------------------------------------------------
extern "C" void kernel_launch(void* const* d_in, const int* in_sizes, int n_in,
                              void* d_out, int out_size)
{
    (void)in_sizes; (void)n_in; (void)out_size;
    const float* x         = (const float*)d_in[0];
    const float* padding   = (const float*)d_in[1];
    const float* rms_scale = (const float*)d_in[2];
    const float* pds       = (const float*)d_in[3];
    const float* wq        = (const float*)d_in[4];
    const float* bq        = (const float*)d_in[5];
    const float* wk        = (const float*)d_in[6];
    const float* bk        = (const float*)d_in[7];
    const float* wv        = (const float*)d_in[8];
    const float* bv        = (const float*)d_in[9];
    const float* wo        = (const float*)d_in[10];
    const float* bo        = (const float*)d_in[11];
    const float* ln_gamma  = (const float*)d_in[12];
    const float* ln_beta   = (const float*)d_in[13];
    const float* w1        = (const float*)d_in[14];
    const float* b1        = (const float*)d_in[15];
    const float* w2        = (const float*)d_in[16];
    const float* b2        = (const float*)d_in[17];
    float* out = (float*)d_out;

    __half *xn, *qkv, *ao, *hn, *h1, *wqkvt, *wot, *w1t, *w2t;
    float *ar, *bqkv;
    cudaGetSymbolAddress((void**)&xn,  g_xn);
    cudaGetSymbolAddress((void**)&qkv, g_qkv);
    cudaGetSymbolAddress((void**)&ao,  g_ao);
    cudaGetSymbolAddress((void**)&ar,  g_ar);
    cudaGetSymbolAddress((void**)&hn,  g_hn);
    cudaGetSymbolAddress((void**)&h1,  g_h1);
    cudaGetSymbolAddress((void**)&wqkvt, g_wqkvt);
    cudaGetSymbolAddress((void**)&bqkv,  g_bqkv);
    cudaGetSymbolAddress((void**)&wot, g_wot);
    cudaGetSymbolAddress((void**)&w1t, g_w1t);
    cudaGetSymbolAddress((void**)&w2t, g_w2t);

    static int attr_done = 0;
    if (!attr_done) {
        cudaFuncSetAttribute(flash_kernel,
            cudaFuncAttributeMaxDynamicSharedMemorySize, FLASH_SMEM_BYTES);
        cudaFuncSetAttribute(mma_gemm_kernel<1, true>,
            cudaFuncAttributeMaxDynamicSharedMemorySize, GEMM_SMEM_BYTES);
        cudaFuncSetAttribute(mma_gemm_kernel<2, false>,
            cudaFuncAttributeMaxDynamicSharedMemorySize, GEMM_SMEM_BYTES);
        cudaFuncSetAttribute(mma_gemm_kernel<3, true>,
            cudaFuncAttributeMaxDynamicSharedMemorySize, GEMM_SMEM_BYTES);
        attr_done = 1;
    }

    // 0. Fused weight prep
    prep_kernel<<<PREP_BLOCKS, 256>>>(wq, wk, wv, w1, w2, wo, bq, bk, bv,
                                      wqkvt, w1t, w2t, wot, bqkv);

    // 1. RMSNorm
    rmsnorm_kernel<<<MM, 256>>>(x, rms_scale, xn);

    // 2. Fused QKV projection
    dim3 gQKV(QKVN / 128, MM / 128);
    mma_gemm_kernel<1, true><<<gQKV, 256, GEMM_SMEM_BYTES>>>(
        xn, wqkvt, bqkv, pds, qkv, MM, QKVN, DD);

    // 3. Flash attention v4 (128-row Q tiles)
    flash_kernel<<<dim3(TT / 128, BB * NHEAD), 256, FLASH_SMEM_BYTES>>>(
        qkv, padding, ao);

    // 4. Output projection + bias + residual(x)
    dim3 gD(DD / 128, MM / 128);
    mma_gemm_kernel<2, false><<<gD, 256, GEMM_SMEM_BYTES>>>(
        ao, wot, bo, x, ar, MM, DD, DD);

    // 5. LayerNorm
    layernorm_kernel<<<MM, 256>>>(ar, ln_gamma, ln_beta, hn);

    // 6. FFN up + ReLU
    dim3 gF(FF / 128, MM / 128);
    mma_gemm_kernel<3, true><<<gF, 256, GEMM_SMEM_BYTES>>>(
        hn, w1t, b1, nullptr, h1, MM, FF, DD);

    // 7. FFN down + bias + residual(ar) -> output
    mma_gemm_kernel<2, false><<<gD, 256, GEMM_SMEM_BYTES>>>(
        h1, w2t, b2, ar, out, MM, DD, FF);
}

// round 10
// speedup vs baseline: 8.0512x; 1.0131x over previous
#include <cuda_runtime.h>
#include <cuda_fp16.h>
#include <cstdint>
#include <math.h>

// Problem constants
#define BB 8
#define TT 1024
#define DD 1024
#define NHEAD 16
#define HDIM 64
#define FF 4096
#define MM (BB * TT)   // 8192
#define QKVN 3072

// ---------------------------------------------------------------------------
// Scratch (device globals)
// ---------------------------------------------------------------------------
__device__ __half g_xn [MM * DD];
__device__ __half g_qkv[MM * QKVN];
__device__ __half g_ao [MM * DD];
__device__ float  g_ar [MM * DD];
__device__ __half g_hn [MM * DD];
__device__ __half g_h1 [MM * FF];
__device__ __half g_wqkvt[QKVN * DD];   // [3072][1024] K-major (q|k|v)
__device__ float  g_bqkv [QKVN];
__device__ __half g_wot[DD * DD];
__device__ __half g_w1t[FF * DD];
__device__ __half g_w2t[DD * FF];

// ---------------------------------------------------------------------------
// Helpers
// ---------------------------------------------------------------------------
__device__ __forceinline__ uint32_t s2u(const void* p) {
    uint32_t a;
    asm("{ .reg .u64 t; cvta.to.shared.u64 t, %1; cvt.u32.u64 %0, t; }"
        : "=r"(a) : "l"(p));
    return a;
}

__device__ __forceinline__ void cp_async16(uint32_t saddr, const void* gaddr) {
    asm volatile("cp.async.cg.shared.global [%0], [%1], 16;"
                 :: "r"(saddr), "l"(gaddr));
}
__device__ __forceinline__ void cp_async4(uint32_t saddr, const void* gaddr) {
    asm volatile("cp.async.ca.shared.global [%0], [%1], 4;"
                 :: "r"(saddr), "l"(gaddr));
}
__device__ __forceinline__ void cp_commit() {
    asm volatile("cp.async.commit_group;");
}
template <int N>
__device__ __forceinline__ void cp_wait() {
    asm volatile("cp.async.wait_group %0;" :: "n"(N));
}

__device__ __forceinline__ void ldsm4(uint32_t& r0, uint32_t& r1,
                                      uint32_t& r2, uint32_t& r3, uint32_t addr) {
    asm volatile("ldmatrix.sync.aligned.m8n8.x4.shared.b16 {%0,%1,%2,%3}, [%4];"
                 : "=r"(r0), "=r"(r1), "=r"(r2), "=r"(r3) : "r"(addr));
}
__device__ __forceinline__ void ldsm4t(uint32_t& r0, uint32_t& r1,
                                       uint32_t& r2, uint32_t& r3, uint32_t addr) {
    asm volatile("ldmatrix.sync.aligned.m8n8.x4.trans.shared.b16 {%0,%1,%2,%3}, [%4];"
                 : "=r"(r0), "=r"(r1), "=r"(r2), "=r"(r3) : "r"(addr));
}

// fp16 MMA m16n8k16, fp32 accumulate
__device__ __forceinline__ void mma_f16(float* c, const uint32_t* a,
                                        uint32_t b0, uint32_t b1) {
    asm volatile(
        "mma.sync.aligned.m16n8k16.row.col.f32.f16.f16.f32 "
        "{%0,%1,%2,%3}, {%4,%5,%6,%7}, {%8,%9}, {%0,%1,%2,%3};"
        : "+f"(c[0]), "+f"(c[1]), "+f"(c[2]), "+f"(c[3])
        : "r"(a[0]), "r"(a[1]), "r"(a[2]), "r"(a[3]), "r"(b0), "r"(b1));
}

__device__ __forceinline__ uint32_t pkh2(float a, float b) {
    const __half2 h = __floats2half2_rn(a, b);
    return *(const uint32_t*)&h;
}

// ---------------------------------------------------------------------------
// Fused prep kernel
// ---------------------------------------------------------------------------
__device__ __forceinline__ void transpose_tile(
    const float* __restrict__ in, __half* __restrict__ out,
    int bx, int by, int C, int R, float (*t)[33], int tid)
{
    const int txx = tid & 31, tyy = tid >> 5;
    #pragma unroll
    for (int j = 0; j < 32; j += 8)
        t[tyy + j][txx] = in[(size_t)(by + tyy + j) * C + bx + txx];
    __syncthreads();
    #pragma unroll
    for (int j = 0; j < 32; j += 8)
        out[(size_t)(bx + tyy + j) * R + by + txx] = __float2half_rn(t[txx][tyy + j]);
}

#define PREP_BLOCKS 12300

__global__ __launch_bounds__(256) void prep_kernel(
    const float* __restrict__ wq, const float* __restrict__ wk,
    const float* __restrict__ wv, const float* __restrict__ w1,
    const float* __restrict__ w2, const float* __restrict__ wo,
    const float* __restrict__ bq, const float* __restrict__ bk,
    const float* __restrict__ bv,
    __half* __restrict__ wqkvt, __half* __restrict__ w1t,
    __half* __restrict__ w2t, __half* __restrict__ wot,
    float* __restrict__ bqkv)
{
    __shared__ float t[32][33];
    const int id = blockIdx.x;
    const int tid = threadIdx.x;

    if (id < 3072) {
        const int w = id >> 10, tt = id & 1023;
        const float* in = (w == 0) ? wq : (w == 1) ? wk : wv;
        __half* outp = wqkvt + (size_t)w * 1024 * DD;
        transpose_tile(in, outp, (tt & 31) << 5, (tt >> 5) << 5, DD, DD, t, tid);
    } else if (id < 7168) {
        const int tt = id - 3072;
        transpose_tile(w1, w1t, (tt & 127) << 5, (tt >> 7) << 5, FF, DD, t, tid);
    } else if (id < 11264) {
        const int tt = id - 7168;
        transpose_tile(w2, w2t, (tt & 31) << 5, (tt >> 5) << 5, DD, FF, t, tid);
    } else if (id < 12288) {
        const int i = (id - 11264) * 1024 + tid * 4;
        const float4 v = *(const float4*)(wo + i);
        __half2* o2 = (__half2*)(wot + i);
        o2[0] = __floats2half2_rn(v.x, v.y);
        o2[1] = __floats2half2_rn(v.z, v.w);
    } else {
        const int i = (id - 12288) * 256 + tid;
        if (i < QKVN)
            bqkv[i] = (i < 1024) ? bq[i] : (i < 2048) ? bk[i - 1024] : bv[i - 2048];
    }
}

// ---------------------------------------------------------------------------
// RMSNorm / LayerNorm: warp-per-row (8 rows per 256-thread block, no barriers)
// ---------------------------------------------------------------------------
__global__ __launch_bounds__(256) void rmsnorm_kernel(
    const float* __restrict__ x, const float* __restrict__ scale,
    __half* __restrict__ out)
{
    const int lane = threadIdx.x & 31;
    const int row = blockIdx.x * 8 + (threadIdx.x >> 5);
    const float4* xp = (const float4*)(x + (size_t)row * DD);
    const float4* sp = (const float4*)scale;
    float4 v[8];
    float ss = 0.f;
    #pragma unroll
    for (int u = 0; u < 8; u++) {
        v[u] = xp[lane + 32 * u];
        ss += v[u].x * v[u].x + v[u].y * v[u].y + v[u].z * v[u].z + v[u].w * v[u].w;
    }
    #pragma unroll
    for (int m = 16; m; m >>= 1) ss += __shfl_xor_sync(0xffffffffu, ss, m);
    const float r = rsqrtf(ss * (1.0f / DD) + 1e-6f);
    __half2* o2 = (__half2*)(out + (size_t)row * DD);
    #pragma unroll
    for (int u = 0; u < 8; u++) {
        const float4 s4 = sp[lane + 32 * u];
        o2[(lane + 32 * u) * 2 + 0] = __floats2half2_rn(v[u].x * r * s4.x, v[u].y * r * s4.y);
        o2[(lane + 32 * u) * 2 + 1] = __floats2half2_rn(v[u].z * r * s4.z, v[u].w * r * s4.w);
    }
}

__global__ __launch_bounds__(256) void layernorm_kernel(
    const float* __restrict__ x, const float* __restrict__ gamma,
    const float* __restrict__ beta, __half* __restrict__ out)
{
    const int lane = threadIdx.x & 31;
    const int row = blockIdx.x * 8 + (threadIdx.x >> 5);
    const float4* xp = (const float4*)(x + (size_t)row * DD);
    float4 v[8];
    float s = 0.f, ss = 0.f;
    #pragma unroll
    for (int u = 0; u < 8; u++) {
        v[u] = xp[lane + 32 * u];
        s  += v[u].x + v[u].y + v[u].z + v[u].w;
        ss += v[u].x * v[u].x + v[u].y * v[u].y + v[u].z * v[u].z + v[u].w * v[u].w;
    }
    #pragma unroll
    for (int m = 16; m; m >>= 1) {
        s  += __shfl_xor_sync(0xffffffffu, s,  m);
        ss += __shfl_xor_sync(0xffffffffu, ss, m);
    }
    const float mean = s * (1.0f / DD);
    const float var  = ss * (1.0f / DD) - mean * mean;
    const float r = rsqrtf(var + 1e-5f);
    __half2* o2 = (__half2*)(out + (size_t)row * DD);
    const float4* gp = (const float4*)gamma;
    const float4* bp = (const float4*)beta;
    #pragma unroll
    for (int u = 0; u < 8; u++) {
        const float4 g4 = gp[lane + 32 * u];
        const float4 b4 = bp[lane + 32 * u];
        o2[(lane + 32 * u) * 2 + 0] = __floats2half2_rn(
            (v[u].x - mean) * r * g4.x + b4.x, (v[u].y - mean) * r * g4.y + b4.y);
        o2[(lane + 32 * u) * 2 + 1] = __floats2half2_rn(
            (v[u].z - mean) * r * g4.z + b4.z, (v[u].w - mean) * r * g4.w + b4.w);
    }
}

// ---------------------------------------------------------------------------
// fp16 mma.sync GEMM (EPI1 scale now includes extra LOG2E for exp2 softmax)
// ---------------------------------------------------------------------------
__device__ __forceinline__ float softplus_f(float x) {
    return (x > 15.f) ? x : log1pf(__expf(x));
}

#define GSTAGE 32768
#define GEMM_SMEM_BYTES (3 * GSTAGE)

template <int EPI, bool OUTH>
__global__ __launch_bounds__(256, 2) void mma_gemm_kernel(
    const __half* __restrict__ A, const __half* __restrict__ Bw,
    const float* __restrict__ bias, const float* __restrict__ extra,
    void* __restrict__ Cv, int M, int N, int K)
{
    extern __shared__ char gsm[];
    const uint32_t smbase = s2u(gsm);
    const int tid = threadIdx.x;
    const int lane = tid & 31;
    const int wid = tid >> 5;
    const int m0 = blockIdx.y << 7;
    const int n0 = blockIdx.x << 7;
    const int wm = (wid & 3) << 5;
    const int wn = (wid >> 2) << 6;

    uint32_t a_soff[4], b_soff[4];
    const __half* a_g[4]; const __half* b_g[4];
    #pragma unroll
    for (int u = 0; u < 4; u++) {
        const int qch = tid + u * 256;
        const int m = qch >> 3, kc = qch & 7;
        const uint32_t sw = (uint32_t)(kc ^ (m & 7));
        a_soff[u] = (uint32_t)(m * 128) + (sw << 4);
        b_soff[u] = a_soff[u] + 16384u;
        a_g[u] = A  + (size_t)(m0 + m) * K + kc * 8;
        b_g[u] = Bw + (size_t)(n0 + m) * K + kc * 8;
    }

    const int arow = wm + (lane & 15);
    const uint32_t acadd = (uint32_t)(lane >> 4);
    const uint32_t aswz = (uint32_t)(arow & 7);
    const uint32_t aoff = (uint32_t)(arow * 128);
    const int brow = wn + ((lane >> 4) << 3) + (lane & 7);
    const uint32_t bcc = (uint32_t)((lane >> 3) & 1);
    const uint32_t bswz = (uint32_t)(brow & 7);
    const uint32_t boff = (uint32_t)(brow * 128) + 16384u;

    float acc[2][8][4];
    #pragma unroll
    for (int i = 0; i < 2; i++)
        #pragma unroll
        for (int j = 0; j < 8; j++)
            #pragma unroll
            for (int t = 0; t < 4; t++) acc[i][j][t] = 0.f;

    const int nk = K >> 6;
    #pragma unroll
    for (int s = 0; s < 2; s++) {
        const uint32_t sb = smbase + (uint32_t)s * GSTAGE;
        #pragma unroll
        for (int u = 0; u < 4; u++) {
            cp_async16(sb + a_soff[u], a_g[u] + s * 64);
            cp_async16(sb + b_soff[u], b_g[u] + s * 64);
        }
        cp_commit();
    }

    int sidx = 0;
    for (int kc = 0; kc < nk; kc++) {
        if (kc == nk - 1) cp_wait<0>(); else cp_wait<1>();
        __syncthreads();
        if (kc + 2 < nk) {
            const int s2 = (sidx + 2 >= 3) ? sidx - 1 : sidx + 2;
            const uint32_t sb = smbase + (uint32_t)s2 * GSTAGE;
            #pragma unroll
            for (int u = 0; u < 4; u++) {
                cp_async16(sb + a_soff[u], a_g[u] + (kc + 2) * 64);
                cp_async16(sb + b_soff[u], b_g[u] + (kc + 2) * 64);
            }
            cp_commit();
        }
        const uint32_t sb = smbase + (uint32_t)sidx * GSTAGE;
        #pragma unroll
        for (int ks = 0; ks < 4; ks++) {
            const uint32_t kc0 = (uint32_t)(2 * ks);
            uint32_t af[2][4];
            #pragma unroll
            for (int i = 0; i < 2; i++) {
                const uint32_t addr = sb + aoff + (uint32_t)(i * 2048) +
                                      (((kc0 + acadd) ^ aswz) << 4);
                ldsm4(af[i][0], af[i][1], af[i][2], af[i][3], addr);
            }
            #pragma unroll
            for (int jp = 0; jp < 4; jp++) {
                uint32_t b0, b1, b2, b3;
                const uint32_t addr = sb + boff + (uint32_t)(jp * 2048) +
                                      (((kc0 + bcc) ^ bswz) << 4);
                ldsm4(b0, b1, b2, b3, addr);
                #pragma unroll
                for (int i = 0; i < 2; i++) {
                    mma_f16(acc[i][2 * jp + 0], af[i], b0, b1);
                    mma_f16(acc[i][2 * jp + 1], af[i], b2, b3);
                }
            }
        }
        sidx = (sidx == 2) ? 0 : sidx + 1;
    }

    const int g = lane >> 2, tg = lane & 3;
    #pragma unroll
    for (int i = 0; i < 2; i++) {
        #pragma unroll
        for (int j = 0; j < 8; j++) {
            const int col = n0 + wn + j * 8 + tg * 2;
            const float2 b2 = *(const float2*)(bias + col);
            float sx = 1.f, sy = 1.f;
            if (EPI == 1) {
                if (col < 1024) {
                    // LOG2E^2 / sqrt(64): extra LOG2E folds softmax into exp2
                    const float c = 0.26017101f;
                    sx = c * softplus_f(extra[col & 63]);
                    sy = c * softplus_f(extra[(col + 1) & 63]);
                }
            }
            #pragma unroll
            for (int h = 0; h < 2; h++) {
                const int row = m0 + wm + i * 16 + g + h * 8;
                float vx = acc[i][j][2 * h + 0] + b2.x;
                float vy = acc[i][j][2 * h + 1] + b2.y;
                if (EPI == 1) { vx *= sx; vy *= sy; }
                if (EPI == 2) {
                    const float2 r2 = *(const float2*)(extra + (size_t)row * N + col);
                    vx += r2.x; vy += r2.y;
                }
                if (EPI == 3) { vx = fmaxf(vx, 0.f); vy = fmaxf(vy, 0.f); }
                if (OUTH) {
                    *(__half2*)((__half*)Cv + (size_t)row * N + col) =
                        __floats2half2_rn(vx, vy);
                } else {
                    float2 o2; o2.x = vx; o2.y = vy;
                    *(float2*)((float*)Cv + (size_t)row * N + col) = o2;
                }
            }
        }
    }
}

// ---------------------------------------------------------------------------
// Flash attention v5: v4 + log2-domain softmax (exp2f) + additive masking
// with warp-uniform causal branch.
// ---------------------------------------------------------------------------
#define FL_PQ_I 12288   // float idx (byte 49152): padq[128]
#define FL_PS_I 12416   // pads[2][64]
#define FLASH_SMEM_BYTES 50176

__global__ __launch_bounds__(256) void flash_kernel(
    const __half* __restrict__ qkv, const float* __restrict__ pad,
    __half* __restrict__ out)
{
    extern __shared__ float sf[];
    const uint32_t sbase = s2u(sf);
    const int tid = threadIdx.x;
    const int lane = tid & 31;
    const int wid = tid >> 5;
    const int wm = wid << 4;
    const int g = lane >> 2, tg = lane & 3;
    const int t0 = (7 - blockIdx.x) << 7;         // longest first
    const int b = blockIdx.y >> 4, n = blockIdx.y & 15;

    const int arow = wm + (lane & 15);
    const uint32_t acadd = (uint32_t)(lane >> 4);
    const uint32_t aswz = (uint32_t)(arow & 7);
    const uint32_t qbase = sbase + (uint32_t)(arow * 128);
    const int brw = ((lane >> 4) << 3) + (lane & 7);
    const uint32_t bcc = (uint32_t)((lane >> 3) & 1);
    const int vkr = ((lane >> 3) & 1) * 8 + (lane & 7);
    const int vcc = lane >> 4;

    // ---- load Q tile + padq
    {
        const int r = tid >> 1;
        const int c0 = (tid & 1) << 2;
        const __half* qp = qkv + (size_t)(b * TT + t0 + r) * QKVN + n * 64;
        #pragma unroll
        for (int u = 0; u < 4; u++) {
            const int c = c0 + u;
            cp_async16(sbase + (uint32_t)(r * 128 + ((c ^ (r & 7)) << 4)),
                       qp + c * 8);
        }
        if (tid < 128)
            cp_async4(sbase + (uint32_t)((FL_PQ_I + tid) * 4),
                      pad + b * TT + t0 + tid);
    }
    // ---- prefetch first K/V tile into buf 0
    {
        const int lr = tid >> 2;
        const int lc0 = (tid & 3) << 1;
        const __half* kp = qkv + (size_t)(b * TT + lr) * QKVN + 1024 + n * 64;
        const __half* vp = kp + 1024;
        #pragma unroll
        for (int u = 0; u < 2; u++) {
            const int c = lc0 + u;
            const uint32_t so = (uint32_t)(lr * 128 + ((c ^ (lr & 7)) << 4));
            cp_async16(sbase + 16384u + so, kp + c * 8);
            cp_async16(sbase + 24576u + so, vp + c * 8);
        }
        if (tid < 64)
            cp_async4(sbase + (uint32_t)((FL_PS_I + tid) * 4), pad + b * TT + tid);
    }
    cp_commit();

    float o[8][4];
    #pragma unroll
    for (int j = 0; j < 8; j++)
        #pragma unroll
        for (int c = 0; c < 4; c++) o[j][c] = 0.f;
    float m0 = -1e30f, m1 = -1e30f, l0 = 0.f, l1 = 0.f;
    const int r0l = wm + g, r1l = r0l + 8;

    const int nIter = (t0 >> 6) + 2;
    for (int it = 0; it < nIter; it++) {
        const int s0 = it << 6;
        const int buf = it & 1;
        const uint32_t kbuf = sbase + 16384u + (uint32_t)buf * 16384u;
        const uint32_t vbuf = kbuf + 8192u;

        cp_wait<0>();
        __syncthreads();

        if (it + 1 < nIter) {
            const int lr = tid >> 2;
            const int lc0 = (tid & 3) << 1;
            const __half* kp = qkv + (size_t)(b * TT + s0 + 64 + lr) * QKVN + 1024 + n * 64;
            const __half* vp = kp + 1024;
            const uint32_t ob = sbase + 16384u + (uint32_t)(buf ^ 1) * 16384u;
            #pragma unroll
            for (int u = 0; u < 2; u++) {
                const int c = lc0 + u;
                const uint32_t so = (uint32_t)(lr * 128 + ((c ^ (lr & 7)) << 4));
                cp_async16(ob + so, kp + c * 8);
                cp_async16(ob + 8192u + so, vp + c * 8);
            }
            if (tid < 64)
                cp_async4(sbase + (uint32_t)((FL_PS_I + (buf ^ 1) * 64 + tid) * 4),
                          pad + b * TT + s0 + 64 + tid);
            cp_commit();
        }

        // ---- S = Q K^T: warp's 16 rows x 64 s-cols (log2-domain scores)
        float sacc[8][4];
        #pragma unroll
        for (int j = 0; j < 8; j++)
            #pragma unroll
            for (int c = 0; c < 4; c++) sacc[j][c] = 0.f;
        #pragma unroll
        for (int ks = 0; ks < 4; ks++) {
            const uint32_t kc0 = (uint32_t)(2 * ks);
            uint32_t af[4];
            ldsm4(af[0], af[1], af[2], af[3],
                  qbase + (((kc0 + acadd) ^ aswz) << 4));
            #pragma unroll
            for (int jp = 0; jp < 4; jp++) {
                const int brow = jp * 16 + brw;
                uint32_t b0, b1, b2, b3;
                ldsm4(b0, b1, b2, b3,
                      kbuf + (uint32_t)(brow * 128) +
                      (((kc0 + bcc) ^ (uint32_t)(brow & 7)) << 4));
                mma_f16(sacc[2 * jp + 0], af, b0, b1);
                mma_f16(sacc[2 * jp + 1], af, b2, b3);
            }
        }

        // ---- additive masking (warp-uniform causal branch)
        const float pq0 = sf[FL_PQ_I + r0l], pq1 = sf[FL_PQ_I + r1l];
        const float pqa0 = (pq0 != 0.f) ? 0.f : -1e9f;
        const float pqa1 = (pq1 != 0.f) ? 0.f : -1e9f;
        const int rg0 = t0 + r0l, rg1 = t0 + r1l;
        const int psb = FL_PS_I + buf * 64;
        if (s0 + 64 <= t0 + wm) {              // interior: no causal checks
            #pragma unroll
            for (int j = 0; j < 8; j++) {
                const int cl = j * 8 + 2 * tg;
                const float psa0 = (sf[psb + cl]     != 0.f) ? 0.f : -1e9f;
                const float psa1 = (sf[psb + cl + 1] != 0.f) ? 0.f : -1e9f;
                sacc[j][0] += pqa0 + psa0;
                sacc[j][1] += pqa0 + psa1;
                sacc[j][2] += pqa1 + psa0;
                sacc[j][3] += pqa1 + psa1;
            }
        } else {                               // diagonal region
            #pragma unroll
            for (int j = 0; j < 8; j++) {
                const int cl = j * 8 + 2 * tg;
                const int cg = s0 + cl;
                const float psa0 = (sf[psb + cl]     != 0.f) ? 0.f : -1e9f;
                const float psa1 = (sf[psb + cl + 1] != 0.f) ? 0.f : -1e9f;
                sacc[j][0] += pqa0 + psa0 + ((cg     <= rg0) ? 0.f : -1e9f);
                sacc[j][1] += pqa0 + psa1 + ((cg + 1 <= rg0) ? 0.f : -1e9f);
                sacc[j][2] += pqa1 + psa0 + ((cg     <= rg1) ? 0.f : -1e9f);
                sacc[j][3] += pqa1 + psa1 + ((cg + 1 <= rg1) ? 0.f : -1e9f);
            }
        }

        // ---- warp-local online softmax in log2 domain
        float rm0 = -1e30f, rm1 = -1e30f;
        #pragma unroll
        for (int j = 0; j < 8; j++) {
            rm0 = fmaxf(rm0, fmaxf(sacc[j][0], sacc[j][1]));
            rm1 = fmaxf(rm1, fmaxf(sacc[j][2], sacc[j][3]));
        }
        rm0 = fmaxf(rm0, __shfl_xor_sync(0xffffffffu, rm0, 1));
        rm0 = fmaxf(rm0, __shfl_xor_sync(0xffffffffu, rm0, 2));
        rm1 = fmaxf(rm1, __shfl_xor_sync(0xffffffffu, rm1, 1));
        rm1 = fmaxf(rm1, __shfl_xor_sync(0xffffffffu, rm1, 2));
        const float mn0 = fmaxf(m0, rm0), mn1 = fmaxf(m1, rm1);
        const float alpha0 = exp2f(m0 - mn0), alpha1 = exp2f(m1 - mn1);
        m0 = mn0; m1 = mn1;
        float rs0 = 0.f, rs1 = 0.f;
        #pragma unroll
        for (int j = 0; j < 8; j++) {
            sacc[j][0] = exp2f(sacc[j][0] - mn0);
            sacc[j][1] = exp2f(sacc[j][1] - mn0);
            sacc[j][2] = exp2f(sacc[j][2] - mn1);
            sacc[j][3] = exp2f(sacc[j][3] - mn1);
            rs0 += sacc[j][0] + sacc[j][1];
            rs1 += sacc[j][2] + sacc[j][3];
        }
        rs0 += __shfl_xor_sync(0xffffffffu, rs0, 1);
        rs0 += __shfl_xor_sync(0xffffffffu, rs0, 2);
        rs1 += __shfl_xor_sync(0xffffffffu, rs1, 1);
        rs1 += __shfl_xor_sync(0xffffffffu, rs1, 2);
        l0 = l0 * alpha0 + rs0;
        l1 = l1 * alpha1 + rs1;
        #pragma unroll
        for (int j = 0; j < 8; j++) {
            o[j][0] *= alpha0; o[j][1] *= alpha0;
            o[j][2] *= alpha1; o[j][3] *= alpha1;
        }

        // ---- pack P into 4 k16 A-fragments
        uint32_t pa[4][4];
        #pragma unroll
        for (int ks = 0; ks < 4; ks++) {
            pa[ks][0] = pkh2(sacc[2 * ks][0],     sacc[2 * ks][1]);
            pa[ks][1] = pkh2(sacc[2 * ks][2],     sacc[2 * ks][3]);
            pa[ks][2] = pkh2(sacc[2 * ks + 1][0], sacc[2 * ks + 1][1]);
            pa[ks][3] = pkh2(sacc[2 * ks + 1][2], sacc[2 * ks + 1][3]);
        }

        // ---- O += P V
        #pragma unroll
        for (int ks = 0; ks < 4; ks++) {
            const int kr = ks * 16 + vkr;
            #pragma unroll
            for (int jp = 0; jp < 4; jp++) {
                const int c = jp * 2 + vcc;
                uint32_t b0, b1, b2, b3;
                ldsm4t(b0, b1, b2, b3,
                       vbuf + (uint32_t)(kr * 128) +
                       (((uint32_t)c ^ (uint32_t)(kr & 7)) << 4));
                mma_f16(o[2 * jp + 0], pa[ks], b0, b1);
                mma_f16(o[2 * jp + 1], pa[ks], b2, b3);
            }
        }
    }

    // ---- finalize
    const float inv0 = 1.f / l0;
    const float inv1 = 1.f / l1;
    const size_t row0 = (size_t)(b * TT + t0 + r0l);
    const size_t row1 = (size_t)(b * TT + t0 + r1l);
    #pragma unroll
    for (int j = 0; j < 8; j++) {
        const int col = n * 64 + j * 8 + 2 * tg;
        *(__half2*)(out + row0 * DD + col) =
            __floats2half2_rn(o[j][0] * inv0, o[j][1] * inv0);
        *(__half2*)(out + row1 * DD + col) =
            __floats2half2_rn(o[j][2] * inv1, o[j][3] * inv1);
    }
}

// ---------------------------------------------------------------------------
// Host launch
// ---------------------------------------------------------------------------
extern "C" void kernel_launch(void* const* d_in, const int* in_sizes, int n_in,
                              void* d_out, int out_size)
{
    (void)in_sizes; (void)n_in; (void)out_size;
    const float* x         = (const float*)d_in[0];
    const float* padding   = (const float*)d_in[1];
    const float* rms_scale = (const float*)d_in[2];
    const float* pds       = (const float*)d_in[3];
    const float* wq        = (const float*)d_in[4];
    const float* bq        = (const float*)d_in[5];
    const float* wk        = (const float*)d_in[6];
    const float* bk        = (const float*)d_in[7];
    const float* wv        = (const float*)d_in[8];
    const float* bv        = (const float*)d_in[9];
    const float* wo        = (const float*)d_in[10];
    const float* bo        = (const float*)d_in[11];
    const float* ln_gamma  = (const float*)d_in[12];
    const float* ln_beta   = (const float*)d_in[13];
    const float* w1        = (const float*)d_in[14];
    const float* b1        = (const float*)d_in[15];
    const float* w2        = (const float*)d_in[16];
    const float* b2        = (const float*)d_in[17];
    float* out = (float*)d_out;

    __half *xn, *qkv, *ao, *hn, *h1, *wqkvt, *wot, *w1t, *w2t;
    float *ar, *bqkv;
    cudaGetSymbolAddress((void**)&xn,  g_xn);
    cudaGetSymbolAddress((void**)&qkv, g_qkv);
    cudaGetSymbolAddress((void**)&ao,  g_ao);
    cudaGetSymbolAddress((void**)&ar,  g_ar);
    cudaGetSymbolAddress((void**)&hn,  g_hn);
    cudaGetSymbolAddress((void**)&h1,  g_h1);
    cudaGetSymbolAddress((void**)&wqkvt, g_wqkvt);
    cudaGetSymbolAddress((void**)&bqkv,  g_bqkv);
    cudaGetSymbolAddress((void**)&wot, g_wot);
    cudaGetSymbolAddress((void**)&w1t, g_w1t);
    cudaGetSymbolAddress((void**)&w2t, g_w2t);

    static int attr_done = 0;
    if (!attr_done) {
        cudaFuncSetAttribute(flash_kernel,
            cudaFuncAttributeMaxDynamicSharedMemorySize, FLASH_SMEM_BYTES);
        cudaFuncSetAttribute(mma_gemm_kernel<1, true>,
            cudaFuncAttributeMaxDynamicSharedMemorySize, GEMM_SMEM_BYTES);
        cudaFuncSetAttribute(mma_gemm_kernel<2, false>,
            cudaFuncAttributeMaxDynamicSharedMemorySize, GEMM_SMEM_BYTES);
        cudaFuncSetAttribute(mma_gemm_kernel<3, true>,
            cudaFuncAttributeMaxDynamicSharedMemorySize, GEMM_SMEM_BYTES);
        attr_done = 1;
    }

    // 0. Fused weight prep
    prep_kernel<<<PREP_BLOCKS, 256>>>(wq, wk, wv, w1, w2, wo, bq, bk, bv,
                                      wqkvt, w1t, w2t, wot, bqkv);

    // 1. RMSNorm (warp-per-row)
    rmsnorm_kernel<<<MM / 8, 256>>>(x, rms_scale, xn);

    // 2. Fused QKV projection (q pre-scaled for exp2 softmax)
    dim3 gQKV(QKVN / 128, MM / 128);
    mma_gemm_kernel<1, true><<<gQKV, 256, GEMM_SMEM_BYTES>>>(
        xn, wqkvt, bqkv, pds, qkv, MM, QKVN, DD);

    // 3. Flash attention v5
    flash_kernel<<<dim3(TT / 128, BB * NHEAD), 256, FLASH_SMEM_BYTES>>>(
        qkv, padding, ao);

    // 4. Output projection + bias + residual(x)
    dim3 gD(DD / 128, MM / 128);
    mma_gemm_kernel<2, false><<<gD, 256, GEMM_SMEM_BYTES>>>(
        ao, wot, bo, x, ar, MM, DD, DD);

    // 5. LayerNorm (warp-per-row)
    layernorm_kernel<<<MM / 8, 256>>>(ar, ln_gamma, ln_beta, hn);

    // 6. FFN up + ReLU
    dim3 gF(FF / 128, MM / 128);
    mma_gemm_kernel<3, true><<<gF, 256, GEMM_SMEM_BYTES>>>(
        hn, w1t, b1, nullptr, h1, MM, FF, DD);

    // 7. FFN down + bias + residual(ar) -> output
    mma_gemm_kernel<2, false><<<gD, 256, GEMM_SMEM_BYTES>>>(
        h1, w2t, b2, ar, out, MM, DD, FF);
}